// round 12
// baseline (speedup 1.0000x reference)
#include <cuda_runtime.h>
#include <cuda_bf16.h>
#include <math.h>
#include <stdint.h>

// ---------------------------------------------------------------------------
// EEGformer forward. int8 dual-plane GEMMs (mma.sync.m16n8k32.s8).
// R12: fc1 epilogue quantizes h directly (32-col group scales); fc2
// dequantizes per k-tile into fp32 accumulators. hbuf round-trip removed.
// A=120, B=2048, Bp1=2049, M=128, T = 120*2049 = 245880 tokens.
// ---------------------------------------------------------------------------

#define AA    120
#define BB    2048
#define BP1   2049
#define TTOK  (AA * BP1)      // 245880
#define TXTOK (AA * BB)       // 245760
#define TPAD  246016          // 1922 * 128

__device__ float  g_big[(size_t)TTOK * 128];        // imv32 fp32 (~126MB)
__device__ int8_t g_act8[(size_t)TTOK * 256];       // z / imv planes
__device__ int8_t g_h8  [(size_t)TTOK * 512 * 2];   // h planes / x planes
__device__ int8_t g_w8h[278528];
__device__ int8_t g_w8l[278528];
__device__ float  g_sc_w[1792];
__device__ float  g_sc_tok[(size_t)3 * TTOK + TXTOK];
__device__ float  g_sch[(size_t)TPAD * 16];         // h group scales (~15.7MB)
__device__ float  g_part[AA * 16 * 128];

// ---------------------------------------------------------------------------
// PTX helpers
// ---------------------------------------------------------------------------
__device__ __forceinline__ uint32_t smem_to_u32(const void* p) {
    uint32_t a;
    asm("{ .reg .u64 t; cvta.to.shared.u64 t, %1; cvt.u32.u64 %0, t; }" : "=r"(a) : "l"(p));
    return a;
}
__device__ __forceinline__ void ldm4(uint32_t r[4], uint32_t addr) {
    asm volatile("ldmatrix.sync.aligned.m8n8.x4.shared.b16 {%0,%1,%2,%3}, [%4];"
        : "=r"(r[0]), "=r"(r[1]), "=r"(r[2]), "=r"(r[3]) : "r"(addr));
}
__device__ __forceinline__ void imma(int d[4], const uint32_t a[4],
                                     uint32_t b0, uint32_t b1) {
    asm volatile("mma.sync.aligned.m16n8k32.row.col.s32.s8.s8.s32 "
        "{%0,%1,%2,%3}, {%4,%5,%6,%7}, {%8,%9}, {%0,%1,%2,%3};"
        : "+r"(d[0]), "+r"(d[1]), "+r"(d[2]), "+r"(d[3])
        : "r"(a[0]), "r"(a[1]), "r"(a[2]), "r"(a[3]), "r"(b0), "r"(b1));
}
__device__ __forceinline__ void cp16(uint32_t saddr, const void* g, bool p) {
    int sz = p ? 16 : 0;
    asm volatile("cp.async.cg.shared.global [%0], [%1], 16, %2;"
        :: "r"(saddr), "l"(g), "r"(sz) : "memory");
}
#define CP_COMMIT() asm volatile("cp.async.commit_group;" ::: "memory")
#define CP_WAIT1()  asm volatile("cp.async.wait_group 1;" ::: "memory")
#define CP_WAIT0()  asm volatile("cp.async.wait_group 0;" ::: "memory")

// 32-byte-row swizzle inside one k-tile: line = row>>2 (128B)
#define SWZ8(row, kc) ((((row) >> 2) * 128) + \
    (((((row) & 3) * 2 + (kc)) ^ (((row) >> 2) & 7)) << 4))

// Fragment loads for one BK=32 k-tile, block 128(M) x 64(N), 8 warps
// 4(M, wid&3) x 2(N, wid>>2), warp tile 32x32 (R8-validated layout).
#define LOAD_FRAGS64(sAh, sAl, sBh, sBl) do { \
    int arow = (wid & 3) * 32 + (lane & 7) + ((lane >> 3) & 1) * 8; \
    int akc  = lane >> 4; \
    _Pragma("unroll") for (int mt = 0; mt < 2; mt++) { \
        uint32_t off = SWZ8(arow + mt * 16, akc); \
        ldm4(fAh[mt], (sAh) + off); \
        ldm4(fAl[mt], (sAl) + off); \
    } \
    int brow = (wid >> 2) * 32 + ((lane >> 4) & 1) * 8 + (lane & 7); \
    int bkc  = (lane >> 3) & 1; \
    _Pragma("unroll") for (int j = 0; j < 2; j++) { \
        uint32_t off = SWZ8(brow + j * 16, bkc); \
        ldm4(fBh[j], (sBh) + off); \
        ldm4(fBl[j], (sBl) + off); \
    } \
} while (0)

__device__ __forceinline__ void compute_tile64(
    uint32_t sAh_, uint32_t sAl_, uint32_t sBh_, uint32_t sBl_,
    int wid, int lane, int accHH[2][4][4], int accMID[2][4][4])
{
    uint32_t fAh[2][4], fAl[2][4], fBh[2][4], fBl[2][4];
    LOAD_FRAGS64(sAh_, sAl_, sBh_, sBl_);
#pragma unroll
    for (int mt = 0; mt < 2; mt++)
#pragma unroll
        for (int nt = 0; nt < 4; nt++) {
            int j = nt >> 1, o = (nt & 1) * 2;
            imma(accHH[mt][nt],  fAh[mt], fBh[j][o], fBh[j][o + 1]);
            imma(accMID[mt][nt], fAh[mt], fBl[j][o], fBl[j][o + 1]);
            imma(accMID[mt][nt], fAl[mt], fBh[j][o], fBh[j][o + 1]);
        }
}

// 16-warp variant (qkv_rsa): block 128x128, warp 32x32.
__device__ __forceinline__ void compute_tile(
    uint32_t sAh_, uint32_t sAl_, uint32_t sBh_, uint32_t sBl_,
    int wid, int lane, int accHH[2][4][4], int accMID[2][4][4])
{
    uint32_t fAh[2][4], fAl[2][4], fBh[2][4], fBl[2][4];
    LOAD_FRAGS64(sAh_, sAl_, sBh_, sBl_);
#pragma unroll
    for (int mt = 0; mt < 2; mt++)
#pragma unroll
        for (int nt = 0; nt < 4; nt++) {
            int j = nt >> 1, o = (nt & 1) * 2;
            imma(accHH[mt][nt],  fAh[mt], fBh[j][o], fBh[j][o + 1]);
            imma(accMID[mt][nt], fAh[mt], fBl[j][o], fBl[j][o + 1]);
            imma(accMID[mt][nt], fAl[mt], fBh[j][o], fBh[j][o + 1]);
        }
}

#define ZERO_ACC(accHH, accMID) do { \
    _Pragma("unroll") for (int i = 0; i < 2; i++) \
    _Pragma("unroll") for (int j = 0; j < 4; j++) \
    _Pragma("unroll") for (int q = 0; q < 4; q++) { accHH[i][j][q] = 0; accMID[i][j][q] = 0; } \
} while (0)

// ---------------------------------------------------------------------------
// Resident-A GEMM, 256 threads, 2 CTAs/SM (init, Wo). N = NCH*64.
// ---------------------------------------------------------------------------
template<int NCH, int REMAP>
__global__ __launch_bounds__(256, 2)
void i8_gemm_res2(const int8_t* __restrict__ a_h, const int8_t* __restrict__ a_l,
                  const float* __restrict__ sA,
                  const int8_t* __restrict__ w_h, const int8_t* __restrict__ w_l,
                  const float* __restrict__ uB,
                  const float* __restrict__ biasv,
                  const float* __restrict__ addend,
                  float* __restrict__ outf, int T)
{
    constexpr int K = 128;
    constexpr int Nfull = NCH * 64;
    extern __shared__ char smem[];
    const uint32_t sbase = smem_to_u32(smem);
    const uint32_t sAh = sbase, sAl = sbase + 16384, sB0 = sbase + 32768;
    const int tid = threadIdx.x, wid = tid >> 5, lane = tid & 31;
    const int t0 = blockIdx.x * 128;

#pragma unroll
    for (int h = 0; h < 8; h++) {
        int i = tid + h * 256;
        int plane = i >> 10, idx = i & 1023;
        int kt = idx >> 8, sub = idx & 255, row = sub >> 1, kc = sub & 1;
        int t = t0 + row; bool p = t < T;
        uint32_t dst = (plane ? sAl : sAh) + (uint32_t)kt * 4096 + SWZ8(row, kc);
        cp16(dst, (plane ? a_l : a_h) + (size_t)(p ? t : 0) * K + kt * 32 + kc * 16, p);
    }
    auto stageB = [&](int c) {
        uint32_t bb = sB0 + (uint32_t)(c & 1) * 16384;
#pragma unroll
        for (int h = 0; h < 4; h++) {
            int i = tid + h * 256;
            int plane = i >> 9, idx = i & 511;
            int kt = idx >> 7, sub = idx & 127, row = sub >> 1, kc = sub & 1;
            uint32_t dst = bb + (plane ? 8192u : 0u) + (uint32_t)kt * 2048 + SWZ8(row, kc);
            cp16(dst, (plane ? w_l : w_h) + (size_t)(c * 64 + row) * K + kt * 32 + kc * 16, true);
        }
    };
    stageB(0); CP_COMMIT();
    if (NCH > 1) { stageB(1); CP_COMMIT(); }

#pragma unroll 1
    for (int c = 0; c < NCH; c++) {
        if (c < NCH - 1) CP_WAIT1(); else CP_WAIT0();
        __syncthreads();
        uint32_t bb = sB0 + (uint32_t)(c & 1) * 16384;
        int accHH[2][4][4], accMID[2][4][4];
        ZERO_ACC(accHH, accMID);
#pragma unroll
        for (int kt = 0; kt < 4; kt++)
            compute_tile64(sAh + kt * 4096, sAl + kt * 4096,
                           bb + kt * 2048, bb + 8192 + kt * 2048,
                           wid, lane, accHH, accMID);
        __syncthreads();
        if (c + 2 < NCH) { stageB(c + 2); CP_COMMIT(); }

#pragma unroll
        for (int mt = 0; mt < 2; mt++)
#pragma unroll
            for (int r2 = 0; r2 < 2; r2++) {
                int row = (wid & 3) * 32 + mt * 16 + (lane >> 2) + r2 * 8;
                int t = t0 + row;
                if (t >= T) continue;
                size_t orow = REMAP ? ((size_t)t + (size_t)((unsigned)t / 2048u) + 1)
                                    : (size_t)t;
                float sa = sA[t];
#pragma unroll
                for (int nt = 0; nt < 4; nt++) {
                    int col = c * 64 + (wid >> 2) * 32 + nt * 8 + (lane & 3) * 2;
                    int i0 = accHH[mt][nt][r2 * 2]     * 128 + accMID[mt][nt][r2 * 2];
                    int i1 = accHH[mt][nt][r2 * 2 + 1] * 128 + accMID[mt][nt][r2 * 2 + 1];
                    float v0 = (float)i0 * sa * uB[col];
                    float v1 = (float)i1 * sa * uB[col + 1];
                    if (biasv) {
                        float2 b2 = *(const float2*)(biasv + col);
                        v0 += b2.x; v1 += b2.y;
                    }
                    if (addend) {
                        float2 a2 = *(const float2*)(addend + orow * Nfull + col);
                        v0 += a2.x; v1 += a2.y;
                    }
                    *(float2*)(outf + orow * Nfull + col) = make_float2(v0, v1);
                }
            }
    }
}

// ---------------------------------------------------------------------------
// fc1 GEMM (N=512, 8 chunks) with fused GELU + int8 group quantization.
// Scale per (row, 32-col group); group g = c*2 + (wid>>2), 16 per row.
// ---------------------------------------------------------------------------
__global__ __launch_bounds__(256, 2)
void i8_gemm_fc1(const int8_t* __restrict__ a_h, const int8_t* __restrict__ a_l,
                 const float* __restrict__ sA,
                 const int8_t* __restrict__ w_h, const int8_t* __restrict__ w_l,
                 const float* __restrict__ uB,
                 const float* __restrict__ biasv,
                 int8_t* __restrict__ out_h, int8_t* __restrict__ out_l,
                 float* __restrict__ scg, int T)
{
    constexpr int K = 128;
    constexpr int NCH = 8;
    extern __shared__ char smem[];
    const uint32_t sbase = smem_to_u32(smem);
    const uint32_t sAh = sbase, sAl = sbase + 16384, sB0 = sbase + 32768;
    const int tid = threadIdx.x, wid = tid >> 5, lane = tid & 31;
    const int t0 = blockIdx.x * 128;

#pragma unroll
    for (int h = 0; h < 8; h++) {
        int i = tid + h * 256;
        int plane = i >> 10, idx = i & 1023;
        int kt = idx >> 8, sub = idx & 255, row = sub >> 1, kc = sub & 1;
        int t = t0 + row; bool p = t < T;
        uint32_t dst = (plane ? sAl : sAh) + (uint32_t)kt * 4096 + SWZ8(row, kc);
        cp16(dst, (plane ? a_l : a_h) + (size_t)(p ? t : 0) * K + kt * 32 + kc * 16, p);
    }
    auto stageB = [&](int c) {
        uint32_t bb = sB0 + (uint32_t)(c & 1) * 16384;
#pragma unroll
        for (int h = 0; h < 4; h++) {
            int i = tid + h * 256;
            int plane = i >> 9, idx = i & 511;
            int kt = idx >> 7, sub = idx & 127, row = sub >> 1, kc = sub & 1;
            uint32_t dst = bb + (plane ? 8192u : 0u) + (uint32_t)kt * 2048 + SWZ8(row, kc);
            cp16(dst, (plane ? w_l : w_h) + (size_t)(c * 64 + row) * K + kt * 32 + kc * 16, true);
        }
    };
    stageB(0); CP_COMMIT();
    stageB(1); CP_COMMIT();

#pragma unroll 1
    for (int c = 0; c < NCH; c++) {
        if (c < NCH - 1) CP_WAIT1(); else CP_WAIT0();
        __syncthreads();
        uint32_t bb = sB0 + (uint32_t)(c & 1) * 16384;
        int accHH[2][4][4], accMID[2][4][4];
        ZERO_ACC(accHH, accMID);
#pragma unroll
        for (int kt = 0; kt < 4; kt++)
            compute_tile64(sAh + kt * 4096, sAl + kt * 4096,
                           bb + kt * 2048, bb + 8192 + kt * 2048,
                           wid, lane, accHH, accMID);
        __syncthreads();
        if (c + 2 < NCH) { stageB(c + 2); CP_COMMIT(); }

        // Fused epilogue: bias + GELU + group quantize (group = 32 cols/warp).
#pragma unroll
        for (int mt = 0; mt < 2; mt++)
#pragma unroll
            for (int r2 = 0; r2 < 2; r2++) {
                int row = (wid & 3) * 32 + mt * 16 + (lane >> 2) + r2 * 8;
                int t = t0 + row;
                bool ok = t < T;
                float sa = sA[ok ? t : 0];
                float v[8];
                float m = 0.0f;
#pragma unroll
                for (int nt = 0; nt < 4; nt++) {
                    int col = c * 64 + (wid >> 2) * 32 + nt * 8 + (lane & 3) * 2;
                    int i0 = accHH[mt][nt][r2 * 2]     * 128 + accMID[mt][nt][r2 * 2];
                    int i1 = accHH[mt][nt][r2 * 2 + 1] * 128 + accMID[mt][nt][r2 * 2 + 1];
                    float2 b2 = *(const float2*)(biasv + col);
                    float v0 = (float)i0 * sa * uB[col]     + b2.x;
                    float v1 = (float)i1 * sa * uB[col + 1] + b2.y;
                    v0 = 0.5f * v0 * (1.0f + erff(v0 * 0.70710678118654752f));
                    v1 = 0.5f * v1 * (1.0f + erff(v1 * 0.70710678118654752f));
                    v[nt * 2] = v0; v[nt * 2 + 1] = v1;
                    m = fmaxf(m, fmaxf(fabsf(v0), fabsf(v1)));
                }
                // quad reduction (lanes sharing this row: lane ^ 1, lane ^ 2)
                m = fmaxf(m, __shfl_xor_sync(0xffffffffu, m, 1));
                m = fmaxf(m, __shfl_xor_sync(0xffffffffu, m, 2));
                float inv = (m > 0.0f) ? (16256.0f / m) : 0.0f;
                if (ok) {
#pragma unroll
                    for (int nt = 0; nt < 4; nt++) {
                        int col = c * 64 + (wid >> 2) * 32 + nt * 8 + (lane & 3) * 2;
                        char hh[2], ll[2];
#pragma unroll
                        for (int e = 0; e < 2; e++) {
                            int iv = __float2int_rn(v[nt * 2 + e] * inv);
                            int vh = (iv + 64) >> 7;
                            hh[e] = (char)vh;
                            ll[e] = (char)(iv - (vh << 7));
                        }
                        *(char2*)(out_h + (size_t)t * 512 + col) = make_char2(hh[0], hh[1]);
                        *(char2*)(out_l + (size_t)t * 512 + col) = make_char2(ll[0], ll[1]);
                    }
                    if ((lane & 3) == 0)
                        scg[(size_t)t * 16 + c * 2 + (wid >> 2)] = m * (1.0f / 16256.0f);
                }
            }
    }
}

// ---------------------------------------------------------------------------
// fc2 GEMM (K=512) with per-k-tile group dequantization into fp32 accs.
// A = h8 planes with scg scales (group = k-tile of 32). grid.y = N half.
// ---------------------------------------------------------------------------
__global__ __launch_bounds__(256, 2)
void i8_gemm_fc2(const int8_t* __restrict__ a_h, const int8_t* __restrict__ a_l,
                 const float* __restrict__ scg,
                 const int8_t* __restrict__ w_h, const int8_t* __restrict__ w_l,
                 const float* __restrict__ uB,
                 const float* __restrict__ biasv,
                 const float* __restrict__ addend,
                 float* __restrict__ outf, int T)
{
    constexpr int K = 512;
    extern __shared__ char smem[];
    const uint32_t sbase = smem_to_u32(smem);
    const uint32_t sA0 = sbase;            // 2 x 32KB
    const uint32_t sB0 = sbase + 65536;    // 2 x 16KB
    const int tid = threadIdx.x, wid = tid >> 5, lane = tid & 31;
    const int t0 = blockIdx.x * 128;
    const int nc = blockIdx.y;

    auto stage = [&](int q) {
        uint32_t ab = sA0 + (uint32_t)(q & 1) * 32768;
#pragma unroll
        for (int h = 0; h < 8; h++) {
            int i = tid + h * 256;
            int plane = i >> 10, idx = i & 1023;
            int kt = idx >> 8, sub = idx & 255, row = sub >> 1, kc = sub & 1;
            int t = t0 + row; bool p = t < T;
            uint32_t dst = ab + (plane ? 16384u : 0u) + (uint32_t)kt * 4096 + SWZ8(row, kc);
            cp16(dst, (plane ? a_l : a_h) + (size_t)(p ? t : 0) * K
                          + q * 128 + kt * 32 + kc * 16, p);
        }
        uint32_t bb = sB0 + (uint32_t)(q & 1) * 16384;
#pragma unroll
        for (int h = 0; h < 4; h++) {
            int i = tid + h * 256;
            int plane = i >> 9, idx = i & 511;
            int kt = idx >> 7, sub = idx & 127, row = sub >> 1, kc = sub & 1;
            uint32_t dst = bb + (plane ? 8192u : 0u) + (uint32_t)kt * 2048 + SWZ8(row, kc);
            cp16(dst, (plane ? w_l : w_h) + (size_t)(nc * 64 + row) * K
                          + q * 128 + kt * 32 + kc * 16, true);
        }
    };
    stage(0); CP_COMMIT();
    stage(1); CP_COMMIT();

    float facc[2][4][4];
#pragma unroll
    for (int i = 0; i < 2; i++)
#pragma unroll
        for (int j = 0; j < 4; j++)
#pragma unroll
            for (int q = 0; q < 4; q++) facc[i][j][q] = 0.0f;

#pragma unroll 1
    for (int q = 0; q < 4; q++) {
        if (q < 3) CP_WAIT1(); else CP_WAIT0();
        __syncthreads();
        uint32_t ab = sA0 + (uint32_t)(q & 1) * 32768;
        uint32_t bb = sB0 + (uint32_t)(q & 1) * 16384;
#pragma unroll
        for (int kt = 0; kt < 4; kt++) {
            int g = q * 4 + kt;
            // group scales for this thread's 4 rows
            float sg[2][2];
#pragma unroll
            for (int mt = 0; mt < 2; mt++)
#pragma unroll
                for (int r2 = 0; r2 < 2; r2++) {
                    int row = (wid & 3) * 32 + mt * 16 + (lane >> 2) + r2 * 8;
                    int t = t0 + row;
                    sg[mt][r2] = scg[(size_t)(t < T ? t : 0) * 16 + g];
                }
            uint32_t fAh[2][4], fAl[2][4], fBh[2][4], fBl[2][4];
            uint32_t sAh_ = ab + kt * 4096, sAl_ = ab + 16384 + kt * 4096;
            uint32_t sBh_ = bb + kt * 2048, sBl_ = bb + 8192 + kt * 2048;
            LOAD_FRAGS64(sAh_, sAl_, sBh_, sBl_);
#pragma unroll
            for (int mt = 0; mt < 2; mt++)
#pragma unroll
                for (int nt = 0; nt < 4; nt++) {
                    int j = nt >> 1, o = (nt & 1) * 2;
                    int aHH[4] = {0, 0, 0, 0}, aMID[4] = {0, 0, 0, 0};
                    imma(aHH,  fAh[mt], fBh[j][o], fBh[j][o + 1]);
                    imma(aMID, fAh[mt], fBl[j][o], fBl[j][o + 1]);
                    imma(aMID, fAl[mt], fBh[j][o], fBh[j][o + 1]);
#pragma unroll
                    for (int e = 0; e < 4; e++)
                        facc[mt][nt][e] += (float)(aHH[e] * 128 + aMID[e]) * sg[mt][e >> 1];
                }
        }
        __syncthreads();
        if (q + 2 < 4) { stage(q + 2); CP_COMMIT(); }
    }

#pragma unroll
    for (int mt = 0; mt < 2; mt++)
#pragma unroll
        for (int r2 = 0; r2 < 2; r2++) {
            int row = (wid & 3) * 32 + mt * 16 + (lane >> 2) + r2 * 8;
            int t = t0 + row;
            if (t >= T) continue;
#pragma unroll
            for (int nt = 0; nt < 4; nt++) {
                int col = nc * 64 + (wid >> 2) * 32 + nt * 8 + (lane & 3) * 2;
                float v0 = facc[mt][nt][r2 * 2]     * uB[col];
                float v1 = facc[mt][nt][r2 * 2 + 1] * uB[col + 1];
                float2 b2 = *(const float2*)(biasv + col);
                v0 += b2.x; v1 += b2.y;
                float2 a2 = *(const float2*)(addend + (size_t)t * 128 + col);
                v0 += a2.x; v1 += a2.y;
                *(float2*)(outf + (size_t)t * 128 + col) = make_float2(v0, v1);
            }
        }
}

// ---------------------------------------------------------------------------
// Fused QKV + rsa + imv (512 threads, 1 CTA/SM) — unchanged from R9/R11.
// ---------------------------------------------------------------------------
__global__ __launch_bounds__(512)
void i8_qkv_rsa(const int8_t* __restrict__ a_h, const int8_t* __restrict__ a_l,
                const float* __restrict__ sA,
                const int8_t* __restrict__ w_h, const int8_t* __restrict__ w_l,
                const float* __restrict__ uB,
                float* __restrict__ imv32, int T)
{
    constexpr int K = 128;
    extern __shared__ char smem[];
    const uint32_t sbase = smem_to_u32(smem);
    const uint32_t sAh = sbase, sAl = sbase + 16384, sB0 = sbase + 32768;
    float* Q   = (float*)(smem + 98304);
    float* RSA = (float*)(smem + 165888);
    const int tid = threadIdx.x, wid = tid >> 5, lane = tid & 31;
    const int t0 = blockIdx.x * 128;

    for (int i = tid; i < 1024; i += 512) RSA[i] = 0.0f;

#pragma unroll
    for (int h = 0; h < 4; h++) {
        int i = tid + h * 512;
        int plane = i >> 10, idx = i & 1023;
        int kt = idx >> 8, sub = idx & 255, row = sub >> 1, kc = sub & 1;
        int t = t0 + row; bool p = t < T;
        uint32_t dst = (plane ? sAl : sAh) + (uint32_t)kt * 4096 + SWZ8(row, kc);
        cp16(dst, (plane ? a_l : a_h) + (size_t)(p ? t : 0) * K + kt * 32 + kc * 16, p);
    }
    auto stageB = [&](int c) {
        uint32_t bb = sB0 + (uint32_t)(c & 1) * 32768;
#pragma unroll
        for (int h = 0; h < 4; h++) {
            int i = tid + h * 512;
            int plane = i >> 10, idx = i & 1023;
            int kt = idx >> 8, sub = idx & 255, row = sub >> 1, kc = sub & 1;
            uint32_t dst = bb + (plane ? 16384u : 0u) + (uint32_t)kt * 4096 + SWZ8(row, kc);
            cp16(dst, (plane ? w_l : w_h) + (size_t)(c * 128 + row) * K + kt * 32 + kc * 16, true);
        }
    };
    stageB(0); CP_COMMIT();
    stageB(1); CP_COMMIT();

#pragma unroll 1
    for (int c = 0; c < 3; c++) {
        if (c < 2) CP_WAIT1(); else CP_WAIT0();
        __syncthreads();
        uint32_t bb = sB0 + (uint32_t)(c & 1) * 32768;
        int accHH[2][4][4], accMID[2][4][4];
        ZERO_ACC(accHH, accMID);
#pragma unroll
        for (int kt = 0; kt < 4; kt++)
            compute_tile(sAh + kt * 4096, sAl + kt * 4096,
                         bb + kt * 4096, bb + 16384 + kt * 4096,
                         wid, lane, accHH, accMID);
        __syncthreads();
        if (c + 2 < 3) { stageB(c + 2); CP_COMMIT(); }

        const int colb = (wid >> 2) * 32 + (lane & 3) * 2;
        const int cb = c * 128;
#pragma unroll
        for (int mt = 0; mt < 2; mt++)
#pragma unroll
            for (int r2 = 0; r2 < 2; r2++) {
                int row = (wid & 3) * 32 + mt * 16 + (lane >> 2) + r2 * 8;
                int t = t0 + row;
                bool ok = t < T;
                float sa = ok ? sA[t] : 0.0f;
                if (c == 0) {
#pragma unroll
                    for (int nt = 0; nt < 4; nt++) {
                        int col = colb + nt * 8;
                        int i0 = accHH[mt][nt][r2*2]   * 128 + accMID[mt][nt][r2*2];
                        int i1 = accHH[mt][nt][r2*2+1] * 128 + accMID[mt][nt][r2*2+1];
                        *(float2*)(Q + row * 132 + col) =
                            make_float2((float)i0 * sa * uB[cb + col],
                                        (float)i1 * sa * uB[cb + col + 1]);
                    }
                } else if (c == 1) {
                    float p0 = 0.0f, p1 = 0.0f;
#pragma unroll
                    for (int nt = 0; nt < 4; nt++) {
                        int col = colb + nt * 8;
                        int i0 = accHH[mt][nt][r2*2]   * 128 + accMID[mt][nt][r2*2];
                        int i1 = accHH[mt][nt][r2*2+1] * 128 + accMID[mt][nt][r2*2+1];
                        float k0 = (float)i0 * sa * uB[cb + col];
                        float k1 = (float)i1 * sa * uB[cb + col + 1];
                        float2 qv = *(float2*)(Q + row * 132 + col);
                        float d = qv.x * k0 + qv.y * k1;
                        if (nt < 2) p0 += d; else p1 += d;
                    }
                    atomicAdd(&RSA[row * 8 + (wid >> 2) * 2 + 0], p0);
                    atomicAdd(&RSA[row * 8 + (wid >> 2) * 2 + 1], p1);
                } else {
#pragma unroll
                    for (int nt = 0; nt < 4; nt++) {
                        int col = colb + nt * 8;
                        int i0 = accHH[mt][nt][r2*2]   * 128 + accMID[mt][nt][r2*2];
                        int i1 = accHH[mt][nt][r2*2+1] * 128 + accMID[mt][nt][r2*2+1];
                        float v0 = (float)i0 * sa * uB[cb + col];
                        float v1 = (float)i1 * sa * uB[cb + col + 1];
                        float r = RSA[row * 8 + (wid >> 2) * 2 + (nt >> 1)] * 0.25f;
                        if (ok)
                            *(float2*)(imv32 + (size_t)t * 128 + col) =
                                make_float2(r * v0, r * v1);
                    }
                }
            }
    }
}

// ---------------------------------------------------------------------------
// Row quantization helpers.
// ---------------------------------------------------------------------------
__device__ __forceinline__ void quant_row_dev(
    const float* __restrict__ src, int8_t* __restrict__ dh,
    int8_t* __restrict__ dl, float* __restrict__ sout,
    int kd, float smul, int lane)
{
    int n4 = kd >> 7;
    float4 v[4];
    float m = 0.0f;
#pragma unroll 4
    for (int i = 0; i < n4; i++) {
        v[i] = ((const float4*)src)[lane + 32 * i];
        m = fmaxf(m, fmaxf(fmaxf(fabsf(v[i].x), fabsf(v[i].y)),
                           fmaxf(fabsf(v[i].z), fabsf(v[i].w))));
    }
#pragma unroll
    for (int o = 16; o >= 1; o >>= 1) m = fmaxf(m, __shfl_xor_sync(0xffffffffu, m, o));
    float s   = m * (1.0f / 16256.0f);
    float inv = (m > 0.0f) ? (16256.0f / m) : 0.0f;
#pragma unroll 4
    for (int i = 0; i < n4; i++) {
        float vv[4] = {v[i].x, v[i].y, v[i].z, v[i].w};
        char h4[4], l4[4];
#pragma unroll
        for (int q = 0; q < 4; q++) {
            int iv = __float2int_rn(vv[q] * inv);
            int vh = (iv + 64) >> 7;
            int vl = iv - (vh << 7);
            h4[q] = (char)vh; l4[q] = (char)vl;
        }
        ((char4*)dh)[lane + 32 * i] = make_char4(h4[0], h4[1], h4[2], h4[3]);
        ((char4*)dl)[lane + 32 * i] = make_char4(l4[0], l4[1], l4[2], l4[3]);
    }
    if (lane == 0) *sout = s * smul;
}

template<int KD>
__global__ void quant_rows(const float* __restrict__ src,
                           int8_t* __restrict__ dh, int8_t* __restrict__ dl,
                           float* __restrict__ sc, int T)
{
    int warp = threadIdx.x >> 5, lane = threadIdx.x & 31;
    int t = blockIdx.x * 8 + warp;
    if (t >= T) return;
    quant_row_dev(src + (size_t)t * KD, dh + (size_t)t * KD, dl + (size_t)t * KD,
                  sc + t, KD, 1.0f, lane);
}

__global__ void quantW(const float* __restrict__ w0, const float* __restrict__ wq,
                       const float* __restrict__ wo, const float* __restrict__ f1,
                       const float* __restrict__ f2,
                       int8_t* __restrict__ dh, int8_t* __restrict__ dl,
                       float* __restrict__ sc)
{
    int gw = blockIdx.x * 8 + (threadIdx.x >> 5);
    int lane = threadIdx.x & 31;
    if (gw >= 1792) return;
    const float* src; int kd = 128; size_t off;
    if (gw < 128)       { src = w0 + (size_t)gw * 128;          off = (size_t)gw * 128; }
    else if (gw < 896)  { int q = gw - 128;  src = wq + (size_t)q * 128; off = 16384  + (size_t)q * 128; }
    else if (gw < 1152) { int q = gw - 896;  src = wo + (size_t)q * 128; off = 114688 + (size_t)q * 128; }
    else if (gw < 1664) { int q = gw - 1152; src = f1 + (size_t)q * 128; off = 147456 + (size_t)q * 128; }
    else                { int q = gw - 1664; src = f2 + (size_t)q * 512; off = 212992 + (size_t)q * 512; kd = 512; }
    quant_row_dev(src, dh + off, dl + off, sc + gw, kd, 128.0f, lane);
}

// ---------------------------------------------------------------------------
// LayerNorm (dim 128) fused with int8 quantization.
// ---------------------------------------------------------------------------
__global__ void ln_quant(const float* __restrict__ x,
                         const float* __restrict__ g,
                         const float* __restrict__ b,
                         int8_t* __restrict__ zh, int8_t* __restrict__ zl,
                         float* __restrict__ sc, int T)
{
    int warp = threadIdx.x >> 5, lane = threadIdx.x & 31;
    int t = blockIdx.x * 8 + warp;
    if (t >= T) return;

    float4 v = ((const float4*)(x + (size_t)t * 128))[lane];
    float s = v.x + v.y + v.z + v.w;
#pragma unroll
    for (int o = 16; o >= 1; o >>= 1) s += __shfl_xor_sync(0xffffffffu, s, o);
    float mu = s * (1.0f / 128.0f);
    float dx = v.x - mu, dy = v.y - mu, dz = v.z - mu, dw = v.w - mu;
    float q = dx * dx + dy * dy + dz * dz + dw * dw;
#pragma unroll
    for (int o = 16; o >= 1; o >>= 1) q += __shfl_xor_sync(0xffffffffu, q, o);
    float rs = rsqrtf(q * (1.0f / 128.0f) + 1e-5f);

    float4 gg = ((const float4*)g)[lane];
    float4 bb = ((const float4*)b)[lane];
    float o0 = dx * rs * gg.x + bb.x;
    float o1 = dy * rs * gg.y + bb.y;
    float o2 = dz * rs * gg.z + bb.z;
    float o3 = dw * rs * gg.w + bb.w;

    float m = fmaxf(fmaxf(fabsf(o0), fabsf(o1)), fmaxf(fabsf(o2), fabsf(o3)));
#pragma unroll
    for (int o = 16; o >= 1; o >>= 1) m = fmaxf(m, __shfl_xor_sync(0xffffffffu, m, o));
    float sq  = m * (1.0f / 16256.0f);
    float inv = (m > 0.0f) ? (16256.0f / m) : 0.0f;

    float vv[4] = {o0, o1, o2, o3};
    char h4[4], l4[4];
#pragma unroll
    for (int qi = 0; qi < 4; qi++) {
        int iv = __float2int_rn(vv[qi] * inv);
        int vh = (iv + 64) >> 7;
        int vl = iv - (vh << 7);
        h4[qi] = (char)vh; l4[qi] = (char)vl;
    }
    size_t base = (size_t)t * 128;
    ((char4*)(zh + base))[lane] = make_char4(h4[0], h4[1], h4[2], h4[3]);
    ((char4*)(zl + base))[lane] = make_char4(l4[0], l4[1], l4[2], l4[3]);
    if (lane == 0) sc[t] = sq;
}

// ---------------------------------------------------------------------------
// Chunked cumsum + fused quantization.
// ---------------------------------------------------------------------------
__global__ void csum_partial(const float* __restrict__ imv, float* __restrict__ part)
{
    int c = blockIdx.x, i = blockIdx.y, f = threadIdx.x;
    size_t base = ((size_t)i * BP1 + c * 128) * 128 + f;
    float sum = 0.0f;
#pragma unroll 8
    for (int j = 0; j < 128; j++) sum += imv[base + (size_t)j * 128];
    part[((size_t)i * 16 + c) * 128 + f] = sum;
}

__global__ void csum_scan(float* __restrict__ part)
{
    int i = blockIdx.x, f = threadIdx.x;
    float run = 0.0f;
#pragma unroll
    for (int c = 0; c < 16; c++) {
        size_t idx = ((size_t)i * 16 + c) * 128 + f;
        float t = part[idx];
        part[idx] = run;
        run += t;
    }
}

__global__ void csum_apply(const float* __restrict__ imv,
                           const float* __restrict__ part,
                           int8_t* __restrict__ dh, int8_t* __restrict__ dl,
                           float* __restrict__ sc)
{
    __shared__ float sm[4][8];
    int c = blockIdx.x, i = blockIdx.y, f = threadIdx.x;
    int warp = f >> 5, lane = f & 31;
    size_t base = ((size_t)i * BP1 + c * 128) * 128 + f;
    float acc = part[((size_t)i * 16 + c) * 128 + f];

#pragma unroll 1
    for (int jb = 0; jb < 16; jb++) {
        float val[8], mx[8];
#pragma unroll
        for (int u = 0; u < 8; u++) {
            acc += imv[base + (size_t)(jb * 8 + u) * 128];
            val[u] = acc;
            mx[u] = fabsf(acc);
        }
#pragma unroll
        for (int o = 16; o >= 1; o >>= 1)
#pragma unroll
            for (int u = 0; u < 8; u++)
                mx[u] = fmaxf(mx[u], __shfl_xor_sync(0xffffffffu, mx[u], o));
        if (lane == 0) {
#pragma unroll
            for (int u = 0; u < 8; u++) sm[warp][u] = mx[u];
        }
        __syncthreads();
#pragma unroll
        for (int u = 0; u < 8; u++) {
            float m = fmaxf(fmaxf(sm[0][u], sm[1][u]), fmaxf(sm[2][u], sm[3][u]));
            float inv = (m > 0.0f) ? (16256.0f / m) : 0.0f;
            int iv = __float2int_rn(val[u] * inv);
            int vh = (iv + 64) >> 7;
            int vl = iv - (vh << 7);
            size_t row = (size_t)i * BP1 + c * 128 + jb * 8 + u;
            dh[row * 128 + f] = (int8_t)vh;
            dl[row * 128 + f] = (int8_t)vl;
            if (f == 0) sc[row] = m * (1.0f / 16256.0f);
        }
        __syncthreads();
    }
}

__global__ void quant_last(const float* __restrict__ imv,
                           int8_t* __restrict__ dh, int8_t* __restrict__ dl,
                           float* __restrict__ sc)
{
    int w = blockIdx.x * 8 + (threadIdx.x >> 5), lane = threadIdx.x & 31;
    if (w >= AA) return;
    size_t row = (size_t)w * BP1 + BB;
    quant_row_dev(imv + row * 128, dh + row * 128, dl + row * 128,
                  sc + row, 128, 1.0f, lane);
}

__global__ void cls_kernel(const float* __restrict__ cls,
                           const float* __restrict__ bias,
                           float* __restrict__ out)
{
    int i = blockIdx.x, l = threadIdx.x;
    out[(size_t)i * BP1 * 128 + l] = cls[i * 128 + l] + bias[(size_t)i * BP1 * 128 + l];
}

// ---------------------------------------------------------------------------
// Launch
// ---------------------------------------------------------------------------
extern "C" void kernel_launch(void* const* d_in, const int* in_sizes, int n_in,
                              void* d_out, int out_size)
{
    const float* x      = (const float*)d_in[0];
    const float* weight = (const float*)d_in[1];
    const float* cls    = (const float*)d_in[2];
    const float* bias   = (const float*)d_in[3];
    const float* Wqkv   = (const float*)d_in[4];
    const float* Wo     = (const float*)d_in[5];
    const float* ln1_g  = (const float*)d_in[6];
    const float* ln1_b  = (const float*)d_in[7];
    const float* ln2_g  = (const float*)d_in[8];
    const float* ln2_b  = (const float*)d_in[9];
    const float* fc1_w  = (const float*)d_in[10];
    const float* fc1_b  = (const float*)d_in[11];
    const float* fc2_w  = (const float*)d_in[12];
    const float* fc2_b  = (const float*)d_in[13];
    float* s = (float*)d_out;

    void *pbig, *pact, *ph8, *pwh, *pwl, *pscw, *psct, *psch, *ppart;
    cudaGetSymbolAddress(&pbig, g_big);
    cudaGetSymbolAddress(&pact, g_act8);
    cudaGetSymbolAddress(&ph8,  g_h8);
    cudaGetSymbolAddress(&pwh,  g_w8h);
    cudaGetSymbolAddress(&pwl,  g_w8l);
    cudaGetSymbolAddress(&pscw, g_sc_w);
    cudaGetSymbolAddress(&psct, g_sc_tok);
    cudaGetSymbolAddress(&psch, g_sch);
    cudaGetSymbolAddress(&ppart, g_part);

    float*  big   = (float*)pbig;
    int8_t* act8  = (int8_t*)pact;
    int8_t* h8    = (int8_t*)ph8;
    int8_t* w8h   = (int8_t*)pwh;
    int8_t* w8l   = (int8_t*)pwl;
    float*  sc_w  = (float*)pscw;
    float*  sc_t  = (float*)psct;
    float*  sc_h  = (float*)psch;
    float*  partb = (float*)ppart;

    const int T  = TTOK;
    const int Tx = TXTOK;
    const int tokBlocks = (T + 127) / 128;   // 1922
    const int txBlocks  = Tx / 128;          // 1920

    int8_t* z8h   = act8;
    int8_t* z8l   = z8h + (size_t)T * 128;
    int8_t* imv8h = z8h;                     // alias (z dead after qkv)
    int8_t* imv8l = z8l;
    int8_t* h8h   = h8;
    int8_t* h8l   = h8h + (size_t)T * 512;
    int8_t* x8h   = h8;                      // alias (x only used at init)
    int8_t* x8l   = x8h + (size_t)Tx * 128;
    float* imv32 = big;                      // T*128
    float* s_z   = sc_t;
    float* s_imv = sc_t + T;
    float* s_x   = sc_t + 3 * (size_t)T;

    const int SM_RES2 = 65536;
    const int SM_QKV  = 169984;
    const int SM_K512 = 98304;
    cudaFuncSetAttribute(i8_gemm_res2<2,1>, cudaFuncAttributeMaxDynamicSharedMemorySize, SM_RES2);
    cudaFuncSetAttribute(i8_gemm_res2<2,0>, cudaFuncAttributeMaxDynamicSharedMemorySize, SM_RES2);
    cudaFuncSetAttribute(i8_gemm_fc1,  cudaFuncAttributeMaxDynamicSharedMemorySize, SM_RES2);
    cudaFuncSetAttribute(i8_gemm_fc2,  cudaFuncAttributeMaxDynamicSharedMemorySize, SM_K512);
    cudaFuncSetAttribute(i8_qkv_rsa,   cudaFuncAttributeMaxDynamicSharedMemorySize, SM_QKV);

    // 1: weights
    quantW<<<224, 256>>>(weight, Wqkv, Wo, fc1_w, fc2_w, w8h, w8l, sc_w);
    // 2: x rows
    quant_rows<128><<<(Tx + 7) / 8, 256>>>(x, x8h, x8l, s_x, Tx);
    // 3: cls row
    cls_kernel<<<AA, 128>>>(cls, bias, s);
    // 4: s = concat([cls, x @ W^T], 1) + bias
    i8_gemm_res2<2,1><<<txBlocks, 256, SM_RES2>>>(
        x8h, x8l, s_x, w8h, w8l, sc_w, nullptr, bias, s, Tx);

    for (int a = 0; a < 2; a++) {
        const int8_t* wq_h = w8h + 16384 + (size_t)a * 49152;
        const int8_t* wq_l = w8l + 16384 + (size_t)a * 49152;
        const float*  uq   = sc_w + 128 + a * 384;
        const int8_t* wo_h = w8h + 114688 + (size_t)a * 16384;
        const int8_t* wo_l = w8l + 114688 + (size_t)a * 16384;
        const float*  uo   = sc_w + 896 + a * 128;

        // z = LN1(s)
        ln_quant<<<(T + 7) / 8, 256>>>(s, ln1_g, ln1_b, z8h, z8l, s_z, T);
        // imv32 = 0.25*(q.k per head)*v  (fused qkv + rsa)
        i8_qkv_rsa<<<tokBlocks, 512, SM_QKV>>>(
            z8h, z8l, s_z, wq_h, wq_l, uq, imv32, T);
        // chunked causal cumsum + quantization
        csum_partial<<<dim3(16, AA), 128>>>(imv32, partb);
        csum_scan<<<AA, 128>>>(partb);
        csum_apply<<<dim3(16, AA), 128>>>(imv32, partb, imv8h, imv8l, s_imv);
        quant_last<<<(AA + 7) / 8, 256>>>(imv32, imv8h, imv8l, s_imv);
        // s += imv @ Wo^T
        i8_gemm_res2<2,0><<<tokBlocks, 256, SM_RES2>>>(
            imv8h, imv8l, s_imv, wo_h, wo_l, uo, nullptr, s, s, T);
        // z = LN2(s)
        ln_quant<<<(T + 7) / 8, 256>>>(s, ln2_g, ln2_b, z8h, z8l, s_z, T);
        // h8 = quant(gelu(z @ fc1^T + b1)) with 32-col group scales (fused)
        i8_gemm_fc1<<<tokBlocks, 256, SM_RES2>>>(
            z8h, z8l, s_z, w8h + 147456, w8l + 147456, sc_w + 1152,
            fc1_b, h8h, h8l, sc_h, T);
        // s = h @ fc2^T + b2 + s  (K=512, group-dequant accumulate)
        i8_gemm_fc2<<<dim3(tokBlocks, 2), 256, SM_K512>>>(
            h8h, h8l, sc_h, w8h + 212992, w8l + 212992, sc_w + 1664,
            fc2_b, s, s, T);
    }
    (void)in_sizes; (void)n_in; (void)out_size;
}

// round 13
// speedup vs baseline: 1.0042x; 1.0042x over previous
#include <cuda_runtime.h>
#include <cuda_bf16.h>
#include <math.h>
#include <stdint.h>

// ---------------------------------------------------------------------------
// EEGformer forward. int8 dual-plane GEMMs (mma.sync.m16n8k32.s8).
// R13: fc2 re-tiled to M=64 x N=128 (single pass over h8 planes, 2 CTAs/SM).
// A=120, B=2048, Bp1=2049, M=128, T = 120*2049 = 245880 tokens.
// ---------------------------------------------------------------------------

#define AA    120
#define BB    2048
#define BP1   2049
#define TTOK  (AA * BP1)      // 245880
#define TXTOK (AA * BB)       // 245760
#define TPAD  246016

__device__ float  g_big[(size_t)TTOK * 128];        // imv32 fp32
__device__ int8_t g_act8[(size_t)TTOK * 256];       // z / imv planes
__device__ int8_t g_h8  [(size_t)TTOK * 512 * 2];   // h planes / x planes
__device__ int8_t g_w8h[278528];
__device__ int8_t g_w8l[278528];
__device__ float  g_sc_w[1792];
__device__ float  g_sc_tok[(size_t)3 * TTOK + TXTOK];
__device__ float  g_sch[(size_t)TPAD * 16];         // h group scales
__device__ float  g_part[AA * 16 * 128];

// ---------------------------------------------------------------------------
// PTX helpers
// ---------------------------------------------------------------------------
__device__ __forceinline__ uint32_t smem_to_u32(const void* p) {
    uint32_t a;
    asm("{ .reg .u64 t; cvta.to.shared.u64 t, %1; cvt.u32.u64 %0, t; }" : "=r"(a) : "l"(p));
    return a;
}
__device__ __forceinline__ void ldm4(uint32_t r[4], uint32_t addr) {
    asm volatile("ldmatrix.sync.aligned.m8n8.x4.shared.b16 {%0,%1,%2,%3}, [%4];"
        : "=r"(r[0]), "=r"(r[1]), "=r"(r[2]), "=r"(r[3]) : "r"(addr));
}
__device__ __forceinline__ void imma(int d[4], const uint32_t a[4],
                                     uint32_t b0, uint32_t b1) {
    asm volatile("mma.sync.aligned.m16n8k32.row.col.s32.s8.s8.s32 "
        "{%0,%1,%2,%3}, {%4,%5,%6,%7}, {%8,%9}, {%0,%1,%2,%3};"
        : "+r"(d[0]), "+r"(d[1]), "+r"(d[2]), "+r"(d[3])
        : "r"(a[0]), "r"(a[1]), "r"(a[2]), "r"(a[3]), "r"(b0), "r"(b1));
}
__device__ __forceinline__ void cp16(uint32_t saddr, const void* g, bool p) {
    int sz = p ? 16 : 0;
    asm volatile("cp.async.cg.shared.global [%0], [%1], 16, %2;"
        :: "r"(saddr), "l"(g), "r"(sz) : "memory");
}
#define CP_COMMIT() asm volatile("cp.async.commit_group;" ::: "memory")
#define CP_WAIT1()  asm volatile("cp.async.wait_group 1;" ::: "memory")
#define CP_WAIT0()  asm volatile("cp.async.wait_group 0;" ::: "memory")

// 32-byte-row swizzle inside one k-tile: line = row>>2 (128B)
#define SWZ8(row, kc) ((((row) >> 2) * 128) + \
    (((((row) & 3) * 2 + (kc)) ^ (((row) >> 2) & 7)) << 4))

// Fragment loads, block 128(M) x 64(N), 8 warps 4(M, wid&3) x 2(N, wid>>2).
#define LOAD_FRAGS64(sAh, sAl, sBh, sBl) do { \
    int arow = (wid & 3) * 32 + (lane & 7) + ((lane >> 3) & 1) * 8; \
    int akc  = lane >> 4; \
    _Pragma("unroll") for (int mt = 0; mt < 2; mt++) { \
        uint32_t off = SWZ8(arow + mt * 16, akc); \
        ldm4(fAh[mt], (sAh) + off); \
        ldm4(fAl[mt], (sAl) + off); \
    } \
    int brow = (wid >> 2) * 32 + ((lane >> 4) & 1) * 8 + (lane & 7); \
    int bkc  = (lane >> 3) & 1; \
    _Pragma("unroll") for (int j = 0; j < 2; j++) { \
        uint32_t off = SWZ8(brow + j * 16, bkc); \
        ldm4(fBh[j], (sBh) + off); \
        ldm4(fBl[j], (sBl) + off); \
    } \
} while (0)

__device__ __forceinline__ void compute_tile64(
    uint32_t sAh_, uint32_t sAl_, uint32_t sBh_, uint32_t sBl_,
    int wid, int lane, int accHH[2][4][4], int accMID[2][4][4])
{
    uint32_t fAh[2][4], fAl[2][4], fBh[2][4], fBl[2][4];
    LOAD_FRAGS64(sAh_, sAl_, sBh_, sBl_);
#pragma unroll
    for (int mt = 0; mt < 2; mt++)
#pragma unroll
        for (int nt = 0; nt < 4; nt++) {
            int j = nt >> 1, o = (nt & 1) * 2;
            imma(accHH[mt][nt],  fAh[mt], fBh[j][o], fBh[j][o + 1]);
            imma(accMID[mt][nt], fAh[mt], fBl[j][o], fBl[j][o + 1]);
            imma(accMID[mt][nt], fAl[mt], fBh[j][o], fBh[j][o + 1]);
        }
}

// 16-warp variant (qkv_rsa): block 128x128, warp 32x32.
__device__ __forceinline__ void compute_tile(
    uint32_t sAh_, uint32_t sAl_, uint32_t sBh_, uint32_t sBl_,
    int wid, int lane, int accHH[2][4][4], int accMID[2][4][4])
{
    uint32_t fAh[2][4], fAl[2][4], fBh[2][4], fBl[2][4];
    LOAD_FRAGS64(sAh_, sAl_, sBh_, sBl_);
#pragma unroll
    for (int mt = 0; mt < 2; mt++)
#pragma unroll
        for (int nt = 0; nt < 4; nt++) {
            int j = nt >> 1, o = (nt & 1) * 2;
            imma(accHH[mt][nt],  fAh[mt], fBh[j][o], fBh[j][o + 1]);
            imma(accMID[mt][nt], fAh[mt], fBl[j][o], fBl[j][o + 1]);
            imma(accMID[mt][nt], fAl[mt], fBh[j][o], fBh[j][o + 1]);
        }
}

#define ZERO_ACC(accHH, accMID) do { \
    _Pragma("unroll") for (int i = 0; i < 2; i++) \
    _Pragma("unroll") for (int j = 0; j < 4; j++) \
    _Pragma("unroll") for (int q = 0; q < 4; q++) { accHH[i][j][q] = 0; accMID[i][j][q] = 0; } \
} while (0)

// ---------------------------------------------------------------------------
// Resident-A GEMM, 256 threads, 2 CTAs/SM (init, Wo). N = NCH*64.
// ---------------------------------------------------------------------------
template<int NCH, int REMAP>
__global__ __launch_bounds__(256, 2)
void i8_gemm_res2(const int8_t* __restrict__ a_h, const int8_t* __restrict__ a_l,
                  const float* __restrict__ sA,
                  const int8_t* __restrict__ w_h, const int8_t* __restrict__ w_l,
                  const float* __restrict__ uB,
                  const float* __restrict__ biasv,
                  const float* __restrict__ addend,
                  float* __restrict__ outf, int T)
{
    constexpr int K = 128;
    constexpr int Nfull = NCH * 64;
    extern __shared__ char smem[];
    const uint32_t sbase = smem_to_u32(smem);
    const uint32_t sAh = sbase, sAl = sbase + 16384, sB0 = sbase + 32768;
    const int tid = threadIdx.x, wid = tid >> 5, lane = tid & 31;
    const int t0 = blockIdx.x * 128;

#pragma unroll
    for (int h = 0; h < 8; h++) {
        int i = tid + h * 256;
        int plane = i >> 10, idx = i & 1023;
        int kt = idx >> 8, sub = idx & 255, row = sub >> 1, kc = sub & 1;
        int t = t0 + row; bool p = t < T;
        uint32_t dst = (plane ? sAl : sAh) + (uint32_t)kt * 4096 + SWZ8(row, kc);
        cp16(dst, (plane ? a_l : a_h) + (size_t)(p ? t : 0) * K + kt * 32 + kc * 16, p);
    }
    auto stageB = [&](int c) {
        uint32_t bb = sB0 + (uint32_t)(c & 1) * 16384;
#pragma unroll
        for (int h = 0; h < 4; h++) {
            int i = tid + h * 256;
            int plane = i >> 9, idx = i & 511;
            int kt = idx >> 7, sub = idx & 127, row = sub >> 1, kc = sub & 1;
            uint32_t dst = bb + (plane ? 8192u : 0u) + (uint32_t)kt * 2048 + SWZ8(row, kc);
            cp16(dst, (plane ? w_l : w_h) + (size_t)(c * 64 + row) * K + kt * 32 + kc * 16, true);
        }
    };
    stageB(0); CP_COMMIT();
    if (NCH > 1) { stageB(1); CP_COMMIT(); }

#pragma unroll 1
    for (int c = 0; c < NCH; c++) {
        if (c < NCH - 1) CP_WAIT1(); else CP_WAIT0();
        __syncthreads();
        uint32_t bb = sB0 + (uint32_t)(c & 1) * 16384;
        int accHH[2][4][4], accMID[2][4][4];
        ZERO_ACC(accHH, accMID);
#pragma unroll
        for (int kt = 0; kt < 4; kt++)
            compute_tile64(sAh + kt * 4096, sAl + kt * 4096,
                           bb + kt * 2048, bb + 8192 + kt * 2048,
                           wid, lane, accHH, accMID);
        __syncthreads();
        if (c + 2 < NCH) { stageB(c + 2); CP_COMMIT(); }

#pragma unroll
        for (int mt = 0; mt < 2; mt++)
#pragma unroll
            for (int r2 = 0; r2 < 2; r2++) {
                int row = (wid & 3) * 32 + mt * 16 + (lane >> 2) + r2 * 8;
                int t = t0 + row;
                if (t >= T) continue;
                size_t orow = REMAP ? ((size_t)t + (size_t)((unsigned)t / 2048u) + 1)
                                    : (size_t)t;
                float sa = sA[t];
#pragma unroll
                for (int nt = 0; nt < 4; nt++) {
                    int col = c * 64 + (wid >> 2) * 32 + nt * 8 + (lane & 3) * 2;
                    int i0 = accHH[mt][nt][r2 * 2]     * 128 + accMID[mt][nt][r2 * 2];
                    int i1 = accHH[mt][nt][r2 * 2 + 1] * 128 + accMID[mt][nt][r2 * 2 + 1];
                    float v0 = (float)i0 * sa * uB[col];
                    float v1 = (float)i1 * sa * uB[col + 1];
                    if (biasv) {
                        float2 b2 = *(const float2*)(biasv + col);
                        v0 += b2.x; v1 += b2.y;
                    }
                    if (addend) {
                        float2 a2 = *(const float2*)(addend + orow * Nfull + col);
                        v0 += a2.x; v1 += a2.y;
                    }
                    *(float2*)(outf + orow * Nfull + col) = make_float2(v0, v1);
                }
            }
    }
}

// ---------------------------------------------------------------------------
// fc1 GEMM (N=512, 8 chunks) with fused GELU + int8 group quantization.
// ---------------------------------------------------------------------------
__global__ __launch_bounds__(256, 2)
void i8_gemm_fc1(const int8_t* __restrict__ a_h, const int8_t* __restrict__ a_l,
                 const float* __restrict__ sA,
                 const int8_t* __restrict__ w_h, const int8_t* __restrict__ w_l,
                 const float* __restrict__ uB,
                 const float* __restrict__ biasv,
                 int8_t* __restrict__ out_h, int8_t* __restrict__ out_l,
                 float* __restrict__ scg, int T)
{
    constexpr int K = 128;
    constexpr int NCH = 8;
    extern __shared__ char smem[];
    const uint32_t sbase = smem_to_u32(smem);
    const uint32_t sAh = sbase, sAl = sbase + 16384, sB0 = sbase + 32768;
    const int tid = threadIdx.x, wid = tid >> 5, lane = tid & 31;
    const int t0 = blockIdx.x * 128;

#pragma unroll
    for (int h = 0; h < 8; h++) {
        int i = tid + h * 256;
        int plane = i >> 10, idx = i & 1023;
        int kt = idx >> 8, sub = idx & 255, row = sub >> 1, kc = sub & 1;
        int t = t0 + row; bool p = t < T;
        uint32_t dst = (plane ? sAl : sAh) + (uint32_t)kt * 4096 + SWZ8(row, kc);
        cp16(dst, (plane ? a_l : a_h) + (size_t)(p ? t : 0) * K + kt * 32 + kc * 16, p);
    }
    auto stageB = [&](int c) {
        uint32_t bb = sB0 + (uint32_t)(c & 1) * 16384;
#pragma unroll
        for (int h = 0; h < 4; h++) {
            int i = tid + h * 256;
            int plane = i >> 9, idx = i & 511;
            int kt = idx >> 7, sub = idx & 127, row = sub >> 1, kc = sub & 1;
            uint32_t dst = bb + (plane ? 8192u : 0u) + (uint32_t)kt * 2048 + SWZ8(row, kc);
            cp16(dst, (plane ? w_l : w_h) + (size_t)(c * 64 + row) * K + kt * 32 + kc * 16, true);
        }
    };
    stageB(0); CP_COMMIT();
    stageB(1); CP_COMMIT();

#pragma unroll 1
    for (int c = 0; c < NCH; c++) {
        if (c < NCH - 1) CP_WAIT1(); else CP_WAIT0();
        __syncthreads();
        uint32_t bb = sB0 + (uint32_t)(c & 1) * 16384;
        int accHH[2][4][4], accMID[2][4][4];
        ZERO_ACC(accHH, accMID);
#pragma unroll
        for (int kt = 0; kt < 4; kt++)
            compute_tile64(sAh + kt * 4096, sAl + kt * 4096,
                           bb + kt * 2048, bb + 8192 + kt * 2048,
                           wid, lane, accHH, accMID);
        __syncthreads();
        if (c + 2 < NCH) { stageB(c + 2); CP_COMMIT(); }

#pragma unroll
        for (int mt = 0; mt < 2; mt++)
#pragma unroll
            for (int r2 = 0; r2 < 2; r2++) {
                int row = (wid & 3) * 32 + mt * 16 + (lane >> 2) + r2 * 8;
                int t = t0 + row;
                bool ok = t < T;
                float sa = sA[ok ? t : 0];
                float v[8];
                float m = 0.0f;
#pragma unroll
                for (int nt = 0; nt < 4; nt++) {
                    int col = c * 64 + (wid >> 2) * 32 + nt * 8 + (lane & 3) * 2;
                    int i0 = accHH[mt][nt][r2 * 2]     * 128 + accMID[mt][nt][r2 * 2];
                    int i1 = accHH[mt][nt][r2 * 2 + 1] * 128 + accMID[mt][nt][r2 * 2 + 1];
                    float2 b2 = *(const float2*)(biasv + col);
                    float v0 = (float)i0 * sa * uB[col]     + b2.x;
                    float v1 = (float)i1 * sa * uB[col + 1] + b2.y;
                    v0 = 0.5f * v0 * (1.0f + erff(v0 * 0.70710678118654752f));
                    v1 = 0.5f * v1 * (1.0f + erff(v1 * 0.70710678118654752f));
                    v[nt * 2] = v0; v[nt * 2 + 1] = v1;
                    m = fmaxf(m, fmaxf(fabsf(v0), fabsf(v1)));
                }
                m = fmaxf(m, __shfl_xor_sync(0xffffffffu, m, 1));
                m = fmaxf(m, __shfl_xor_sync(0xffffffffu, m, 2));
                float inv = (m > 0.0f) ? (16256.0f / m) : 0.0f;
                if (ok) {
#pragma unroll
                    for (int nt = 0; nt < 4; nt++) {
                        int col = c * 64 + (wid >> 2) * 32 + nt * 8 + (lane & 3) * 2;
                        char hh[2], ll[2];
#pragma unroll
                        for (int e = 0; e < 2; e++) {
                            int iv = __float2int_rn(v[nt * 2 + e] * inv);
                            int vh = (iv + 64) >> 7;
                            hh[e] = (char)vh;
                            ll[e] = (char)(iv - (vh << 7));
                        }
                        *(char2*)(out_h + (size_t)t * 512 + col) = make_char2(hh[0], hh[1]);
                        *(char2*)(out_l + (size_t)t * 512 + col) = make_char2(ll[0], ll[1]);
                    }
                    if ((lane & 3) == 0)
                        scg[(size_t)t * 16 + c * 2 + (wid >> 2)] = m * (1.0f / 16256.0f);
                }
            }
    }
}

// ---------------------------------------------------------------------------
// fc2 GEMM (K=512), M=64 x N=128 tiles, single pass over h8 (2 CTAs/SM).
// 8 warps: mwid = wid&1 (2 x 32 rows), nwid = wid>>1 (4 x 32 cols).
// smem/stage 48KB: Ah 8K | Al 8K | Bh 16K | Bl 16K; double-buffered 96KB.
// ---------------------------------------------------------------------------
__global__ __launch_bounds__(256, 2)
void i8_gemm_fc2m64(const int8_t* __restrict__ a_h, const int8_t* __restrict__ a_l,
                    const float* __restrict__ scg,
                    const int8_t* __restrict__ w_h, const int8_t* __restrict__ w_l,
                    const float* __restrict__ uB,
                    const float* __restrict__ biasv,
                    const float* __restrict__ addend,
                    float* __restrict__ outf, int T)
{
    constexpr int K = 512;
    extern __shared__ char smem[];
    const uint32_t sbase = smem_to_u32(smem);
    const int tid = threadIdx.x, wid = tid >> 5, lane = tid & 31;
    const int t0 = blockIdx.x * 64;
    const int mwid = wid & 1, nwid = wid >> 1;

    auto stage = [&](int q) {
        uint32_t sb = sbase + (uint32_t)(q & 1) * 49152;
        // A: 2 planes x 4 kt x 64 rows x 2 kc = 1024 cp16
#pragma unroll
        for (int h = 0; h < 4; h++) {
            int i = tid + h * 256;
            int plane = i >> 9, idx = i & 511;
            int kt = idx >> 7, sub = idx & 127, row = sub >> 1, kc = sub & 1;
            int t = t0 + row; bool p = t < T;
            uint32_t dst = sb + (plane ? 8192u : 0u) + (uint32_t)kt * 2048 + SWZ8(row, kc);
            cp16(dst, (plane ? a_l : a_h) + (size_t)(p ? t : 0) * K
                          + q * 128 + kt * 32 + kc * 16, p);
        }
        // B: 2 planes x 4 kt x 128 rows x 2 kc = 2048 cp16
#pragma unroll
        for (int h = 0; h < 8; h++) {
            int i = tid + h * 256;
            int plane = i >> 10, idx = i & 1023;
            int kt = idx >> 8, sub = idx & 255, row = sub >> 1, kc = sub & 1;
            uint32_t dst = sb + 16384 + (plane ? 16384u : 0u) + (uint32_t)kt * 4096 + SWZ8(row, kc);
            cp16(dst, (plane ? w_l : w_h) + (size_t)row * K
                          + q * 128 + kt * 32 + kc * 16, true);
        }
    };
    stage(0); CP_COMMIT();
    stage(1); CP_COMMIT();

    float facc[2][4][4];
#pragma unroll
    for (int i = 0; i < 2; i++)
#pragma unroll
        for (int j = 0; j < 4; j++)
#pragma unroll
            for (int q = 0; q < 4; q++) facc[i][j][q] = 0.0f;

#pragma unroll 1
    for (int q = 0; q < 4; q++) {
        if (q < 3) CP_WAIT1(); else CP_WAIT0();
        __syncthreads();
        uint32_t sb = sbase + (uint32_t)(q & 1) * 49152;
#pragma unroll
        for (int kt = 0; kt < 4; kt++) {
            int g = q * 4 + kt;
            float sg[2][2];
#pragma unroll
            for (int mt = 0; mt < 2; mt++)
#pragma unroll
                for (int r2 = 0; r2 < 2; r2++) {
                    int row = mwid * 32 + mt * 16 + (lane >> 2) + r2 * 8;
                    int t = t0 + row;
                    sg[mt][r2] = scg[(size_t)(t < T ? t : 0) * 16 + g];
                }
            // fragments (M=64 layout)
            uint32_t fAh[2][4], fAl[2][4], fBh[2][4], fBl[2][4];
            {
                int arow = mwid * 32 + (lane & 7) + ((lane >> 3) & 1) * 8;
                int akc  = lane >> 4;
#pragma unroll
                for (int mt = 0; mt < 2; mt++) {
                    uint32_t off = (uint32_t)kt * 2048 + SWZ8(arow + mt * 16, akc);
                    ldm4(fAh[mt], sb + off);
                    ldm4(fAl[mt], sb + 8192 + off);
                }
                int brow = nwid * 32 + ((lane >> 4) & 1) * 8 + (lane & 7);
                int bkc  = (lane >> 3) & 1;
#pragma unroll
                for (int j = 0; j < 2; j++) {
                    uint32_t off = (uint32_t)kt * 4096 + SWZ8(brow + j * 16, bkc);
                    ldm4(fBh[j], sb + 16384 + off);
                    ldm4(fBl[j], sb + 32768 + off);
                }
            }
#pragma unroll
            for (int mt = 0; mt < 2; mt++)
#pragma unroll
                for (int nt = 0; nt < 4; nt++) {
                    int j = nt >> 1, o = (nt & 1) * 2;
                    int aHH[4] = {0, 0, 0, 0}, aMID[4] = {0, 0, 0, 0};
                    imma(aHH,  fAh[mt], fBh[j][o], fBh[j][o + 1]);
                    imma(aMID, fAh[mt], fBl[j][o], fBl[j][o + 1]);
                    imma(aMID, fAl[mt], fBh[j][o], fBh[j][o + 1]);
#pragma unroll
                    for (int e = 0; e < 4; e++)
                        facc[mt][nt][e] += (float)(aHH[e] * 128 + aMID[e]) * sg[mt][e >> 1];
                }
        }
        __syncthreads();
        if (q + 2 < 4) { stage(q + 2); CP_COMMIT(); }
    }

#pragma unroll
    for (int mt = 0; mt < 2; mt++)
#pragma unroll
        for (int r2 = 0; r2 < 2; r2++) {
            int row = mwid * 32 + mt * 16 + (lane >> 2) + r2 * 8;
            int t = t0 + row;
            if (t >= T) continue;
#pragma unroll
            for (int nt = 0; nt < 4; nt++) {
                int col = nwid * 32 + nt * 8 + (lane & 3) * 2;
                float v0 = facc[mt][nt][r2 * 2]     * uB[col];
                float v1 = facc[mt][nt][r2 * 2 + 1] * uB[col + 1];
                float2 b2 = *(const float2*)(biasv + col);
                v0 += b2.x; v1 += b2.y;
                float2 a2 = *(const float2*)(addend + (size_t)t * 128 + col);
                v0 += a2.x; v1 += a2.y;
                *(float2*)(outf + (size_t)t * 128 + col) = make_float2(v0, v1);
            }
        }
}

// ---------------------------------------------------------------------------
// Fused QKV + rsa + imv (512 threads, 1 CTA/SM).
// ---------------------------------------------------------------------------
__global__ __launch_bounds__(512)
void i8_qkv_rsa(const int8_t* __restrict__ a_h, const int8_t* __restrict__ a_l,
                const float* __restrict__ sA,
                const int8_t* __restrict__ w_h, const int8_t* __restrict__ w_l,
                const float* __restrict__ uB,
                float* __restrict__ imv32, int T)
{
    constexpr int K = 128;
    extern __shared__ char smem[];
    const uint32_t sbase = smem_to_u32(smem);
    const uint32_t sAh = sbase, sAl = sbase + 16384, sB0 = sbase + 32768;
    float* Q   = (float*)(smem + 98304);
    float* RSA = (float*)(smem + 165888);
    const int tid = threadIdx.x, wid = tid >> 5, lane = tid & 31;
    const int t0 = blockIdx.x * 128;

    for (int i = tid; i < 1024; i += 512) RSA[i] = 0.0f;

#pragma unroll
    for (int h = 0; h < 4; h++) {
        int i = tid + h * 512;
        int plane = i >> 10, idx = i & 1023;
        int kt = idx >> 8, sub = idx & 255, row = sub >> 1, kc = sub & 1;
        int t = t0 + row; bool p = t < T;
        uint32_t dst = (plane ? sAl : sAh) + (uint32_t)kt * 4096 + SWZ8(row, kc);
        cp16(dst, (plane ? a_l : a_h) + (size_t)(p ? t : 0) * K + kt * 32 + kc * 16, p);
    }
    auto stageB = [&](int c) {
        uint32_t bb = sB0 + (uint32_t)(c & 1) * 32768;
#pragma unroll
        for (int h = 0; h < 4; h++) {
            int i = tid + h * 512;
            int plane = i >> 10, idx = i & 1023;
            int kt = idx >> 8, sub = idx & 255, row = sub >> 1, kc = sub & 1;
            uint32_t dst = bb + (plane ? 16384u : 0u) + (uint32_t)kt * 4096 + SWZ8(row, kc);
            cp16(dst, (plane ? w_l : w_h) + (size_t)(c * 128 + row) * K + kt * 32 + kc * 16, true);
        }
    };
    stageB(0); CP_COMMIT();
    stageB(1); CP_COMMIT();

#pragma unroll 1
    for (int c = 0; c < 3; c++) {
        if (c < 2) CP_WAIT1(); else CP_WAIT0();
        __syncthreads();
        uint32_t bb = sB0 + (uint32_t)(c & 1) * 32768;
        int accHH[2][4][4], accMID[2][4][4];
        ZERO_ACC(accHH, accMID);
#pragma unroll
        for (int kt = 0; kt < 4; kt++)
            compute_tile(sAh + kt * 4096, sAl + kt * 4096,
                         bb + kt * 4096, bb + 16384 + kt * 4096,
                         wid, lane, accHH, accMID);
        __syncthreads();
        if (c + 2 < 3) { stageB(c + 2); CP_COMMIT(); }

        const int colb = (wid >> 2) * 32 + (lane & 3) * 2;
        const int cb = c * 128;
#pragma unroll
        for (int mt = 0; mt < 2; mt++)
#pragma unroll
            for (int r2 = 0; r2 < 2; r2++) {
                int row = (wid & 3) * 32 + mt * 16 + (lane >> 2) + r2 * 8;
                int t = t0 + row;
                bool ok = t < T;
                float sa = ok ? sA[t] : 0.0f;
                if (c == 0) {
#pragma unroll
                    for (int nt = 0; nt < 4; nt++) {
                        int col = colb + nt * 8;
                        int i0 = accHH[mt][nt][r2*2]   * 128 + accMID[mt][nt][r2*2];
                        int i1 = accHH[mt][nt][r2*2+1] * 128 + accMID[mt][nt][r2*2+1];
                        *(float2*)(Q + row * 132 + col) =
                            make_float2((float)i0 * sa * uB[cb + col],
                                        (float)i1 * sa * uB[cb + col + 1]);
                    }
                } else if (c == 1) {
                    float p0 = 0.0f, p1 = 0.0f;
#pragma unroll
                    for (int nt = 0; nt < 4; nt++) {
                        int col = colb + nt * 8;
                        int i0 = accHH[mt][nt][r2*2]   * 128 + accMID[mt][nt][r2*2];
                        int i1 = accHH[mt][nt][r2*2+1] * 128 + accMID[mt][nt][r2*2+1];
                        float k0 = (float)i0 * sa * uB[cb + col];
                        float k1 = (float)i1 * sa * uB[cb + col + 1];
                        float2 qv = *(float2*)(Q + row * 132 + col);
                        float d = qv.x * k0 + qv.y * k1;
                        if (nt < 2) p0 += d; else p1 += d;
                    }
                    atomicAdd(&RSA[row * 8 + (wid >> 2) * 2 + 0], p0);
                    atomicAdd(&RSA[row * 8 + (wid >> 2) * 2 + 1], p1);
                } else {
#pragma unroll
                    for (int nt = 0; nt < 4; nt++) {
                        int col = colb + nt * 8;
                        int i0 = accHH[mt][nt][r2*2]   * 128 + accMID[mt][nt][r2*2];
                        int i1 = accHH[mt][nt][r2*2+1] * 128 + accMID[mt][nt][r2*2+1];
                        float v0 = (float)i0 * sa * uB[cb + col];
                        float v1 = (float)i1 * sa * uB[cb + col + 1];
                        float r = RSA[row * 8 + (wid >> 2) * 2 + (nt >> 1)] * 0.25f;
                        if (ok)
                            *(float2*)(imv32 + (size_t)t * 128 + col) =
                                make_float2(r * v0, r * v1);
                    }
                }
            }
    }
}

// ---------------------------------------------------------------------------
// Row quantization helpers.
// ---------------------------------------------------------------------------
__device__ __forceinline__ void quant_row_dev(
    const float* __restrict__ src, int8_t* __restrict__ dh,
    int8_t* __restrict__ dl, float* __restrict__ sout,
    int kd, float smul, int lane)
{
    int n4 = kd >> 7;
    float4 v[4];
    float m = 0.0f;
#pragma unroll 4
    for (int i = 0; i < n4; i++) {
        v[i] = ((const float4*)src)[lane + 32 * i];
        m = fmaxf(m, fmaxf(fmaxf(fabsf(v[i].x), fabsf(v[i].y)),
                           fmaxf(fabsf(v[i].z), fabsf(v[i].w))));
    }
#pragma unroll
    for (int o = 16; o >= 1; o >>= 1) m = fmaxf(m, __shfl_xor_sync(0xffffffffu, m, o));
    float s   = m * (1.0f / 16256.0f);
    float inv = (m > 0.0f) ? (16256.0f / m) : 0.0f;
#pragma unroll 4
    for (int i = 0; i < n4; i++) {
        float vv[4] = {v[i].x, v[i].y, v[i].z, v[i].w};
        char h4[4], l4[4];
#pragma unroll
        for (int q = 0; q < 4; q++) {
            int iv = __float2int_rn(vv[q] * inv);
            int vh = (iv + 64) >> 7;
            int vl = iv - (vh << 7);
            h4[q] = (char)vh; l4[q] = (char)vl;
        }
        ((char4*)dh)[lane + 32 * i] = make_char4(h4[0], h4[1], h4[2], h4[3]);
        ((char4*)dl)[lane + 32 * i] = make_char4(l4[0], l4[1], l4[2], l4[3]);
    }
    if (lane == 0) *sout = s * smul;
}

template<int KD>
__global__ void quant_rows(const float* __restrict__ src,
                           int8_t* __restrict__ dh, int8_t* __restrict__ dl,
                           float* __restrict__ sc, int T)
{
    int warp = threadIdx.x >> 5, lane = threadIdx.x & 31;
    int t = blockIdx.x * 8 + warp;
    if (t >= T) return;
    quant_row_dev(src + (size_t)t * KD, dh + (size_t)t * KD, dl + (size_t)t * KD,
                  sc + t, KD, 1.0f, lane);
}

__global__ void quantW(const float* __restrict__ w0, const float* __restrict__ wq,
                       const float* __restrict__ wo, const float* __restrict__ f1,
                       const float* __restrict__ f2,
                       int8_t* __restrict__ dh, int8_t* __restrict__ dl,
                       float* __restrict__ sc)
{
    int gw = blockIdx.x * 8 + (threadIdx.x >> 5);
    int lane = threadIdx.x & 31;
    if (gw >= 1792) return;
    const float* src; int kd = 128; size_t off;
    if (gw < 128)       { src = w0 + (size_t)gw * 128;          off = (size_t)gw * 128; }
    else if (gw < 896)  { int q = gw - 128;  src = wq + (size_t)q * 128; off = 16384  + (size_t)q * 128; }
    else if (gw < 1152) { int q = gw - 896;  src = wo + (size_t)q * 128; off = 114688 + (size_t)q * 128; }
    else if (gw < 1664) { int q = gw - 1152; src = f1 + (size_t)q * 128; off = 147456 + (size_t)q * 128; }
    else                { int q = gw - 1664; src = f2 + (size_t)q * 512; off = 212992 + (size_t)q * 512; kd = 512; }
    quant_row_dev(src, dh + off, dl + off, sc + gw, kd, 128.0f, lane);
}

// ---------------------------------------------------------------------------
// LayerNorm (dim 128) fused with int8 quantization.
// ---------------------------------------------------------------------------
__global__ void ln_quant(const float* __restrict__ x,
                         const float* __restrict__ g,
                         const float* __restrict__ b,
                         int8_t* __restrict__ zh, int8_t* __restrict__ zl,
                         float* __restrict__ sc, int T)
{
    int warp = threadIdx.x >> 5, lane = threadIdx.x & 31;
    int t = blockIdx.x * 8 + warp;
    if (t >= T) return;

    float4 v = ((const float4*)(x + (size_t)t * 128))[lane];
    float s = v.x + v.y + v.z + v.w;
#pragma unroll
    for (int o = 16; o >= 1; o >>= 1) s += __shfl_xor_sync(0xffffffffu, s, o);
    float mu = s * (1.0f / 128.0f);
    float dx = v.x - mu, dy = v.y - mu, dz = v.z - mu, dw = v.w - mu;
    float q = dx * dx + dy * dy + dz * dz + dw * dw;
#pragma unroll
    for (int o = 16; o >= 1; o >>= 1) q += __shfl_xor_sync(0xffffffffu, q, o);
    float rs = rsqrtf(q * (1.0f / 128.0f) + 1e-5f);

    float4 gg = ((const float4*)g)[lane];
    float4 bb = ((const float4*)b)[lane];
    float o0 = dx * rs * gg.x + bb.x;
    float o1 = dy * rs * gg.y + bb.y;
    float o2 = dz * rs * gg.z + bb.z;
    float o3 = dw * rs * gg.w + bb.w;

    float m = fmaxf(fmaxf(fabsf(o0), fabsf(o1)), fmaxf(fabsf(o2), fabsf(o3)));
#pragma unroll
    for (int o = 16; o >= 1; o >>= 1) m = fmaxf(m, __shfl_xor_sync(0xffffffffu, m, o));
    float sq  = m * (1.0f / 16256.0f);
    float inv = (m > 0.0f) ? (16256.0f / m) : 0.0f;

    float vv[4] = {o0, o1, o2, o3};
    char h4[4], l4[4];
#pragma unroll
    for (int qi = 0; qi < 4; qi++) {
        int iv = __float2int_rn(vv[qi] * inv);
        int vh = (iv + 64) >> 7;
        int vl = iv - (vh << 7);
        h4[qi] = (char)vh; l4[qi] = (char)vl;
    }
    size_t base = (size_t)t * 128;
    ((char4*)(zh + base))[lane] = make_char4(h4[0], h4[1], h4[2], h4[3]);
    ((char4*)(zl + base))[lane] = make_char4(l4[0], l4[1], l4[2], l4[3]);
    if (lane == 0) sc[t] = sq;
}

// ---------------------------------------------------------------------------
// Chunked cumsum + fused quantization.
// ---------------------------------------------------------------------------
__global__ void csum_partial(const float* __restrict__ imv, float* __restrict__ part)
{
    int c = blockIdx.x, i = blockIdx.y, f = threadIdx.x;
    size_t base = ((size_t)i * BP1 + c * 128) * 128 + f;
    float sum = 0.0f;
#pragma unroll 8
    for (int j = 0; j < 128; j++) sum += imv[base + (size_t)j * 128];
    part[((size_t)i * 16 + c) * 128 + f] = sum;
}

__global__ void csum_scan(float* __restrict__ part)
{
    int i = blockIdx.x, f = threadIdx.x;
    float run = 0.0f;
#pragma unroll
    for (int c = 0; c < 16; c++) {
        size_t idx = ((size_t)i * 16 + c) * 128 + f;
        float t = part[idx];
        part[idx] = run;
        run += t;
    }
}

__global__ void csum_apply(const float* __restrict__ imv,
                           const float* __restrict__ part,
                           int8_t* __restrict__ dh, int8_t* __restrict__ dl,
                           float* __restrict__ sc)
{
    __shared__ float sm[4][8];
    int c = blockIdx.x, i = blockIdx.y, f = threadIdx.x;
    int warp = f >> 5, lane = f & 31;
    size_t base = ((size_t)i * BP1 + c * 128) * 128 + f;
    float acc = part[((size_t)i * 16 + c) * 128 + f];

#pragma unroll 1
    for (int jb = 0; jb < 16; jb++) {
        float val[8], mx[8];
#pragma unroll
        for (int u = 0; u < 8; u++) {
            acc += imv[base + (size_t)(jb * 8 + u) * 128];
            val[u] = acc;
            mx[u] = fabsf(acc);
        }
#pragma unroll
        for (int o = 16; o >= 1; o >>= 1)
#pragma unroll
            for (int u = 0; u < 8; u++)
                mx[u] = fmaxf(mx[u], __shfl_xor_sync(0xffffffffu, mx[u], o));
        if (lane == 0) {
#pragma unroll
            for (int u = 0; u < 8; u++) sm[warp][u] = mx[u];
        }
        __syncthreads();
#pragma unroll
        for (int u = 0; u < 8; u++) {
            float m = fmaxf(fmaxf(sm[0][u], sm[1][u]), fmaxf(sm[2][u], sm[3][u]));
            float inv = (m > 0.0f) ? (16256.0f / m) : 0.0f;
            int iv = __float2int_rn(val[u] * inv);
            int vh = (iv + 64) >> 7;
            int vl = iv - (vh << 7);
            size_t row = (size_t)i * BP1 + c * 128 + jb * 8 + u;
            dh[row * 128 + f] = (int8_t)vh;
            dl[row * 128 + f] = (int8_t)vl;
            if (f == 0) sc[row] = m * (1.0f / 16256.0f);
        }
        __syncthreads();
    }
}

__global__ void quant_last(const float* __restrict__ imv,
                           int8_t* __restrict__ dh, int8_t* __restrict__ dl,
                           float* __restrict__ sc)
{
    int w = blockIdx.x * 8 + (threadIdx.x >> 5), lane = threadIdx.x & 31;
    if (w >= AA) return;
    size_t row = (size_t)w * BP1 + BB;
    quant_row_dev(imv + row * 128, dh + row * 128, dl + row * 128,
                  sc + row, 128, 1.0f, lane);
}

__global__ void cls_kernel(const float* __restrict__ cls,
                           const float* __restrict__ bias,
                           float* __restrict__ out)
{
    int i = blockIdx.x, l = threadIdx.x;
    out[(size_t)i * BP1 * 128 + l] = cls[i * 128 + l] + bias[(size_t)i * BP1 * 128 + l];
}

// ---------------------------------------------------------------------------
// Launch
// ---------------------------------------------------------------------------
extern "C" void kernel_launch(void* const* d_in, const int* in_sizes, int n_in,
                              void* d_out, int out_size)
{
    const float* x      = (const float*)d_in[0];
    const float* weight = (const float*)d_in[1];
    const float* cls    = (const float*)d_in[2];
    const float* bias   = (const float*)d_in[3];
    const float* Wqkv   = (const float*)d_in[4];
    const float* Wo     = (const float*)d_in[5];
    const float* ln1_g  = (const float*)d_in[6];
    const float* ln1_b  = (const float*)d_in[7];
    const float* ln2_g  = (const float*)d_in[8];
    const float* ln2_b  = (const float*)d_in[9];
    const float* fc1_w  = (const float*)d_in[10];
    const float* fc1_b  = (const float*)d_in[11];
    const float* fc2_w  = (const float*)d_in[12];
    const float* fc2_b  = (const float*)d_in[13];
    float* s = (float*)d_out;

    void *pbig, *pact, *ph8, *pwh, *pwl, *pscw, *psct, *psch, *ppart;
    cudaGetSymbolAddress(&pbig, g_big);
    cudaGetSymbolAddress(&pact, g_act8);
    cudaGetSymbolAddress(&ph8,  g_h8);
    cudaGetSymbolAddress(&pwh,  g_w8h);
    cudaGetSymbolAddress(&pwl,  g_w8l);
    cudaGetSymbolAddress(&pscw, g_sc_w);
    cudaGetSymbolAddress(&psct, g_sc_tok);
    cudaGetSymbolAddress(&psch, g_sch);
    cudaGetSymbolAddress(&ppart, g_part);

    float*  big   = (float*)pbig;
    int8_t* act8  = (int8_t*)pact;
    int8_t* h8    = (int8_t*)ph8;
    int8_t* w8h   = (int8_t*)pwh;
    int8_t* w8l   = (int8_t*)pwl;
    float*  sc_w  = (float*)pscw;
    float*  sc_t  = (float*)psct;
    float*  sc_h  = (float*)psch;
    float*  partb = (float*)ppart;

    const int T  = TTOK;
    const int Tx = TXTOK;
    const int tokBlocks = (T + 127) / 128;   // 1922
    const int txBlocks  = Tx / 128;          // 1920
    const int m64Blocks = (T + 63) / 64;     // 3842

    int8_t* z8h   = act8;
    int8_t* z8l   = z8h + (size_t)T * 128;
    int8_t* imv8h = z8h;                     // alias (z dead after qkv)
    int8_t* imv8l = z8l;
    int8_t* h8h   = h8;
    int8_t* h8l   = h8h + (size_t)T * 512;
    int8_t* x8h   = h8;                      // alias (x only used at init)
    int8_t* x8l   = x8h + (size_t)Tx * 128;
    float* imv32 = big;                      // T*128
    float* s_z   = sc_t;
    float* s_imv = sc_t + T;
    float* s_x   = sc_t + 3 * (size_t)T;

    const int SM_RES2 = 65536;
    const int SM_QKV  = 169984;
    const int SM_FC2  = 98304;
    cudaFuncSetAttribute(i8_gemm_res2<2,1>, cudaFuncAttributeMaxDynamicSharedMemorySize, SM_RES2);
    cudaFuncSetAttribute(i8_gemm_res2<2,0>, cudaFuncAttributeMaxDynamicSharedMemorySize, SM_RES2);
    cudaFuncSetAttribute(i8_gemm_fc1,    cudaFuncAttributeMaxDynamicSharedMemorySize, SM_RES2);
    cudaFuncSetAttribute(i8_gemm_fc2m64, cudaFuncAttributeMaxDynamicSharedMemorySize, SM_FC2);
    cudaFuncSetAttribute(i8_qkv_rsa,     cudaFuncAttributeMaxDynamicSharedMemorySize, SM_QKV);

    // 1: weights
    quantW<<<224, 256>>>(weight, Wqkv, Wo, fc1_w, fc2_w, w8h, w8l, sc_w);
    // 2: x rows
    quant_rows<128><<<(Tx + 7) / 8, 256>>>(x, x8h, x8l, s_x, Tx);
    // 3: cls row
    cls_kernel<<<AA, 128>>>(cls, bias, s);
    // 4: s = concat([cls, x @ W^T], 1) + bias
    i8_gemm_res2<2,1><<<txBlocks, 256, SM_RES2>>>(
        x8h, x8l, s_x, w8h, w8l, sc_w, nullptr, bias, s, Tx);

    for (int a = 0; a < 2; a++) {
        const int8_t* wq_h = w8h + 16384 + (size_t)a * 49152;
        const int8_t* wq_l = w8l + 16384 + (size_t)a * 49152;
        const float*  uq   = sc_w + 128 + a * 384;
        const int8_t* wo_h = w8h + 114688 + (size_t)a * 16384;
        const int8_t* wo_l = w8l + 114688 + (size_t)a * 16384;
        const float*  uo   = sc_w + 896 + a * 128;

        // z = LN1(s)
        ln_quant<<<(T + 7) / 8, 256>>>(s, ln1_g, ln1_b, z8h, z8l, s_z, T);
        // imv32 = 0.25*(q.k per head)*v  (fused qkv + rsa)
        i8_qkv_rsa<<<tokBlocks, 512, SM_QKV>>>(
            z8h, z8l, s_z, wq_h, wq_l, uq, imv32, T);
        // chunked causal cumsum + quantization
        csum_partial<<<dim3(16, AA), 128>>>(imv32, partb);
        csum_scan<<<AA, 128>>>(partb);
        csum_apply<<<dim3(16, AA), 128>>>(imv32, partb, imv8h, imv8l, s_imv);
        quant_last<<<(AA + 7) / 8, 256>>>(imv32, imv8h, imv8l, s_imv);
        // s += imv @ Wo^T
        i8_gemm_res2<2,0><<<tokBlocks, 256, SM_RES2>>>(
            imv8h, imv8l, s_imv, wo_h, wo_l, uo, nullptr, s, s, T);
        // z = LN2(s)
        ln_quant<<<(T + 7) / 8, 256>>>(s, ln2_g, ln2_b, z8h, z8l, s_z, T);
        // h8 = quant(gelu(z @ fc1^T + b1)) with 32-col group scales (fused)
        i8_gemm_fc1<<<tokBlocks, 256, SM_RES2>>>(
            z8h, z8l, s_z, w8h + 147456, w8l + 147456, sc_w + 1152,
            fc1_b, h8h, h8l, sc_h, T);
        // s = h @ fc2^T + b2 + s  (K=512, M=64 tiles, single h8 pass)
        i8_gemm_fc2m64<<<m64Blocks, 256, SM_FC2>>>(
            h8h, h8l, sc_h, w8h + 212992, w8l + 212992, sc_w + 1664,
            fc2_b, s, s, T);
    }
    (void)in_sizes; (void)n_in; (void)out_size;
}

// round 14
// speedup vs baseline: 1.0283x; 1.0240x over previous
#include <cuda_runtime.h>
#include <cuda_bf16.h>
#include <math.h>
#include <stdint.h>

// ---------------------------------------------------------------------------
// EEGformer forward. int8 dual-plane GEMMs (mma.sync.m16n8k32.s8).
// R14: LayerNorm+quant fused into producer GEMM epilogues (M=64 x N=128
// tiles own complete rows). ln_quant passes eliminated.
// A=120, B=2048, Bp1=2049, M=128, T = 120*2049 = 245880 tokens.
// ---------------------------------------------------------------------------

#define AA    120
#define BB    2048
#define BP1   2049
#define TTOK  (AA * BP1)      // 245880
#define TXTOK (AA * BB)       // 245760
#define TPAD  246016

__device__ float  g_big[(size_t)TTOK * 128];        // imv32 fp32
__device__ int8_t g_act8[(size_t)TTOK * 256];       // z / imv planes
__device__ int8_t g_h8  [(size_t)TTOK * 512 * 2];   // h planes / x planes
__device__ int8_t g_w8h[278528];
__device__ int8_t g_w8l[278528];
__device__ float  g_sc_w[1792];
__device__ float  g_sc_tok[(size_t)3 * TTOK + TXTOK];
__device__ float  g_sch[(size_t)TPAD * 16];         // h group scales
__device__ float  g_part[AA * 16 * 128];

// ---------------------------------------------------------------------------
// PTX helpers
// ---------------------------------------------------------------------------
__device__ __forceinline__ uint32_t smem_to_u32(const void* p) {
    uint32_t a;
    asm("{ .reg .u64 t; cvta.to.shared.u64 t, %1; cvt.u32.u64 %0, t; }" : "=r"(a) : "l"(p));
    return a;
}
__device__ __forceinline__ void ldm4(uint32_t r[4], uint32_t addr) {
    asm volatile("ldmatrix.sync.aligned.m8n8.x4.shared.b16 {%0,%1,%2,%3}, [%4];"
        : "=r"(r[0]), "=r"(r[1]), "=r"(r[2]), "=r"(r[3]) : "r"(addr));
}
__device__ __forceinline__ void imma(int d[4], const uint32_t a[4],
                                     uint32_t b0, uint32_t b1) {
    asm volatile("mma.sync.aligned.m16n8k32.row.col.s32.s8.s8.s32 "
        "{%0,%1,%2,%3}, {%4,%5,%6,%7}, {%8,%9}, {%0,%1,%2,%3};"
        : "+r"(d[0]), "+r"(d[1]), "+r"(d[2]), "+r"(d[3])
        : "r"(a[0]), "r"(a[1]), "r"(a[2]), "r"(a[3]), "r"(b0), "r"(b1));
}
__device__ __forceinline__ void cp16(uint32_t saddr, const void* g, bool p) {
    int sz = p ? 16 : 0;
    asm volatile("cp.async.cg.shared.global [%0], [%1], 16, %2;"
        :: "r"(saddr), "l"(g), "r"(sz) : "memory");
}
#define CP_COMMIT() asm volatile("cp.async.commit_group;" ::: "memory")
#define CP_WAIT1()  asm volatile("cp.async.wait_group 1;" ::: "memory")
#define CP_WAIT0()  asm volatile("cp.async.wait_group 0;" ::: "memory")

// 32-byte-row swizzle inside one k-tile: line = row>>2 (128B)
#define SWZ8(row, kc) ((((row) >> 2) * 128) + \
    (((((row) & 3) * 2 + (kc)) ^ (((row) >> 2) & 7)) << 4))

// Fragment loads, block 128(M) x 64..128(N) — 16-warp qkv variant.
#define LOAD_FRAGS64(sAh, sAl, sBh, sBl) do { \
    int arow = (wid & 3) * 32 + (lane & 7) + ((lane >> 3) & 1) * 8; \
    int akc  = lane >> 4; \
    _Pragma("unroll") for (int mt = 0; mt < 2; mt++) { \
        uint32_t off = SWZ8(arow + mt * 16, akc); \
        ldm4(fAh[mt], (sAh) + off); \
        ldm4(fAl[mt], (sAl) + off); \
    } \
    int brow = (wid >> 2) * 32 + ((lane >> 4) & 1) * 8 + (lane & 7); \
    int bkc  = (lane >> 3) & 1; \
    _Pragma("unroll") for (int j = 0; j < 2; j++) { \
        uint32_t off = SWZ8(brow + j * 16, bkc); \
        ldm4(fBh[j], (sBh) + off); \
        ldm4(fBl[j], (sBl) + off); \
    } \
} while (0)

__device__ __forceinline__ void compute_tile(
    uint32_t sAh_, uint32_t sAl_, uint32_t sBh_, uint32_t sBl_,
    int wid, int lane, int accHH[2][4][4], int accMID[2][4][4])
{
    uint32_t fAh[2][4], fAl[2][4], fBh[2][4], fBl[2][4];
    LOAD_FRAGS64(sAh_, sAl_, sBh_, sBl_);
#pragma unroll
    for (int mt = 0; mt < 2; mt++)
#pragma unroll
        for (int nt = 0; nt < 4; nt++) {
            int j = nt >> 1, o = (nt & 1) * 2;
            imma(accHH[mt][nt],  fAh[mt], fBh[j][o], fBh[j][o + 1]);
            imma(accMID[mt][nt], fAh[mt], fBl[j][o], fBl[j][o + 1]);
            imma(accMID[mt][nt], fAl[mt], fBh[j][o], fBh[j][o + 1]);
        }
}

#define ZERO_ACC(accHH, accMID) do { \
    _Pragma("unroll") for (int i = 0; i < 2; i++) \
    _Pragma("unroll") for (int j = 0; j < 4; j++) \
    _Pragma("unroll") for (int q = 0; q < 4; q++) { accHH[i][j][q] = 0; accMID[i][j][q] = 0; } \
} while (0)

// ---------------------------------------------------------------------------
// Fused LN + int8 quant epilogue for M=64 x N=128 kernels.
// v[idx][j]: idx = mt*2+r2 (4 rows/thread), j = nt*2+e (8 cols/thread).
// Two __syncthreads; all threads must call unconditionally.
// ---------------------------------------------------------------------------
__device__ __forceinline__ void ln_epilogue_m64(
    float v[4][8], char* smem, int red_off,
    int mwid, int nwid, int lane,
    const int ok[4], const size_t orow[4],
    const float* __restrict__ ln_g, const float* __restrict__ ln_b,
    int8_t* __restrict__ z8h, int8_t* __restrict__ z8l,
    float* __restrict__ s_z)
{
    float* sm_sum = (float*)(smem + red_off);   // [64][4]
    float* sm_sq  = sm_sum + 256;
    float* sm_mx  = sm_sum + 512;
    int rl[4];
#pragma unroll
    for (int idx = 0; idx < 4; idx++)
        rl[idx] = mwid * 32 + (idx >> 1) * 16 + (idx & 1) * 8 + (lane >> 2);

#pragma unroll
    for (int idx = 0; idx < 4; idx++) {
        float ps = 0.0f, pq = 0.0f;
#pragma unroll
        for (int j = 0; j < 8; j++) { ps += v[idx][j]; pq += v[idx][j] * v[idx][j]; }
        ps += __shfl_xor_sync(0xffffffffu, ps, 1);
        ps += __shfl_xor_sync(0xffffffffu, ps, 2);
        pq += __shfl_xor_sync(0xffffffffu, pq, 1);
        pq += __shfl_xor_sync(0xffffffffu, pq, 2);
        if ((lane & 3) == 0) {
            sm_sum[rl[idx] * 4 + nwid] = ps;
            sm_sq [rl[idx] * 4 + nwid] = pq;
        }
    }
    __syncthreads();
#pragma unroll
    for (int idx = 0; idx < 4; idx++) {
        float ts = sm_sum[rl[idx] * 4 + 0] + sm_sum[rl[idx] * 4 + 1]
                 + sm_sum[rl[idx] * 4 + 2] + sm_sum[rl[idx] * 4 + 3];
        float tq = sm_sq[rl[idx] * 4 + 0] + sm_sq[rl[idx] * 4 + 1]
                 + sm_sq[rl[idx] * 4 + 2] + sm_sq[rl[idx] * 4 + 3];
        float mu = ts * (1.0f / 128.0f);
        float var = tq * (1.0f / 128.0f) - mu * mu;
        float rs = rsqrtf(var + 1e-5f);
        float m = 0.0f;
#pragma unroll
        for (int j = 0; j < 8; j++) {
            int col = nwid * 32 + (j >> 1) * 8 + (lane & 3) * 2 + (j & 1);
            float o = (v[idx][j] - mu) * rs * ln_g[col] + ln_b[col];
            v[idx][j] = o;
            m = fmaxf(m, fabsf(o));
        }
        m = fmaxf(m, __shfl_xor_sync(0xffffffffu, m, 1));
        m = fmaxf(m, __shfl_xor_sync(0xffffffffu, m, 2));
        if ((lane & 3) == 0) sm_mx[rl[idx] * 4 + nwid] = m;
    }
    __syncthreads();
#pragma unroll
    for (int idx = 0; idx < 4; idx++) {
        float m = fmaxf(fmaxf(sm_mx[rl[idx] * 4 + 0], sm_mx[rl[idx] * 4 + 1]),
                        fmaxf(sm_mx[rl[idx] * 4 + 2], sm_mx[rl[idx] * 4 + 3]));
        float inv = (m > 0.0f) ? (16256.0f / m) : 0.0f;
        if (ok[idx]) {
#pragma unroll
            for (int nt = 0; nt < 4; nt++) {
                int colp = nwid * 32 + nt * 8 + (lane & 3) * 2;
                char hh[2], ll[2];
#pragma unroll
                for (int e = 0; e < 2; e++) {
                    int iv = __float2int_rn(v[idx][nt * 2 + e] * inv);
                    int vh = (iv + 64) >> 7;
                    hh[e] = (char)vh;
                    ll[e] = (char)(iv - (vh << 7));
                }
                *(char2*)(z8h + orow[idx] * 128 + colp) = make_char2(hh[0], hh[1]);
                *(char2*)(z8l + orow[idx] * 128 + colp) = make_char2(ll[0], ll[1]);
            }
            if ((lane & 3) == 0 && nwid == 0) s_z[orow[idx]] = m * (1.0f / 16256.0f);
        }
    }
}

// ---------------------------------------------------------------------------
// M=64 x N=128, K=128 single-shot burst GEMM (init, Wo) with fused LN+quant.
// 8 warps: mwid = wid&1 (2 x 32 rows), nwid = wid>>1 (4 x 32 cols).
// smem: Ah 8K | Al 8K | Bh 16K | Bl 16K | red 3K = 51K -> 2 CTAs/SM.
// ---------------------------------------------------------------------------
template<int REMAP>
__global__ __launch_bounds__(256, 2)
void i8_gemm_m64k128(const int8_t* __restrict__ a_h, const int8_t* __restrict__ a_l,
                     const float* __restrict__ sA,
                     const int8_t* __restrict__ w_h, const int8_t* __restrict__ w_l,
                     const float* __restrict__ uB,
                     const float* __restrict__ addend,
                     const float* __restrict__ ln_g, const float* __restrict__ ln_b,
                     float* __restrict__ outf,
                     int8_t* __restrict__ z8h, int8_t* __restrict__ z8l,
                     float* __restrict__ s_z, int T)
{
    constexpr int K = 128;
    extern __shared__ char smem[];
    const uint32_t sbase = smem_to_u32(smem);
    const int tid = threadIdx.x, wid = tid >> 5, lane = tid & 31;
    const int t0 = blockIdx.x * 64;
    const int mwid = wid & 1, nwid = wid >> 1;

    // burst A (16KB) + B (32KB)
#pragma unroll
    for (int h = 0; h < 4; h++) {
        int i = tid + h * 256;
        int plane = i >> 9, idx = i & 511;
        int kt = idx >> 7, sub = idx & 127, row = sub >> 1, kc = sub & 1;
        int t = t0 + row; bool p = t < T;
        uint32_t dst = sbase + (plane ? 8192u : 0u) + (uint32_t)kt * 2048 + SWZ8(row, kc);
        cp16(dst, (plane ? a_l : a_h) + (size_t)(p ? t : 0) * K + kt * 32 + kc * 16, p);
    }
#pragma unroll
    for (int h = 0; h < 8; h++) {
        int i = tid + h * 256;
        int plane = i >> 10, idx = i & 1023;
        int kt = idx >> 8, sub = idx & 255, row = sub >> 1, kc = sub & 1;
        uint32_t dst = sbase + 16384 + (plane ? 16384u : 0u) + (uint32_t)kt * 4096 + SWZ8(row, kc);
        cp16(dst, (plane ? w_l : w_h) + (size_t)row * K + kt * 32 + kc * 16, true);
    }
    CP_COMMIT();
    CP_WAIT0();
    __syncthreads();

    int accHH[2][4][4], accMID[2][4][4];
    ZERO_ACC(accHH, accMID);
#pragma unroll
    for (int kt = 0; kt < 4; kt++) {
        uint32_t fAh[2][4], fAl[2][4], fBh[2][4], fBl[2][4];
        {
            int arow = mwid * 32 + (lane & 7) + ((lane >> 3) & 1) * 8;
            int akc  = lane >> 4;
#pragma unroll
            for (int mt = 0; mt < 2; mt++) {
                uint32_t off = (uint32_t)kt * 2048 + SWZ8(arow + mt * 16, akc);
                ldm4(fAh[mt], sbase + off);
                ldm4(fAl[mt], sbase + 8192 + off);
            }
            int brow = nwid * 32 + ((lane >> 4) & 1) * 8 + (lane & 7);
            int bkc  = (lane >> 3) & 1;
#pragma unroll
            for (int j = 0; j < 2; j++) {
                uint32_t off = (uint32_t)kt * 4096 + SWZ8(brow + j * 16, bkc);
                ldm4(fBh[j], sbase + 16384 + off);
                ldm4(fBl[j], sbase + 32768 + off);
            }
        }
#pragma unroll
        for (int mt = 0; mt < 2; mt++)
#pragma unroll
            for (int nt = 0; nt < 4; nt++) {
                int j = nt >> 1, o = (nt & 1) * 2;
                imma(accHH[mt][nt],  fAh[mt], fBh[j][o], fBh[j][o + 1]);
                imma(accMID[mt][nt], fAh[mt], fBl[j][o], fBl[j][o + 1]);
                imma(accMID[mt][nt], fAl[mt], fBh[j][o], fBh[j][o + 1]);
            }
    }

    // Epilogue: compute v, write s, fused LN+quant.
    float v[4][8];
    int ok[4]; size_t orow[4];
#pragma unroll
    for (int idx = 0; idx < 4; idx++) {
        int mt = idx >> 1, r2 = idx & 1;
        int row = mwid * 32 + mt * 16 + (lane >> 2) + r2 * 8;
        int t = t0 + row;
        ok[idx] = (t < T);
        orow[idx] = REMAP ? ((size_t)t + (size_t)((unsigned)t / 2048u) + 1) : (size_t)t;
        float sa = sA[ok[idx] ? t : 0];
#pragma unroll
        for (int nt = 0; nt < 4; nt++) {
            int col = nwid * 32 + nt * 8 + (lane & 3) * 2;
            int i0 = accHH[mt][nt][r2 * 2]     * 128 + accMID[mt][nt][r2 * 2];
            int i1 = accHH[mt][nt][r2 * 2 + 1] * 128 + accMID[mt][nt][r2 * 2 + 1];
            float v0 = (float)i0 * sa * uB[col];
            float v1 = (float)i1 * sa * uB[col + 1];
            float2 a2 = *(const float2*)(addend + orow[idx] * 128 + col);
            v0 += a2.x; v1 += a2.y;
            if (ok[idx])
                *(float2*)(outf + orow[idx] * 128 + col) = make_float2(v0, v1);
            v[idx][nt * 2] = v0; v[idx][nt * 2 + 1] = v1;
        }
    }
    __syncthreads();   // tiles dead; red arrays reuse smem region safely
    ln_epilogue_m64(v, smem, 49152, mwid, nwid, lane, ok, orow,
                    ln_g, ln_b, z8h, z8l, s_z);
}

// ---------------------------------------------------------------------------
// fc1 GEMM (M=128, N=512, 8 chunks) with fused GELU + int8 group quantization.
// ---------------------------------------------------------------------------
__global__ __launch_bounds__(256, 2)
void i8_gemm_fc1(const int8_t* __restrict__ a_h, const int8_t* __restrict__ a_l,
                 const float* __restrict__ sA,
                 const int8_t* __restrict__ w_h, const int8_t* __restrict__ w_l,
                 const float* __restrict__ uB,
                 const float* __restrict__ biasv,
                 int8_t* __restrict__ out_h, int8_t* __restrict__ out_l,
                 float* __restrict__ scg, int T)
{
    constexpr int K = 128;
    constexpr int NCH = 8;
    extern __shared__ char smem[];
    const uint32_t sbase = smem_to_u32(smem);
    const uint32_t sAh = sbase, sAl = sbase + 16384, sB0 = sbase + 32768;
    const int tid = threadIdx.x, wid = tid >> 5, lane = tid & 31;
    const int t0 = blockIdx.x * 128;

#pragma unroll
    for (int h = 0; h < 8; h++) {
        int i = tid + h * 256;
        int plane = i >> 10, idx = i & 1023;
        int kt = idx >> 8, sub = idx & 255, row = sub >> 1, kc = sub & 1;
        int t = t0 + row; bool p = t < T;
        uint32_t dst = (plane ? sAl : sAh) + (uint32_t)kt * 4096 + SWZ8(row, kc);
        cp16(dst, (plane ? a_l : a_h) + (size_t)(p ? t : 0) * K + kt * 32 + kc * 16, p);
    }
    auto stageB = [&](int c) {
        uint32_t bb = sB0 + (uint32_t)(c & 1) * 16384;
#pragma unroll
        for (int h = 0; h < 4; h++) {
            int i = tid + h * 256;
            int plane = i >> 9, idx = i & 511;
            int kt = idx >> 7, sub = idx & 127, row = sub >> 1, kc = sub & 1;
            uint32_t dst = bb + (plane ? 8192u : 0u) + (uint32_t)kt * 2048 + SWZ8(row, kc);
            cp16(dst, (plane ? w_l : w_h) + (size_t)(c * 64 + row) * K + kt * 32 + kc * 16, true);
        }
    };
    stageB(0); CP_COMMIT();
    stageB(1); CP_COMMIT();

#pragma unroll 1
    for (int c = 0; c < NCH; c++) {
        if (c < NCH - 1) CP_WAIT1(); else CP_WAIT0();
        __syncthreads();
        uint32_t bb = sB0 + (uint32_t)(c & 1) * 16384;
        int accHH[2][4][4], accMID[2][4][4];
        ZERO_ACC(accHH, accMID);
#pragma unroll
        for (int kt = 0; kt < 4; kt++) {
            uint32_t fAh[2][4], fAl[2][4], fBh[2][4], fBl[2][4];
            uint32_t a0 = sAh + kt * 4096, a1 = sAl + kt * 4096;
            uint32_t b0 = bb + kt * 2048, b1 = bb + 8192 + kt * 2048;
            LOAD_FRAGS64(a0, a1, b0, b1);
#pragma unroll
            for (int mt = 0; mt < 2; mt++)
#pragma unroll
                for (int nt = 0; nt < 4; nt++) {
                    int j = nt >> 1, o = (nt & 1) * 2;
                    imma(accHH[mt][nt],  fAh[mt], fBh[j][o], fBh[j][o + 1]);
                    imma(accMID[mt][nt], fAh[mt], fBl[j][o], fBl[j][o + 1]);
                    imma(accMID[mt][nt], fAl[mt], fBh[j][o], fBh[j][o + 1]);
                }
        }
        __syncthreads();
        if (c + 2 < NCH) { stageB(c + 2); CP_COMMIT(); }

#pragma unroll
        for (int mt = 0; mt < 2; mt++)
#pragma unroll
            for (int r2 = 0; r2 < 2; r2++) {
                int row = (wid & 3) * 32 + mt * 16 + (lane >> 2) + r2 * 8;
                int t = t0 + row;
                bool ok = t < T;
                float sa = sA[ok ? t : 0];
                float v[8];
                float m = 0.0f;
#pragma unroll
                for (int nt = 0; nt < 4; nt++) {
                    int col = c * 64 + (wid >> 2) * 32 + nt * 8 + (lane & 3) * 2;
                    int i0 = accHH[mt][nt][r2 * 2]     * 128 + accMID[mt][nt][r2 * 2];
                    int i1 = accHH[mt][nt][r2 * 2 + 1] * 128 + accMID[mt][nt][r2 * 2 + 1];
                    float2 b2 = *(const float2*)(biasv + col);
                    float v0 = (float)i0 * sa * uB[col]     + b2.x;
                    float v1 = (float)i1 * sa * uB[col + 1] + b2.y;
                    v0 = 0.5f * v0 * (1.0f + erff(v0 * 0.70710678118654752f));
                    v1 = 0.5f * v1 * (1.0f + erff(v1 * 0.70710678118654752f));
                    v[nt * 2] = v0; v[nt * 2 + 1] = v1;
                    m = fmaxf(m, fmaxf(fabsf(v0), fabsf(v1)));
                }
                m = fmaxf(m, __shfl_xor_sync(0xffffffffu, m, 1));
                m = fmaxf(m, __shfl_xor_sync(0xffffffffu, m, 2));
                float inv = (m > 0.0f) ? (16256.0f / m) : 0.0f;
                if (ok) {
#pragma unroll
                    for (int nt = 0; nt < 4; nt++) {
                        int col = c * 64 + (wid >> 2) * 32 + nt * 8 + (lane & 3) * 2;
                        char hh[2], ll[2];
#pragma unroll
                        for (int e = 0; e < 2; e++) {
                            int iv = __float2int_rn(v[nt * 2 + e] * inv);
                            int vh = (iv + 64) >> 7;
                            hh[e] = (char)vh;
                            ll[e] = (char)(iv - (vh << 7));
                        }
                        *(char2*)(out_h + (size_t)t * 512 + col) = make_char2(hh[0], hh[1]);
                        *(char2*)(out_l + (size_t)t * 512 + col) = make_char2(ll[0], ll[1]);
                    }
                    if ((lane & 3) == 0)
                        scg[(size_t)t * 16 + c * 2 + (wid >> 2)] = m * (1.0f / 16256.0f);
                }
            }
    }
}

// ---------------------------------------------------------------------------
// fc2 GEMM (K=512), M=64 x N=128 tiles, group dequant, optional fused LN.
// ---------------------------------------------------------------------------
template<int DO_LN>
__global__ __launch_bounds__(256, 2)
void i8_gemm_fc2m64(const int8_t* __restrict__ a_h, const int8_t* __restrict__ a_l,
                    const float* __restrict__ scg,
                    const int8_t* __restrict__ w_h, const int8_t* __restrict__ w_l,
                    const float* __restrict__ uB,
                    const float* __restrict__ biasv,
                    const float* __restrict__ addend,
                    const float* __restrict__ ln_g, const float* __restrict__ ln_b,
                    float* __restrict__ outf,
                    int8_t* __restrict__ z8h, int8_t* __restrict__ z8l,
                    float* __restrict__ s_z, int T)
{
    constexpr int K = 512;
    extern __shared__ char smem[];
    const uint32_t sbase = smem_to_u32(smem);
    const int tid = threadIdx.x, wid = tid >> 5, lane = tid & 31;
    const int t0 = blockIdx.x * 64;
    const int mwid = wid & 1, nwid = wid >> 1;

    auto stage = [&](int q) {
        uint32_t sb = sbase + (uint32_t)(q & 1) * 49152;
#pragma unroll
        for (int h = 0; h < 4; h++) {
            int i = tid + h * 256;
            int plane = i >> 9, idx = i & 511;
            int kt = idx >> 7, sub = idx & 127, row = sub >> 1, kc = sub & 1;
            int t = t0 + row; bool p = t < T;
            uint32_t dst = sb + (plane ? 8192u : 0u) + (uint32_t)kt * 2048 + SWZ8(row, kc);
            cp16(dst, (plane ? a_l : a_h) + (size_t)(p ? t : 0) * K
                          + q * 128 + kt * 32 + kc * 16, p);
        }
#pragma unroll
        for (int h = 0; h < 8; h++) {
            int i = tid + h * 256;
            int plane = i >> 10, idx = i & 1023;
            int kt = idx >> 8, sub = idx & 255, row = sub >> 1, kc = sub & 1;
            uint32_t dst = sb + 16384 + (plane ? 16384u : 0u) + (uint32_t)kt * 4096 + SWZ8(row, kc);
            cp16(dst, (plane ? w_l : w_h) + (size_t)row * K
                          + q * 128 + kt * 32 + kc * 16, true);
        }
    };
    stage(0); CP_COMMIT();
    stage(1); CP_COMMIT();

    float facc[2][4][4];
#pragma unroll
    for (int i = 0; i < 2; i++)
#pragma unroll
        for (int j = 0; j < 4; j++)
#pragma unroll
            for (int q = 0; q < 4; q++) facc[i][j][q] = 0.0f;

#pragma unroll 1
    for (int q = 0; q < 4; q++) {
        if (q < 3) CP_WAIT1(); else CP_WAIT0();
        __syncthreads();
        uint32_t sb = sbase + (uint32_t)(q & 1) * 49152;
#pragma unroll
        for (int kt = 0; kt < 4; kt++) {
            int g = q * 4 + kt;
            float sg[2][2];
#pragma unroll
            for (int mt = 0; mt < 2; mt++)
#pragma unroll
                for (int r2 = 0; r2 < 2; r2++) {
                    int row = mwid * 32 + mt * 16 + (lane >> 2) + r2 * 8;
                    int t = t0 + row;
                    sg[mt][r2] = scg[(size_t)(t < T ? t : 0) * 16 + g];
                }
            uint32_t fAh[2][4], fAl[2][4], fBh[2][4], fBl[2][4];
            {
                int arow = mwid * 32 + (lane & 7) + ((lane >> 3) & 1) * 8;
                int akc  = lane >> 4;
#pragma unroll
                for (int mt = 0; mt < 2; mt++) {
                    uint32_t off = (uint32_t)kt * 2048 + SWZ8(arow + mt * 16, akc);
                    ldm4(fAh[mt], sb + off);
                    ldm4(fAl[mt], sb + 8192 + off);
                }
                int brow = nwid * 32 + ((lane >> 4) & 1) * 8 + (lane & 7);
                int bkc  = (lane >> 3) & 1;
#pragma unroll
                for (int j = 0; j < 2; j++) {
                    uint32_t off = (uint32_t)kt * 4096 + SWZ8(brow + j * 16, bkc);
                    ldm4(fBh[j], sb + 16384 + off);
                    ldm4(fBl[j], sb + 32768 + off);
                }
            }
#pragma unroll
            for (int mt = 0; mt < 2; mt++)
#pragma unroll
                for (int nt = 0; nt < 4; nt++) {
                    int j = nt >> 1, o = (nt & 1) * 2;
                    int aHH[4] = {0, 0, 0, 0}, aMID[4] = {0, 0, 0, 0};
                    imma(aHH,  fAh[mt], fBh[j][o], fBh[j][o + 1]);
                    imma(aMID, fAh[mt], fBl[j][o], fBl[j][o + 1]);
                    imma(aMID, fAl[mt], fBh[j][o], fBh[j][o + 1]);
#pragma unroll
                    for (int e = 0; e < 4; e++)
                        facc[mt][nt][e] += (float)(aHH[e] * 128 + aMID[e]) * sg[mt][e >> 1];
                }
        }
        __syncthreads();
        if (q + 2 < 4) { stage(q + 2); CP_COMMIT(); }
    }

    // Epilogue: v, write s, optional LN+quant.
    float v[4][8];
    int ok[4]; size_t orow[4];
#pragma unroll
    for (int idx = 0; idx < 4; idx++) {
        int mt = idx >> 1, r2 = idx & 1;
        int row = mwid * 32 + mt * 16 + (lane >> 2) + r2 * 8;
        int t = t0 + row;
        ok[idx] = (t < T);
        orow[idx] = (size_t)t;
#pragma unroll
        for (int nt = 0; nt < 4; nt++) {
            int col = nwid * 32 + nt * 8 + (lane & 3) * 2;
            float v0 = facc[mt][nt][r2 * 2]     * uB[col];
            float v1 = facc[mt][nt][r2 * 2 + 1] * uB[col + 1];
            float2 b2 = *(const float2*)(biasv + col);
            v0 += b2.x; v1 += b2.y;
            float2 a2 = *(const float2*)(addend + (size_t)(ok[idx] ? t : 0) * 128 + col);
            v0 += a2.x; v1 += a2.y;
            if (ok[idx])
                *(float2*)(outf + (size_t)t * 128 + col) = make_float2(v0, v1);
            v[idx][nt * 2] = v0; v[idx][nt * 2 + 1] = v1;
        }
    }
    if (DO_LN) {
        __syncthreads();
        ln_epilogue_m64(v, smem, 98304, mwid, nwid, lane, ok, orow,
                        ln_g, ln_b, z8h, z8l, s_z);
    }
}

// ---------------------------------------------------------------------------
// Fused QKV + rsa + imv (512 threads, 1 CTA/SM).
// ---------------------------------------------------------------------------
__global__ __launch_bounds__(512)
void i8_qkv_rsa(const int8_t* __restrict__ a_h, const int8_t* __restrict__ a_l,
                const float* __restrict__ sA,
                const int8_t* __restrict__ w_h, const int8_t* __restrict__ w_l,
                const float* __restrict__ uB,
                float* __restrict__ imv32, int T)
{
    constexpr int K = 128;
    extern __shared__ char smem[];
    const uint32_t sbase = smem_to_u32(smem);
    const uint32_t sAh = sbase, sAl = sbase + 16384, sB0 = sbase + 32768;
    float* Q   = (float*)(smem + 98304);
    float* RSA = (float*)(smem + 165888);
    const int tid = threadIdx.x, wid = tid >> 5, lane = tid & 31;
    const int t0 = blockIdx.x * 128;

    for (int i = tid; i < 1024; i += 512) RSA[i] = 0.0f;

#pragma unroll
    for (int h = 0; h < 4; h++) {
        int i = tid + h * 512;
        int plane = i >> 10, idx = i & 1023;
        int kt = idx >> 8, sub = idx & 255, row = sub >> 1, kc = sub & 1;
        int t = t0 + row; bool p = t < T;
        uint32_t dst = (plane ? sAl : sAh) + (uint32_t)kt * 4096 + SWZ8(row, kc);
        cp16(dst, (plane ? a_l : a_h) + (size_t)(p ? t : 0) * K + kt * 32 + kc * 16, p);
    }
    auto stageB = [&](int c) {
        uint32_t bb = sB0 + (uint32_t)(c & 1) * 32768;
#pragma unroll
        for (int h = 0; h < 4; h++) {
            int i = tid + h * 512;
            int plane = i >> 10, idx = i & 1023;
            int kt = idx >> 8, sub = idx & 255, row = sub >> 1, kc = sub & 1;
            uint32_t dst = bb + (plane ? 16384u : 0u) + (uint32_t)kt * 4096 + SWZ8(row, kc);
            cp16(dst, (plane ? w_l : w_h) + (size_t)(c * 128 + row) * K + kt * 32 + kc * 16, true);
        }
    };
    stageB(0); CP_COMMIT();
    stageB(1); CP_COMMIT();

#pragma unroll 1
    for (int c = 0; c < 3; c++) {
        if (c < 2) CP_WAIT1(); else CP_WAIT0();
        __syncthreads();
        uint32_t bb = sB0 + (uint32_t)(c & 1) * 32768;
        int accHH[2][4][4], accMID[2][4][4];
        ZERO_ACC(accHH, accMID);
#pragma unroll
        for (int kt = 0; kt < 4; kt++)
            compute_tile(sAh + kt * 4096, sAl + kt * 4096,
                         bb + kt * 4096, bb + 16384 + kt * 4096,
                         wid, lane, accHH, accMID);
        __syncthreads();
        if (c + 2 < 3) { stageB(c + 2); CP_COMMIT(); }

        const int colb = (wid >> 2) * 32 + (lane & 3) * 2;
        const int cb = c * 128;
#pragma unroll
        for (int mt = 0; mt < 2; mt++)
#pragma unroll
            for (int r2 = 0; r2 < 2; r2++) {
                int row = (wid & 3) * 32 + mt * 16 + (lane >> 2) + r2 * 8;
                int t = t0 + row;
                bool ok = t < T;
                float sa = ok ? sA[t] : 0.0f;
                if (c == 0) {
#pragma unroll
                    for (int nt = 0; nt < 4; nt++) {
                        int col = colb + nt * 8;
                        int i0 = accHH[mt][nt][r2*2]   * 128 + accMID[mt][nt][r2*2];
                        int i1 = accHH[mt][nt][r2*2+1] * 128 + accMID[mt][nt][r2*2+1];
                        *(float2*)(Q + row * 132 + col) =
                            make_float2((float)i0 * sa * uB[cb + col],
                                        (float)i1 * sa * uB[cb + col + 1]);
                    }
                } else if (c == 1) {
                    float p0 = 0.0f, p1 = 0.0f;
#pragma unroll
                    for (int nt = 0; nt < 4; nt++) {
                        int col = colb + nt * 8;
                        int i0 = accHH[mt][nt][r2*2]   * 128 + accMID[mt][nt][r2*2];
                        int i1 = accHH[mt][nt][r2*2+1] * 128 + accMID[mt][nt][r2*2+1];
                        float k0 = (float)i0 * sa * uB[cb + col];
                        float k1 = (float)i1 * sa * uB[cb + col + 1];
                        float2 qv = *(float2*)(Q + row * 132 + col);
                        float d = qv.x * k0 + qv.y * k1;
                        if (nt < 2) p0 += d; else p1 += d;
                    }
                    atomicAdd(&RSA[row * 8 + (wid >> 2) * 2 + 0], p0);
                    atomicAdd(&RSA[row * 8 + (wid >> 2) * 2 + 1], p1);
                } else {
#pragma unroll
                    for (int nt = 0; nt < 4; nt++) {
                        int col = colb + nt * 8;
                        int i0 = accHH[mt][nt][r2*2]   * 128 + accMID[mt][nt][r2*2];
                        int i1 = accHH[mt][nt][r2*2+1] * 128 + accMID[mt][nt][r2*2+1];
                        float v0 = (float)i0 * sa * uB[cb + col];
                        float v1 = (float)i1 * sa * uB[cb + col + 1];
                        float r = RSA[row * 8 + (wid >> 2) * 2 + (nt >> 1)] * 0.25f;
                        if (ok)
                            *(float2*)(imv32 + (size_t)t * 128 + col) =
                                make_float2(r * v0, r * v1);
                    }
                }
            }
    }
}

// ---------------------------------------------------------------------------
// Row quantization helpers.
// ---------------------------------------------------------------------------
__device__ __forceinline__ void quant_row_dev(
    const float* __restrict__ src, int8_t* __restrict__ dh,
    int8_t* __restrict__ dl, float* __restrict__ sout,
    int kd, float smul, int lane)
{
    int n4 = kd >> 7;
    float4 v[4];
    float m = 0.0f;
#pragma unroll 4
    for (int i = 0; i < n4; i++) {
        v[i] = ((const float4*)src)[lane + 32 * i];
        m = fmaxf(m, fmaxf(fmaxf(fabsf(v[i].x), fabsf(v[i].y)),
                           fmaxf(fabsf(v[i].z), fabsf(v[i].w))));
    }
#pragma unroll
    for (int o = 16; o >= 1; o >>= 1) m = fmaxf(m, __shfl_xor_sync(0xffffffffu, m, o));
    float s   = m * (1.0f / 16256.0f);
    float inv = (m > 0.0f) ? (16256.0f / m) : 0.0f;
#pragma unroll 4
    for (int i = 0; i < n4; i++) {
        float vv[4] = {v[i].x, v[i].y, v[i].z, v[i].w};
        char h4[4], l4[4];
#pragma unroll
        for (int q = 0; q < 4; q++) {
            int iv = __float2int_rn(vv[q] * inv);
            int vh = (iv + 64) >> 7;
            int vl = iv - (vh << 7);
            h4[q] = (char)vh; l4[q] = (char)vl;
        }
        ((char4*)dh)[lane + 32 * i] = make_char4(h4[0], h4[1], h4[2], h4[3]);
        ((char4*)dl)[lane + 32 * i] = make_char4(l4[0], l4[1], l4[2], l4[3]);
    }
    if (lane == 0) *sout = s * smul;
}

template<int KD>
__global__ void quant_rows(const float* __restrict__ src,
                           int8_t* __restrict__ dh, int8_t* __restrict__ dl,
                           float* __restrict__ sc, int T)
{
    int warp = threadIdx.x >> 5, lane = threadIdx.x & 31;
    int t = blockIdx.x * 8 + warp;
    if (t >= T) return;
    quant_row_dev(src + (size_t)t * KD, dh + (size_t)t * KD, dl + (size_t)t * KD,
                  sc + t, KD, 1.0f, lane);
}

__global__ void quantW(const float* __restrict__ w0, const float* __restrict__ wq,
                       const float* __restrict__ wo, const float* __restrict__ f1,
                       const float* __restrict__ f2,
                       int8_t* __restrict__ dh, int8_t* __restrict__ dl,
                       float* __restrict__ sc)
{
    int gw = blockIdx.x * 8 + (threadIdx.x >> 5);
    int lane = threadIdx.x & 31;
    if (gw >= 1792) return;
    const float* src; int kd = 128; size_t off;
    if (gw < 128)       { src = w0 + (size_t)gw * 128;          off = (size_t)gw * 128; }
    else if (gw < 896)  { int q = gw - 128;  src = wq + (size_t)q * 128; off = 16384  + (size_t)q * 128; }
    else if (gw < 1152) { int q = gw - 896;  src = wo + (size_t)q * 128; off = 114688 + (size_t)q * 128; }
    else if (gw < 1664) { int q = gw - 1152; src = f1 + (size_t)q * 128; off = 147456 + (size_t)q * 128; }
    else                { int q = gw - 1664; src = f2 + (size_t)q * 512; off = 212992 + (size_t)q * 512; kd = 512; }
    quant_row_dev(src, dh + off, dl + off, sc + gw, kd, 128.0f, lane);
}

// ---------------------------------------------------------------------------
// LN + quant for the 120 cls rows only (REMAP init doesn't cover them).
// ---------------------------------------------------------------------------
__global__ void ln_cls(const float* __restrict__ x,
                       const float* __restrict__ g,
                       const float* __restrict__ b,
                       int8_t* __restrict__ zh, int8_t* __restrict__ zl,
                       float* __restrict__ sc)
{
    int warp = threadIdx.x >> 5, lane = threadIdx.x & 31;
    int w = blockIdx.x * 8 + warp;
    if (w >= AA) return;
    size_t t = (size_t)w * BP1;

    float4 v = ((const float4*)(x + t * 128))[lane];
    float s = v.x + v.y + v.z + v.w;
#pragma unroll
    for (int o = 16; o >= 1; o >>= 1) s += __shfl_xor_sync(0xffffffffu, s, o);
    float mu = s * (1.0f / 128.0f);
    float dx = v.x - mu, dy = v.y - mu, dz = v.z - mu, dw = v.w - mu;
    float q = dx * dx + dy * dy + dz * dz + dw * dw;
#pragma unroll
    for (int o = 16; o >= 1; o >>= 1) q += __shfl_xor_sync(0xffffffffu, q, o);
    float rs = rsqrtf(q * (1.0f / 128.0f) + 1e-5f);

    float4 gg = ((const float4*)g)[lane];
    float4 bb = ((const float4*)b)[lane];
    float o0 = dx * rs * gg.x + bb.x;
    float o1 = dy * rs * gg.y + bb.y;
    float o2 = dz * rs * gg.z + bb.z;
    float o3 = dw * rs * gg.w + bb.w;

    float m = fmaxf(fmaxf(fabsf(o0), fabsf(o1)), fmaxf(fabsf(o2), fabsf(o3)));
#pragma unroll
    for (int o = 16; o >= 1; o >>= 1) m = fmaxf(m, __shfl_xor_sync(0xffffffffu, m, o));
    float inv = (m > 0.0f) ? (16256.0f / m) : 0.0f;

    float vv[4] = {o0, o1, o2, o3};
    char h4[4], l4[4];
#pragma unroll
    for (int qi = 0; qi < 4; qi++) {
        int iv = __float2int_rn(vv[qi] * inv);
        int vh = (iv + 64) >> 7;
        h4[qi] = (char)vh;
        l4[qi] = (char)(iv - (vh << 7));
    }
    ((char4*)(zh + t * 128))[lane] = make_char4(h4[0], h4[1], h4[2], h4[3]);
    ((char4*)(zl + t * 128))[lane] = make_char4(l4[0], l4[1], l4[2], l4[3]);
    if (lane == 0) sc[t] = m * (1.0f / 16256.0f);
}

// ---------------------------------------------------------------------------
// Chunked cumsum + fused quantization.
// ---------------------------------------------------------------------------
__global__ void csum_partial(const float* __restrict__ imv, float* __restrict__ part)
{
    int c = blockIdx.x, i = blockIdx.y, f = threadIdx.x;
    size_t base = ((size_t)i * BP1 + c * 128) * 128 + f;
    float sum = 0.0f;
#pragma unroll 8
    for (int j = 0; j < 128; j++) sum += imv[base + (size_t)j * 128];
    part[((size_t)i * 16 + c) * 128 + f] = sum;
}

__global__ void csum_scan(float* __restrict__ part)
{
    int i = blockIdx.x, f = threadIdx.x;
    float run = 0.0f;
#pragma unroll
    for (int c = 0; c < 16; c++) {
        size_t idx = ((size_t)i * 16 + c) * 128 + f;
        float t = part[idx];
        part[idx] = run;
        run += t;
    }
}

__global__ void csum_apply(const float* __restrict__ imv,
                           const float* __restrict__ part,
                           int8_t* __restrict__ dh, int8_t* __restrict__ dl,
                           float* __restrict__ sc)
{
    __shared__ float sm[4][8];
    int c = blockIdx.x, i = blockIdx.y, f = threadIdx.x;
    int warp = f >> 5, lane = f & 31;
    size_t base = ((size_t)i * BP1 + c * 128) * 128 + f;
    float acc = part[((size_t)i * 16 + c) * 128 + f];

#pragma unroll 1
    for (int jb = 0; jb < 16; jb++) {
        float val[8], mx[8];
#pragma unroll
        for (int u = 0; u < 8; u++) {
            acc += imv[base + (size_t)(jb * 8 + u) * 128];
            val[u] = acc;
            mx[u] = fabsf(acc);
        }
#pragma unroll
        for (int o = 16; o >= 1; o >>= 1)
#pragma unroll
            for (int u = 0; u < 8; u++)
                mx[u] = fmaxf(mx[u], __shfl_xor_sync(0xffffffffu, mx[u], o));
        if (lane == 0) {
#pragma unroll
            for (int u = 0; u < 8; u++) sm[warp][u] = mx[u];
        }
        __syncthreads();
#pragma unroll
        for (int u = 0; u < 8; u++) {
            float m = fmaxf(fmaxf(sm[0][u], sm[1][u]), fmaxf(sm[2][u], sm[3][u]));
            float inv = (m > 0.0f) ? (16256.0f / m) : 0.0f;
            int iv = __float2int_rn(val[u] * inv);
            int vh = (iv + 64) >> 7;
            int vl = iv - (vh << 7);
            size_t row = (size_t)i * BP1 + c * 128 + jb * 8 + u;
            dh[row * 128 + f] = (int8_t)vh;
            dl[row * 128 + f] = (int8_t)vl;
            if (f == 0) sc[row] = m * (1.0f / 16256.0f);
        }
        __syncthreads();
    }
}

__global__ void quant_last(const float* __restrict__ imv,
                           int8_t* __restrict__ dh, int8_t* __restrict__ dl,
                           float* __restrict__ sc)
{
    int w = blockIdx.x * 8 + (threadIdx.x >> 5), lane = threadIdx.x & 31;
    if (w >= AA) return;
    size_t row = (size_t)w * BP1 + BB;
    quant_row_dev(imv + row * 128, dh + row * 128, dl + row * 128,
                  sc + row, 128, 1.0f, lane);
}

__global__ void cls_kernel(const float* __restrict__ cls,
                           const float* __restrict__ bias,
                           float* __restrict__ out)
{
    int i = blockIdx.x, l = threadIdx.x;
    out[(size_t)i * BP1 * 128 + l] = cls[i * 128 + l] + bias[(size_t)i * BP1 * 128 + l];
}

// ---------------------------------------------------------------------------
// Launch
// ---------------------------------------------------------------------------
extern "C" void kernel_launch(void* const* d_in, const int* in_sizes, int n_in,
                              void* d_out, int out_size)
{
    const float* x      = (const float*)d_in[0];
    const float* weight = (const float*)d_in[1];
    const float* cls    = (const float*)d_in[2];
    const float* bias   = (const float*)d_in[3];
    const float* Wqkv   = (const float*)d_in[4];
    const float* Wo     = (const float*)d_in[5];
    const float* ln1_g  = (const float*)d_in[6];
    const float* ln1_b  = (const float*)d_in[7];
    const float* ln2_g  = (const float*)d_in[8];
    const float* ln2_b  = (const float*)d_in[9];
    const float* fc1_w  = (const float*)d_in[10];
    const float* fc1_b  = (const float*)d_in[11];
    const float* fc2_w  = (const float*)d_in[12];
    const float* fc2_b  = (const float*)d_in[13];
    float* s = (float*)d_out;

    void *pbig, *pact, *ph8, *pwh, *pwl, *pscw, *psct, *psch, *ppart;
    cudaGetSymbolAddress(&pbig, g_big);
    cudaGetSymbolAddress(&pact, g_act8);
    cudaGetSymbolAddress(&ph8,  g_h8);
    cudaGetSymbolAddress(&pwh,  g_w8h);
    cudaGetSymbolAddress(&pwl,  g_w8l);
    cudaGetSymbolAddress(&pscw, g_sc_w);
    cudaGetSymbolAddress(&psct, g_sc_tok);
    cudaGetSymbolAddress(&psch, g_sch);
    cudaGetSymbolAddress(&ppart, g_part);

    float*  big   = (float*)pbig;
    int8_t* act8  = (int8_t*)pact;
    int8_t* h8    = (int8_t*)ph8;
    int8_t* w8h   = (int8_t*)pwh;
    int8_t* w8l   = (int8_t*)pwl;
    float*  sc_w  = (float*)pscw;
    float*  sc_t  = (float*)psct;
    float*  sc_h  = (float*)psch;
    float*  partb = (float*)ppart;

    const int T  = TTOK;
    const int Tx = TXTOK;
    const int tokBlocks = (T + 127) / 128;   // 1922
    const int m64Blocks = (T + 63) / 64;     // 3842
    const int m64BlocksX = Tx / 64;          // 3840

    int8_t* z8h   = act8;
    int8_t* z8l   = z8h + (size_t)T * 128;
    int8_t* imv8h = z8h;                     // alias (z dead after qkv)
    int8_t* imv8l = z8l;
    int8_t* h8h   = h8;
    int8_t* h8l   = h8h + (size_t)T * 512;
    int8_t* x8h   = h8;                      // alias (x only used at init)
    int8_t* x8l   = x8h + (size_t)Tx * 128;
    float* imv32 = big;                      // T*128
    float* s_z   = sc_t;
    float* s_imv = sc_t + T;
    float* s_x   = sc_t + 3 * (size_t)T;

    const int SM_M64  = 52224;   // 48K tiles + 3K red (+pad)
    const int SM_QKV  = 169984;
    const int SM_FC2  = 101376;  // 96K tiles + 3K red (+pad)
    const int SM_FC1  = 65536;
    cudaFuncSetAttribute(i8_gemm_m64k128<1>, cudaFuncAttributeMaxDynamicSharedMemorySize, SM_M64);
    cudaFuncSetAttribute(i8_gemm_m64k128<0>, cudaFuncAttributeMaxDynamicSharedMemorySize, SM_M64);
    cudaFuncSetAttribute(i8_gemm_fc1,       cudaFuncAttributeMaxDynamicSharedMemorySize, SM_FC1);
    cudaFuncSetAttribute(i8_gemm_fc2m64<1>, cudaFuncAttributeMaxDynamicSharedMemorySize, SM_FC2);
    cudaFuncSetAttribute(i8_gemm_fc2m64<0>, cudaFuncAttributeMaxDynamicSharedMemorySize, SM_FC2);
    cudaFuncSetAttribute(i8_qkv_rsa,        cudaFuncAttributeMaxDynamicSharedMemorySize, SM_QKV);

    // 1: weights + x quant + cls row
    quantW<<<224, 256>>>(weight, Wqkv, Wo, fc1_w, fc2_w, w8h, w8l, sc_w);
    quant_rows<128><<<(Tx + 7) / 8, 256>>>(x, x8h, x8l, s_x, Tx);
    cls_kernel<<<AA, 128>>>(cls, bias, s);
    // 2: s = concat([cls, x @ W^T], 1) + bias ; fused LN1 -> z8
    i8_gemm_m64k128<1><<<m64BlocksX, 256, SM_M64>>>(
        x8h, x8l, s_x, w8h, w8l, sc_w, bias, ln1_g, ln1_b,
        s, z8h, z8l, s_z, Tx);
    // 3: LN1 for the 120 cls rows
    ln_cls<<<(AA + 7) / 8, 256>>>(s, ln1_g, ln1_b, z8h, z8l, s_z);

    for (int a = 0; a < 2; a++) {
        const int8_t* wq_h = w8h + 16384 + (size_t)a * 49152;
        const int8_t* wq_l = w8l + 16384 + (size_t)a * 49152;
        const float*  uq   = sc_w + 128 + a * 384;
        const int8_t* wo_h = w8h + 114688 + (size_t)a * 16384;
        const int8_t* wo_l = w8l + 114688 + (size_t)a * 16384;
        const float*  uo   = sc_w + 896 + a * 128;

        // imv32 = 0.25*(q.k per head)*v  (fused qkv + rsa; reads z8)
        i8_qkv_rsa<<<tokBlocks, 512, SM_QKV>>>(
            z8h, z8l, s_z, wq_h, wq_l, uq, imv32, T);
        // chunked causal cumsum + quantization
        csum_partial<<<dim3(16, AA), 128>>>(imv32, partb);
        csum_scan<<<AA, 128>>>(partb);
        csum_apply<<<dim3(16, AA), 128>>>(imv32, partb, imv8h, imv8l, s_imv);
        quant_last<<<(AA + 7) / 8, 256>>>(imv32, imv8h, imv8l, s_imv);
        // s += imv @ Wo^T ; fused LN2 -> z8
        i8_gemm_m64k128<0><<<m64Blocks, 256, SM_M64>>>(
            imv8h, imv8l, s_imv, wo_h, wo_l, uo, s, ln2_g, ln2_b,
            s, z8h, z8l, s_z, T);
        // h8 = quant(gelu(z @ fc1^T + b1)) with group scales
        i8_gemm_fc1<<<tokBlocks, 256, SM_FC1>>>(
            z8h, z8l, s_z, w8h + 147456, w8l + 147456, sc_w + 1152,
            fc1_b, h8h, h8l, sc_h, T);
        // s = h @ fc2^T + b2 + s ; fused LN1 for next layer (a=0 only)
        if (a == 0) {
            i8_gemm_fc2m64<1><<<m64Blocks, 256, SM_FC2>>>(
                h8h, h8l, sc_h, w8h + 212992, w8l + 212992, sc_w + 1664,
                fc2_b, s, ln1_g, ln1_b, s, z8h, z8l, s_z, T);
        } else {
            i8_gemm_fc2m64<0><<<m64Blocks, 256, SM_FC2>>>(
                h8h, h8l, sc_h, w8h + 212992, w8l + 212992, sc_w + 1664,
                fc2_b, s, nullptr, nullptr, s, nullptr, nullptr, nullptr, T);
        }
    }
    (void)in_sizes; (void)n_in; (void)out_size;
}

// round 15
// speedup vs baseline: 1.0588x; 1.0296x over previous
#include <cuda_runtime.h>
#include <cuda_bf16.h>
#include <math.h>
#include <stdint.h>

// ---------------------------------------------------------------------------
// EEGformer forward. int8 dual-plane GEMMs (mma.sync.m16n8k32.s8).
// R15: qkv_rsa rewritten M=64 x N=128, q parked in registers, rsa via quad
// shuffles -> 2 CTAs/SM on the heaviest kernel. (R14 base otherwise.)
// A=120, B=2048, Bp1=2049, M=128, T = 120*2049 = 245880 tokens.
// ---------------------------------------------------------------------------

#define AA    120
#define BB    2048
#define BP1   2049
#define TTOK  (AA * BP1)      // 245880
#define TXTOK (AA * BB)       // 245760
#define TPAD  246016

__device__ float  g_big[(size_t)TTOK * 128];        // imv32 fp32
__device__ int8_t g_act8[(size_t)TTOK * 256];       // z / imv planes
__device__ int8_t g_h8  [(size_t)TTOK * 512 * 2];   // h planes / x planes
__device__ int8_t g_w8h[278528];
__device__ int8_t g_w8l[278528];
__device__ float  g_sc_w[1792];
__device__ float  g_sc_tok[(size_t)3 * TTOK + TXTOK];
__device__ float  g_sch[(size_t)TPAD * 16];         // h group scales
__device__ float  g_part[AA * 16 * 128];

// ---------------------------------------------------------------------------
// PTX helpers
// ---------------------------------------------------------------------------
__device__ __forceinline__ uint32_t smem_to_u32(const void* p) {
    uint32_t a;
    asm("{ .reg .u64 t; cvta.to.shared.u64 t, %1; cvt.u32.u64 %0, t; }" : "=r"(a) : "l"(p));
    return a;
}
__device__ __forceinline__ void ldm4(uint32_t r[4], uint32_t addr) {
    asm volatile("ldmatrix.sync.aligned.m8n8.x4.shared.b16 {%0,%1,%2,%3}, [%4];"
        : "=r"(r[0]), "=r"(r[1]), "=r"(r[2]), "=r"(r[3]) : "r"(addr));
}
__device__ __forceinline__ void imma(int d[4], const uint32_t a[4],
                                     uint32_t b0, uint32_t b1) {
    asm volatile("mma.sync.aligned.m16n8k32.row.col.s32.s8.s8.s32 "
        "{%0,%1,%2,%3}, {%4,%5,%6,%7}, {%8,%9}, {%0,%1,%2,%3};"
        : "+r"(d[0]), "+r"(d[1]), "+r"(d[2]), "+r"(d[3])
        : "r"(a[0]), "r"(a[1]), "r"(a[2]), "r"(a[3]), "r"(b0), "r"(b1));
}
__device__ __forceinline__ void cp16(uint32_t saddr, const void* g, bool p) {
    int sz = p ? 16 : 0;
    asm volatile("cp.async.cg.shared.global [%0], [%1], 16, %2;"
        :: "r"(saddr), "l"(g), "r"(sz) : "memory");
}
#define CP_COMMIT() asm volatile("cp.async.commit_group;" ::: "memory")
#define CP_WAIT1()  asm volatile("cp.async.wait_group 1;" ::: "memory")
#define CP_WAIT0()  asm volatile("cp.async.wait_group 0;" ::: "memory")

// 32-byte-row swizzle inside one k-tile: line = row>>2 (128B)
#define SWZ8(row, kc) ((((row) >> 2) * 128) + \
    (((((row) & 3) * 2 + (kc)) ^ (((row) >> 2) & 7)) << 4))

// Fragment loads, block 128(M) x 64(N), 8 warps 4(M, wid&3) x 2(N, wid>>2).
#define LOAD_FRAGS64(sAh, sAl, sBh, sBl) do { \
    int arow = (wid & 3) * 32 + (lane & 7) + ((lane >> 3) & 1) * 8; \
    int akc  = lane >> 4; \
    _Pragma("unroll") for (int mt = 0; mt < 2; mt++) { \
        uint32_t off = SWZ8(arow + mt * 16, akc); \
        ldm4(fAh[mt], (sAh) + off); \
        ldm4(fAl[mt], (sAl) + off); \
    } \
    int brow = (wid >> 2) * 32 + ((lane >> 4) & 1) * 8 + (lane & 7); \
    int bkc  = (lane >> 3) & 1; \
    _Pragma("unroll") for (int j = 0; j < 2; j++) { \
        uint32_t off = SWZ8(brow + j * 16, bkc); \
        ldm4(fBh[j], (sBh) + off); \
        ldm4(fBl[j], (sBl) + off); \
    } \
} while (0)

#define ZERO_ACC(accHH, accMID) do { \
    _Pragma("unroll") for (int i = 0; i < 2; i++) \
    _Pragma("unroll") for (int j = 0; j < 4; j++) \
    _Pragma("unroll") for (int q = 0; q < 4; q++) { accHH[i][j][q] = 0; accMID[i][j][q] = 0; } \
} while (0)

// ---------------------------------------------------------------------------
// Fused LN + int8 quant epilogue for M=64 x N=128 kernels.
// ---------------------------------------------------------------------------
__device__ __forceinline__ void ln_epilogue_m64(
    float v[4][8], char* smem, int red_off,
    int mwid, int nwid, int lane,
    const int ok[4], const size_t orow[4],
    const float* __restrict__ ln_g, const float* __restrict__ ln_b,
    int8_t* __restrict__ z8h, int8_t* __restrict__ z8l,
    float* __restrict__ s_z)
{
    float* sm_sum = (float*)(smem + red_off);   // [64][4]
    float* sm_sq  = sm_sum + 256;
    float* sm_mx  = sm_sum + 512;
    int rl[4];
#pragma unroll
    for (int idx = 0; idx < 4; idx++)
        rl[idx] = mwid * 32 + (idx >> 1) * 16 + (idx & 1) * 8 + (lane >> 2);

#pragma unroll
    for (int idx = 0; idx < 4; idx++) {
        float ps = 0.0f, pq = 0.0f;
#pragma unroll
        for (int j = 0; j < 8; j++) { ps += v[idx][j]; pq += v[idx][j] * v[idx][j]; }
        ps += __shfl_xor_sync(0xffffffffu, ps, 1);
        ps += __shfl_xor_sync(0xffffffffu, ps, 2);
        pq += __shfl_xor_sync(0xffffffffu, pq, 1);
        pq += __shfl_xor_sync(0xffffffffu, pq, 2);
        if ((lane & 3) == 0) {
            sm_sum[rl[idx] * 4 + nwid] = ps;
            sm_sq [rl[idx] * 4 + nwid] = pq;
        }
    }
    __syncthreads();
#pragma unroll
    for (int idx = 0; idx < 4; idx++) {
        float ts = sm_sum[rl[idx] * 4 + 0] + sm_sum[rl[idx] * 4 + 1]
                 + sm_sum[rl[idx] * 4 + 2] + sm_sum[rl[idx] * 4 + 3];
        float tq = sm_sq[rl[idx] * 4 + 0] + sm_sq[rl[idx] * 4 + 1]
                 + sm_sq[rl[idx] * 4 + 2] + sm_sq[rl[idx] * 4 + 3];
        float mu = ts * (1.0f / 128.0f);
        float var = tq * (1.0f / 128.0f) - mu * mu;
        float rs = rsqrtf(var + 1e-5f);
        float m = 0.0f;
#pragma unroll
        for (int j = 0; j < 8; j++) {
            int col = nwid * 32 + (j >> 1) * 8 + (lane & 3) * 2 + (j & 1);
            float o = (v[idx][j] - mu) * rs * ln_g[col] + ln_b[col];
            v[idx][j] = o;
            m = fmaxf(m, fabsf(o));
        }
        m = fmaxf(m, __shfl_xor_sync(0xffffffffu, m, 1));
        m = fmaxf(m, __shfl_xor_sync(0xffffffffu, m, 2));
        if ((lane & 3) == 0) sm_mx[rl[idx] * 4 + nwid] = m;
    }
    __syncthreads();
#pragma unroll
    for (int idx = 0; idx < 4; idx++) {
        float m = fmaxf(fmaxf(sm_mx[rl[idx] * 4 + 0], sm_mx[rl[idx] * 4 + 1]),
                        fmaxf(sm_mx[rl[idx] * 4 + 2], sm_mx[rl[idx] * 4 + 3]));
        float inv = (m > 0.0f) ? (16256.0f / m) : 0.0f;
        if (ok[idx]) {
#pragma unroll
            for (int nt = 0; nt < 4; nt++) {
                int colp = nwid * 32 + nt * 8 + (lane & 3) * 2;
                char hh[2], ll[2];
#pragma unroll
                for (int e = 0; e < 2; e++) {
                    int iv = __float2int_rn(v[idx][nt * 2 + e] * inv);
                    int vh = (iv + 64) >> 7;
                    hh[e] = (char)vh;
                    ll[e] = (char)(iv - (vh << 7));
                }
                *(char2*)(z8h + orow[idx] * 128 + colp) = make_char2(hh[0], hh[1]);
                *(char2*)(z8l + orow[idx] * 128 + colp) = make_char2(ll[0], ll[1]);
            }
            if ((lane & 3) == 0 && nwid == 0) s_z[orow[idx]] = m * (1.0f / 16256.0f);
        }
    }
}

// ---------------------------------------------------------------------------
// M=64 x N=128, K=128 single-shot burst GEMM (init, Wo) with fused LN+quant.
// ---------------------------------------------------------------------------
template<int REMAP>
__global__ __launch_bounds__(256, 2)
void i8_gemm_m64k128(const int8_t* __restrict__ a_h, const int8_t* __restrict__ a_l,
                     const float* __restrict__ sA,
                     const int8_t* __restrict__ w_h, const int8_t* __restrict__ w_l,
                     const float* __restrict__ uB,
                     const float* __restrict__ addend,
                     const float* __restrict__ ln_g, const float* __restrict__ ln_b,
                     float* __restrict__ outf,
                     int8_t* __restrict__ z8h, int8_t* __restrict__ z8l,
                     float* __restrict__ s_z, int T)
{
    constexpr int K = 128;
    extern __shared__ char smem[];
    const uint32_t sbase = smem_to_u32(smem);
    const int tid = threadIdx.x, wid = tid >> 5, lane = tid & 31;
    const int t0 = blockIdx.x * 64;
    const int mwid = wid & 1, nwid = wid >> 1;

#pragma unroll
    for (int h = 0; h < 4; h++) {
        int i = tid + h * 256;
        int plane = i >> 9, idx = i & 511;
        int kt = idx >> 7, sub = idx & 127, row = sub >> 1, kc = sub & 1;
        int t = t0 + row; bool p = t < T;
        uint32_t dst = sbase + (plane ? 8192u : 0u) + (uint32_t)kt * 2048 + SWZ8(row, kc);
        cp16(dst, (plane ? a_l : a_h) + (size_t)(p ? t : 0) * K + kt * 32 + kc * 16, p);
    }
#pragma unroll
    for (int h = 0; h < 8; h++) {
        int i = tid + h * 256;
        int plane = i >> 10, idx = i & 1023;
        int kt = idx >> 8, sub = idx & 255, row = sub >> 1, kc = sub & 1;
        uint32_t dst = sbase + 16384 + (plane ? 16384u : 0u) + (uint32_t)kt * 4096 + SWZ8(row, kc);
        cp16(dst, (plane ? w_l : w_h) + (size_t)row * K + kt * 32 + kc * 16, true);
    }
    CP_COMMIT();
    CP_WAIT0();
    __syncthreads();

    int accHH[2][4][4], accMID[2][4][4];
    ZERO_ACC(accHH, accMID);
#pragma unroll
    for (int kt = 0; kt < 4; kt++) {
        uint32_t fAh[2][4], fAl[2][4], fBh[2][4], fBl[2][4];
        {
            int arow = mwid * 32 + (lane & 7) + ((lane >> 3) & 1) * 8;
            int akc  = lane >> 4;
#pragma unroll
            for (int mt = 0; mt < 2; mt++) {
                uint32_t off = (uint32_t)kt * 2048 + SWZ8(arow + mt * 16, akc);
                ldm4(fAh[mt], sbase + off);
                ldm4(fAl[mt], sbase + 8192 + off);
            }
            int brow = nwid * 32 + ((lane >> 4) & 1) * 8 + (lane & 7);
            int bkc  = (lane >> 3) & 1;
#pragma unroll
            for (int j = 0; j < 2; j++) {
                uint32_t off = (uint32_t)kt * 4096 + SWZ8(brow + j * 16, bkc);
                ldm4(fBh[j], sbase + 16384 + off);
                ldm4(fBl[j], sbase + 32768 + off);
            }
        }
#pragma unroll
        for (int mt = 0; mt < 2; mt++)
#pragma unroll
            for (int nt = 0; nt < 4; nt++) {
                int j = nt >> 1, o = (nt & 1) * 2;
                imma(accHH[mt][nt],  fAh[mt], fBh[j][o], fBh[j][o + 1]);
                imma(accMID[mt][nt], fAh[mt], fBl[j][o], fBl[j][o + 1]);
                imma(accMID[mt][nt], fAl[mt], fBh[j][o], fBh[j][o + 1]);
            }
    }

    float v[4][8];
    int ok[4]; size_t orow[4];
#pragma unroll
    for (int idx = 0; idx < 4; idx++) {
        int mt = idx >> 1, r2 = idx & 1;
        int row = mwid * 32 + mt * 16 + (lane >> 2) + r2 * 8;
        int t = t0 + row;
        ok[idx] = (t < T);
        orow[idx] = REMAP ? ((size_t)t + (size_t)((unsigned)t / 2048u) + 1) : (size_t)t;
        float sa = sA[ok[idx] ? t : 0];
#pragma unroll
        for (int nt = 0; nt < 4; nt++) {
            int col = nwid * 32 + nt * 8 + (lane & 3) * 2;
            int i0 = accHH[mt][nt][r2 * 2]     * 128 + accMID[mt][nt][r2 * 2];
            int i1 = accHH[mt][nt][r2 * 2 + 1] * 128 + accMID[mt][nt][r2 * 2 + 1];
            float v0 = (float)i0 * sa * uB[col];
            float v1 = (float)i1 * sa * uB[col + 1];
            float2 a2 = *(const float2*)(addend + orow[idx] * 128 + col);
            v0 += a2.x; v1 += a2.y;
            if (ok[idx])
                *(float2*)(outf + orow[idx] * 128 + col) = make_float2(v0, v1);
            v[idx][nt * 2] = v0; v[idx][nt * 2 + 1] = v1;
        }
    }
    __syncthreads();
    ln_epilogue_m64(v, smem, 49152, mwid, nwid, lane, ok, orow,
                    ln_g, ln_b, z8h, z8l, s_z);
}

// ---------------------------------------------------------------------------
// Fused QKV + rsa + imv, M=64 x N=128, 256 threads, q in registers,
// rsa via quad shuffles. smem: A 16K | B 2x32K = 80K -> 2 CTAs/SM.
// ---------------------------------------------------------------------------
__global__ __launch_bounds__(256, 2)
void i8_qkv_rsa_m64(const int8_t* __restrict__ a_h, const int8_t* __restrict__ a_l,
                    const float* __restrict__ sA,
                    const int8_t* __restrict__ w_h, const int8_t* __restrict__ w_l,
                    const float* __restrict__ uB,
                    float* __restrict__ imv32, int T)
{
    constexpr int K = 128;
    extern __shared__ char smem[];
    const uint32_t sbase = smem_to_u32(smem);
    const uint32_t sAh = sbase, sAl = sbase + 8192, sB0 = sbase + 16384;
    const int tid = threadIdx.x, wid = tid >> 5, lane = tid & 31;
    const int t0 = blockIdx.x * 64;
    const int mwid = wid & 1, nwid = wid >> 1;

    // A burst: 2 planes x 4 kt x 64 rows x 2 kc = 1024 cp16
#pragma unroll
    for (int h = 0; h < 4; h++) {
        int i = tid + h * 256;
        int plane = i >> 9, idx = i & 511;
        int kt = idx >> 7, sub = idx & 127, row = sub >> 1, kc = sub & 1;
        int t = t0 + row; bool p = t < T;
        uint32_t dst = (plane ? sAl : sAh) + (uint32_t)kt * 2048 + SWZ8(row, kc);
        cp16(dst, (plane ? a_l : a_h) + (size_t)(p ? t : 0) * K + kt * 32 + kc * 16, p);
    }
    auto stageB = [&](int c) {    // 32KB: 2 planes x 4 kt x 128 rows x 2 kc
        uint32_t bb = sB0 + (uint32_t)(c & 1) * 32768;
#pragma unroll
        for (int h = 0; h < 8; h++) {
            int i = tid + h * 256;
            int plane = i >> 10, idx = i & 1023;
            int kt = idx >> 8, sub = idx & 255, row = sub >> 1, kc = sub & 1;
            uint32_t dst = bb + (plane ? 16384u : 0u) + (uint32_t)kt * 4096 + SWZ8(row, kc);
            cp16(dst, (plane ? w_l : w_h) + (size_t)(c * 128 + row) * K + kt * 32 + kc * 16, true);
        }
    };
    stageB(0); CP_COMMIT();
    stageB(1); CP_COMMIT();

    float qv[4][8];     // q values (chunk 0)
    float rsa[4][2];    // per-row, per-local-head rsa (after chunk 1)

#pragma unroll 1
    for (int c = 0; c < 3; c++) {
        if (c < 2) CP_WAIT1(); else CP_WAIT0();
        __syncthreads();
        uint32_t bb = sB0 + (uint32_t)(c & 1) * 32768;
        int accHH[2][4][4], accMID[2][4][4];
        ZERO_ACC(accHH, accMID);
#pragma unroll
        for (int kt = 0; kt < 4; kt++) {
            uint32_t fAh[2][4], fAl[2][4], fBh[2][4], fBl[2][4];
            {
                int arow = mwid * 32 + (lane & 7) + ((lane >> 3) & 1) * 8;
                int akc  = lane >> 4;
#pragma unroll
                for (int mt = 0; mt < 2; mt++) {
                    uint32_t off = (uint32_t)kt * 2048 + SWZ8(arow + mt * 16, akc);
                    ldm4(fAh[mt], sAh + off);
                    ldm4(fAl[mt], sAl + off);
                }
                int brow = nwid * 32 + ((lane >> 4) & 1) * 8 + (lane & 7);
                int bkc  = (lane >> 3) & 1;
#pragma unroll
                for (int j = 0; j < 2; j++) {
                    uint32_t off = (uint32_t)kt * 4096 + SWZ8(brow + j * 16, bkc);
                    ldm4(fBh[j], bb + off);
                    ldm4(fBl[j], bb + 16384 + off);
                }
            }
#pragma unroll
            for (int mt = 0; mt < 2; mt++)
#pragma unroll
                for (int nt = 0; nt < 4; nt++) {
                    int j = nt >> 1, o = (nt & 1) * 2;
                    imma(accHH[mt][nt],  fAh[mt], fBh[j][o], fBh[j][o + 1]);
                    imma(accMID[mt][nt], fAh[mt], fBl[j][o], fBl[j][o + 1]);
                    imma(accMID[mt][nt], fAl[mt], fBh[j][o], fBh[j][o + 1]);
                }
        }
        __syncthreads();
        if (c + 2 < 3) { stageB(c + 2); CP_COMMIT(); }

        const int cb = c * 128;
#pragma unroll
        for (int idx = 0; idx < 4; idx++) {
            int mt = idx >> 1, r2 = idx & 1;
            int row = mwid * 32 + mt * 16 + (lane >> 2) + r2 * 8;
            int t = t0 + row;
            bool ok = t < T;
            float sa = sA[ok ? t : 0];
            if (c == 0) {
#pragma unroll
                for (int nt = 0; nt < 4; nt++) {
                    int col = nwid * 32 + nt * 8 + (lane & 3) * 2;
                    int i0 = accHH[mt][nt][r2*2]   * 128 + accMID[mt][nt][r2*2];
                    int i1 = accHH[mt][nt][r2*2+1] * 128 + accMID[mt][nt][r2*2+1];
                    qv[idx][nt * 2]     = (float)i0 * sa * uB[cb + col];
                    qv[idx][nt * 2 + 1] = (float)i1 * sa * uB[cb + col + 1];
                }
            } else if (c == 1) {
                float p0 = 0.0f, p1 = 0.0f;
#pragma unroll
                for (int nt = 0; nt < 4; nt++) {
                    int col = nwid * 32 + nt * 8 + (lane & 3) * 2;
                    int i0 = accHH[mt][nt][r2*2]   * 128 + accMID[mt][nt][r2*2];
                    int i1 = accHH[mt][nt][r2*2+1] * 128 + accMID[mt][nt][r2*2+1];
                    float k0 = (float)i0 * sa * uB[cb + col];
                    float k1 = (float)i1 * sa * uB[cb + col + 1];
                    float d = qv[idx][nt * 2] * k0 + qv[idx][nt * 2 + 1] * k1;
                    if (nt < 2) p0 += d; else p1 += d;
                }
                // quad lanes (lane^1, lane^2) share this row and cover the head's 16 dims
                p0 += __shfl_xor_sync(0xffffffffu, p0, 1);
                p0 += __shfl_xor_sync(0xffffffffu, p0, 2);
                p1 += __shfl_xor_sync(0xffffffffu, p1, 1);
                p1 += __shfl_xor_sync(0xffffffffu, p1, 2);
                rsa[idx][0] = p0 * 0.25f;
                rsa[idx][1] = p1 * 0.25f;
            } else {
#pragma unroll
                for (int nt = 0; nt < 4; nt++) {
                    int col = nwid * 32 + nt * 8 + (lane & 3) * 2;
                    int i0 = accHH[mt][nt][r2*2]   * 128 + accMID[mt][nt][r2*2];
                    int i1 = accHH[mt][nt][r2*2+1] * 128 + accMID[mt][nt][r2*2+1];
                    float v0 = (float)i0 * sa * uB[cb + col];
                    float v1 = (float)i1 * sa * uB[cb + col + 1];
                    float r = rsa[idx][nt >> 1];
                    if (ok)
                        *(float2*)(imv32 + (size_t)t * 128 + col) =
                            make_float2(r * v0, r * v1);
                }
            }
        }
    }
}

// ---------------------------------------------------------------------------
// fc1 GEMM (M=128, N=512, 8 chunks) with fused GELU + int8 group quantization.
// ---------------------------------------------------------------------------
__global__ __launch_bounds__(256, 2)
void i8_gemm_fc1(const int8_t* __restrict__ a_h, const int8_t* __restrict__ a_l,
                 const float* __restrict__ sA,
                 const int8_t* __restrict__ w_h, const int8_t* __restrict__ w_l,
                 const float* __restrict__ uB,
                 const float* __restrict__ biasv,
                 int8_t* __restrict__ out_h, int8_t* __restrict__ out_l,
                 float* __restrict__ scg, int T)
{
    constexpr int K = 128;
    constexpr int NCH = 8;
    extern __shared__ char smem[];
    const uint32_t sbase = smem_to_u32(smem);
    const uint32_t sAh = sbase, sAl = sbase + 16384, sB0 = sbase + 32768;
    const int tid = threadIdx.x, wid = tid >> 5, lane = tid & 31;
    const int t0 = blockIdx.x * 128;

#pragma unroll
    for (int h = 0; h < 8; h++) {
        int i = tid + h * 256;
        int plane = i >> 10, idx = i & 1023;
        int kt = idx >> 8, sub = idx & 255, row = sub >> 1, kc = sub & 1;
        int t = t0 + row; bool p = t < T;
        uint32_t dst = (plane ? sAl : sAh) + (uint32_t)kt * 4096 + SWZ8(row, kc);
        cp16(dst, (plane ? a_l : a_h) + (size_t)(p ? t : 0) * K + kt * 32 + kc * 16, p);
    }
    auto stageB = [&](int c) {
        uint32_t bb = sB0 + (uint32_t)(c & 1) * 16384;
#pragma unroll
        for (int h = 0; h < 4; h++) {
            int i = tid + h * 256;
            int plane = i >> 9, idx = i & 511;
            int kt = idx >> 7, sub = idx & 127, row = sub >> 1, kc = sub & 1;
            uint32_t dst = bb + (plane ? 8192u : 0u) + (uint32_t)kt * 2048 + SWZ8(row, kc);
            cp16(dst, (plane ? w_l : w_h) + (size_t)(c * 64 + row) * K + kt * 32 + kc * 16, true);
        }
    };
    stageB(0); CP_COMMIT();
    stageB(1); CP_COMMIT();

#pragma unroll 1
    for (int c = 0; c < NCH; c++) {
        if (c < NCH - 1) CP_WAIT1(); else CP_WAIT0();
        __syncthreads();
        uint32_t bb = sB0 + (uint32_t)(c & 1) * 16384;
        int accHH[2][4][4], accMID[2][4][4];
        ZERO_ACC(accHH, accMID);
#pragma unroll
        for (int kt = 0; kt < 4; kt++) {
            uint32_t fAh[2][4], fAl[2][4], fBh[2][4], fBl[2][4];
            uint32_t a0 = sAh + kt * 4096, a1 = sAl + kt * 4096;
            uint32_t b0 = bb + kt * 2048, b1 = bb + 8192 + kt * 2048;
            LOAD_FRAGS64(a0, a1, b0, b1);
#pragma unroll
            for (int mt = 0; mt < 2; mt++)
#pragma unroll
                for (int nt = 0; nt < 4; nt++) {
                    int j = nt >> 1, o = (nt & 1) * 2;
                    imma(accHH[mt][nt],  fAh[mt], fBh[j][o], fBh[j][o + 1]);
                    imma(accMID[mt][nt], fAh[mt], fBl[j][o], fBl[j][o + 1]);
                    imma(accMID[mt][nt], fAl[mt], fBh[j][o], fBh[j][o + 1]);
                }
        }
        __syncthreads();
        if (c + 2 < NCH) { stageB(c + 2); CP_COMMIT(); }

#pragma unroll
        for (int mt = 0; mt < 2; mt++)
#pragma unroll
            for (int r2 = 0; r2 < 2; r2++) {
                int row = (wid & 3) * 32 + mt * 16 + (lane >> 2) + r2 * 8;
                int t = t0 + row;
                bool ok = t < T;
                float sa = sA[ok ? t : 0];
                float v[8];
                float m = 0.0f;
#pragma unroll
                for (int nt = 0; nt < 4; nt++) {
                    int col = c * 64 + (wid >> 2) * 32 + nt * 8 + (lane & 3) * 2;
                    int i0 = accHH[mt][nt][r2 * 2]     * 128 + accMID[mt][nt][r2 * 2];
                    int i1 = accHH[mt][nt][r2 * 2 + 1] * 128 + accMID[mt][nt][r2 * 2 + 1];
                    float2 b2 = *(const float2*)(biasv + col);
                    float v0 = (float)i0 * sa * uB[col]     + b2.x;
                    float v1 = (float)i1 * sa * uB[col + 1] + b2.y;
                    v0 = 0.5f * v0 * (1.0f + erff(v0 * 0.70710678118654752f));
                    v1 = 0.5f * v1 * (1.0f + erff(v1 * 0.70710678118654752f));
                    v[nt * 2] = v0; v[nt * 2 + 1] = v1;
                    m = fmaxf(m, fmaxf(fabsf(v0), fabsf(v1)));
                }
                m = fmaxf(m, __shfl_xor_sync(0xffffffffu, m, 1));
                m = fmaxf(m, __shfl_xor_sync(0xffffffffu, m, 2));
                float inv = (m > 0.0f) ? (16256.0f / m) : 0.0f;
                if (ok) {
#pragma unroll
                    for (int nt = 0; nt < 4; nt++) {
                        int col = c * 64 + (wid >> 2) * 32 + nt * 8 + (lane & 3) * 2;
                        char hh[2], ll[2];
#pragma unroll
                        for (int e = 0; e < 2; e++) {
                            int iv = __float2int_rn(v[nt * 2 + e] * inv);
                            int vh = (iv + 64) >> 7;
                            hh[e] = (char)vh;
                            ll[e] = (char)(iv - (vh << 7));
                        }
                        *(char2*)(out_h + (size_t)t * 512 + col) = make_char2(hh[0], hh[1]);
                        *(char2*)(out_l + (size_t)t * 512 + col) = make_char2(ll[0], ll[1]);
                    }
                    if ((lane & 3) == 0)
                        scg[(size_t)t * 16 + c * 2 + (wid >> 2)] = m * (1.0f / 16256.0f);
                }
            }
    }
}

// ---------------------------------------------------------------------------
// fc2 GEMM (K=512), M=64 x N=128 tiles, group dequant, optional fused LN.
// ---------------------------------------------------------------------------
template<int DO_LN>
__global__ __launch_bounds__(256, 2)
void i8_gemm_fc2m64(const int8_t* __restrict__ a_h, const int8_t* __restrict__ a_l,
                    const float* __restrict__ scg,
                    const int8_t* __restrict__ w_h, const int8_t* __restrict__ w_l,
                    const float* __restrict__ uB,
                    const float* __restrict__ biasv,
                    const float* __restrict__ addend,
                    const float* __restrict__ ln_g, const float* __restrict__ ln_b,
                    float* __restrict__ outf,
                    int8_t* __restrict__ z8h, int8_t* __restrict__ z8l,
                    float* __restrict__ s_z, int T)
{
    constexpr int K = 512;
    extern __shared__ char smem[];
    const uint32_t sbase = smem_to_u32(smem);
    const int tid = threadIdx.x, wid = tid >> 5, lane = tid & 31;
    const int t0 = blockIdx.x * 64;
    const int mwid = wid & 1, nwid = wid >> 1;

    auto stage = [&](int q) {
        uint32_t sb = sbase + (uint32_t)(q & 1) * 49152;
#pragma unroll
        for (int h = 0; h < 4; h++) {
            int i = tid + h * 256;
            int plane = i >> 9, idx = i & 511;
            int kt = idx >> 7, sub = idx & 127, row = sub >> 1, kc = sub & 1;
            int t = t0 + row; bool p = t < T;
            uint32_t dst = sb + (plane ? 8192u : 0u) + (uint32_t)kt * 2048 + SWZ8(row, kc);
            cp16(dst, (plane ? a_l : a_h) + (size_t)(p ? t : 0) * K
                          + q * 128 + kt * 32 + kc * 16, p);
        }
#pragma unroll
        for (int h = 0; h < 8; h++) {
            int i = tid + h * 256;
            int plane = i >> 10, idx = i & 1023;
            int kt = idx >> 8, sub = idx & 255, row = sub >> 1, kc = sub & 1;
            uint32_t dst = sb + 16384 + (plane ? 16384u : 0u) + (uint32_t)kt * 4096 + SWZ8(row, kc);
            cp16(dst, (plane ? w_l : w_h) + (size_t)row * K
                          + q * 128 + kt * 32 + kc * 16, true);
        }
    };
    stage(0); CP_COMMIT();
    stage(1); CP_COMMIT();

    float facc[2][4][4];
#pragma unroll
    for (int i = 0; i < 2; i++)
#pragma unroll
        for (int j = 0; j < 4; j++)
#pragma unroll
            for (int q = 0; q < 4; q++) facc[i][j][q] = 0.0f;

#pragma unroll 1
    for (int q = 0; q < 4; q++) {
        if (q < 3) CP_WAIT1(); else CP_WAIT0();
        __syncthreads();
        uint32_t sb = sbase + (uint32_t)(q & 1) * 49152;
#pragma unroll
        for (int kt = 0; kt < 4; kt++) {
            int g = q * 4 + kt;
            float sg[2][2];
#pragma unroll
            for (int mt = 0; mt < 2; mt++)
#pragma unroll
                for (int r2 = 0; r2 < 2; r2++) {
                    int row = mwid * 32 + mt * 16 + (lane >> 2) + r2 * 8;
                    int t = t0 + row;
                    sg[mt][r2] = scg[(size_t)(t < T ? t : 0) * 16 + g];
                }
            uint32_t fAh[2][4], fAl[2][4], fBh[2][4], fBl[2][4];
            {
                int arow = mwid * 32 + (lane & 7) + ((lane >> 3) & 1) * 8;
                int akc  = lane >> 4;
#pragma unroll
                for (int mt = 0; mt < 2; mt++) {
                    uint32_t off = (uint32_t)kt * 2048 + SWZ8(arow + mt * 16, akc);
                    ldm4(fAh[mt], sb + off);
                    ldm4(fAl[mt], sb + 8192 + off);
                }
                int brow = nwid * 32 + ((lane >> 4) & 1) * 8 + (lane & 7);
                int bkc  = (lane >> 3) & 1;
#pragma unroll
                for (int j = 0; j < 2; j++) {
                    uint32_t off = (uint32_t)kt * 4096 + SWZ8(brow + j * 16, bkc);
                    ldm4(fBh[j], sb + 16384 + off);
                    ldm4(fBl[j], sb + 32768 + off);
                }
            }
#pragma unroll
            for (int mt = 0; mt < 2; mt++)
#pragma unroll
                for (int nt = 0; nt < 4; nt++) {
                    int j = nt >> 1, o = (nt & 1) * 2;
                    int aHH[4] = {0, 0, 0, 0}, aMID[4] = {0, 0, 0, 0};
                    imma(aHH,  fAh[mt], fBh[j][o], fBh[j][o + 1]);
                    imma(aMID, fAh[mt], fBl[j][o], fBl[j][o + 1]);
                    imma(aMID, fAl[mt], fBh[j][o], fBh[j][o + 1]);
#pragma unroll
                    for (int e = 0; e < 4; e++)
                        facc[mt][nt][e] += (float)(aHH[e] * 128 + aMID[e]) * sg[mt][e >> 1];
                }
        }
        __syncthreads();
        if (q + 2 < 4) { stage(q + 2); CP_COMMIT(); }
    }

    float v[4][8];
    int ok[4]; size_t orow[4];
#pragma unroll
    for (int idx = 0; idx < 4; idx++) {
        int mt = idx >> 1, r2 = idx & 1;
        int row = mwid * 32 + mt * 16 + (lane >> 2) + r2 * 8;
        int t = t0 + row;
        ok[idx] = (t < T);
        orow[idx] = (size_t)t;
#pragma unroll
        for (int nt = 0; nt < 4; nt++) {
            int col = nwid * 32 + nt * 8 + (lane & 3) * 2;
            float v0 = facc[mt][nt][r2 * 2]     * uB[col];
            float v1 = facc[mt][nt][r2 * 2 + 1] * uB[col + 1];
            float2 b2 = *(const float2*)(biasv + col);
            v0 += b2.x; v1 += b2.y;
            float2 a2 = *(const float2*)(addend + (size_t)(ok[idx] ? t : 0) * 128 + col);
            v0 += a2.x; v1 += a2.y;
            if (ok[idx])
                *(float2*)(outf + (size_t)t * 128 + col) = make_float2(v0, v1);
            v[idx][nt * 2] = v0; v[idx][nt * 2 + 1] = v1;
        }
    }
    if (DO_LN) {
        __syncthreads();
        ln_epilogue_m64(v, smem, 98304, mwid, nwid, lane, ok, orow,
                        ln_g, ln_b, z8h, z8l, s_z);
    }
}

// ---------------------------------------------------------------------------
// Row quantization helpers.
// ---------------------------------------------------------------------------
__device__ __forceinline__ void quant_row_dev(
    const float* __restrict__ src, int8_t* __restrict__ dh,
    int8_t* __restrict__ dl, float* __restrict__ sout,
    int kd, float smul, int lane)
{
    int n4 = kd >> 7;
    float4 v[4];
    float m = 0.0f;
#pragma unroll 4
    for (int i = 0; i < n4; i++) {
        v[i] = ((const float4*)src)[lane + 32 * i];
        m = fmaxf(m, fmaxf(fmaxf(fabsf(v[i].x), fabsf(v[i].y)),
                           fmaxf(fabsf(v[i].z), fabsf(v[i].w))));
    }
#pragma unroll
    for (int o = 16; o >= 1; o >>= 1) m = fmaxf(m, __shfl_xor_sync(0xffffffffu, m, o));
    float s   = m * (1.0f / 16256.0f);
    float inv = (m > 0.0f) ? (16256.0f / m) : 0.0f;
#pragma unroll 4
    for (int i = 0; i < n4; i++) {
        float vv[4] = {v[i].x, v[i].y, v[i].z, v[i].w};
        char h4[4], l4[4];
#pragma unroll
        for (int q = 0; q < 4; q++) {
            int iv = __float2int_rn(vv[q] * inv);
            int vh = (iv + 64) >> 7;
            int vl = iv - (vh << 7);
            h4[q] = (char)vh; l4[q] = (char)vl;
        }
        ((char4*)dh)[lane + 32 * i] = make_char4(h4[0], h4[1], h4[2], h4[3]);
        ((char4*)dl)[lane + 32 * i] = make_char4(l4[0], l4[1], l4[2], l4[3]);
    }
    if (lane == 0) *sout = s * smul;
}

template<int KD>
__global__ void quant_rows(const float* __restrict__ src,
                           int8_t* __restrict__ dh, int8_t* __restrict__ dl,
                           float* __restrict__ sc, int T)
{
    int warp = threadIdx.x >> 5, lane = threadIdx.x & 31;
    int t = blockIdx.x * 8 + warp;
    if (t >= T) return;
    quant_row_dev(src + (size_t)t * KD, dh + (size_t)t * KD, dl + (size_t)t * KD,
                  sc + t, KD, 1.0f, lane);
}

__global__ void quantW(const float* __restrict__ w0, const float* __restrict__ wq,
                       const float* __restrict__ wo, const float* __restrict__ f1,
                       const float* __restrict__ f2,
                       int8_t* __restrict__ dh, int8_t* __restrict__ dl,
                       float* __restrict__ sc)
{
    int gw = blockIdx.x * 8 + (threadIdx.x >> 5);
    int lane = threadIdx.x & 31;
    if (gw >= 1792) return;
    const float* src; int kd = 128; size_t off;
    if (gw < 128)       { src = w0 + (size_t)gw * 128;          off = (size_t)gw * 128; }
    else if (gw < 896)  { int q = gw - 128;  src = wq + (size_t)q * 128; off = 16384  + (size_t)q * 128; }
    else if (gw < 1152) { int q = gw - 896;  src = wo + (size_t)q * 128; off = 114688 + (size_t)q * 128; }
    else if (gw < 1664) { int q = gw - 1152; src = f1 + (size_t)q * 128; off = 147456 + (size_t)q * 128; }
    else                { int q = gw - 1664; src = f2 + (size_t)q * 512; off = 212992 + (size_t)q * 512; kd = 512; }
    quant_row_dev(src, dh + off, dl + off, sc + gw, kd, 128.0f, lane);
}

// ---------------------------------------------------------------------------
// LN + quant for the 120 cls rows only.
// ---------------------------------------------------------------------------
__global__ void ln_cls(const float* __restrict__ x,
                       const float* __restrict__ g,
                       const float* __restrict__ b,
                       int8_t* __restrict__ zh, int8_t* __restrict__ zl,
                       float* __restrict__ sc)
{
    int warp = threadIdx.x >> 5, lane = threadIdx.x & 31;
    int w = blockIdx.x * 8 + warp;
    if (w >= AA) return;
    size_t t = (size_t)w * BP1;

    float4 v = ((const float4*)(x + t * 128))[lane];
    float s = v.x + v.y + v.z + v.w;
#pragma unroll
    for (int o = 16; o >= 1; o >>= 1) s += __shfl_xor_sync(0xffffffffu, s, o);
    float mu = s * (1.0f / 128.0f);
    float dx = v.x - mu, dy = v.y - mu, dz = v.z - mu, dw = v.w - mu;
    float q = dx * dx + dy * dy + dz * dz + dw * dw;
#pragma unroll
    for (int o = 16; o >= 1; o >>= 1) q += __shfl_xor_sync(0xffffffffu, q, o);
    float rs = rsqrtf(q * (1.0f / 128.0f) + 1e-5f);

    float4 gg = ((const float4*)g)[lane];
    float4 bb = ((const float4*)b)[lane];
    float o0 = dx * rs * gg.x + bb.x;
    float o1 = dy * rs * gg.y + bb.y;
    float o2 = dz * rs * gg.z + bb.z;
    float o3 = dw * rs * gg.w + bb.w;

    float m = fmaxf(fmaxf(fabsf(o0), fabsf(o1)), fmaxf(fabsf(o2), fabsf(o3)));
#pragma unroll
    for (int o = 16; o >= 1; o >>= 1) m = fmaxf(m, __shfl_xor_sync(0xffffffffu, m, o));
    float inv = (m > 0.0f) ? (16256.0f / m) : 0.0f;

    float vv[4] = {o0, o1, o2, o3};
    char h4[4], l4[4];
#pragma unroll
    for (int qi = 0; qi < 4; qi++) {
        int iv = __float2int_rn(vv[qi] * inv);
        int vh = (iv + 64) >> 7;
        h4[qi] = (char)vh;
        l4[qi] = (char)(iv - (vh << 7));
    }
    ((char4*)(zh + t * 128))[lane] = make_char4(h4[0], h4[1], h4[2], h4[3]);
    ((char4*)(zl + t * 128))[lane] = make_char4(l4[0], l4[1], l4[2], l4[3]);
    if (lane == 0) sc[t] = m * (1.0f / 16256.0f);
}

// ---------------------------------------------------------------------------
// Chunked cumsum + fused quantization.
// ---------------------------------------------------------------------------
__global__ void csum_partial(const float* __restrict__ imv, float* __restrict__ part)
{
    int c = blockIdx.x, i = blockIdx.y, f = threadIdx.x;
    size_t base = ((size_t)i * BP1 + c * 128) * 128 + f;
    float sum = 0.0f;
#pragma unroll 8
    for (int j = 0; j < 128; j++) sum += imv[base + (size_t)j * 128];
    part[((size_t)i * 16 + c) * 128 + f] = sum;
}

__global__ void csum_scan(float* __restrict__ part)
{
    int i = blockIdx.x, f = threadIdx.x;
    float run = 0.0f;
#pragma unroll
    for (int c = 0; c < 16; c++) {
        size_t idx = ((size_t)i * 16 + c) * 128 + f;
        float t = part[idx];
        part[idx] = run;
        run += t;
    }
}

__global__ void csum_apply(const float* __restrict__ imv,
                           const float* __restrict__ part,
                           int8_t* __restrict__ dh, int8_t* __restrict__ dl,
                           float* __restrict__ sc)
{
    __shared__ float sm[4][8];
    int c = blockIdx.x, i = blockIdx.y, f = threadIdx.x;
    int warp = f >> 5, lane = f & 31;
    size_t base = ((size_t)i * BP1 + c * 128) * 128 + f;
    float acc = part[((size_t)i * 16 + c) * 128 + f];

#pragma unroll 1
    for (int jb = 0; jb < 16; jb++) {
        float val[8], mx[8];
#pragma unroll
        for (int u = 0; u < 8; u++) {
            acc += imv[base + (size_t)(jb * 8 + u) * 128];
            val[u] = acc;
            mx[u] = fabsf(acc);
        }
#pragma unroll
        for (int o = 16; o >= 1; o >>= 1)
#pragma unroll
            for (int u = 0; u < 8; u++)
                mx[u] = fmaxf(mx[u], __shfl_xor_sync(0xffffffffu, mx[u], o));
        if (lane == 0) {
#pragma unroll
            for (int u = 0; u < 8; u++) sm[warp][u] = mx[u];
        }
        __syncthreads();
#pragma unroll
        for (int u = 0; u < 8; u++) {
            float m = fmaxf(fmaxf(sm[0][u], sm[1][u]), fmaxf(sm[2][u], sm[3][u]));
            float inv = (m > 0.0f) ? (16256.0f / m) : 0.0f;
            int iv = __float2int_rn(val[u] * inv);
            int vh = (iv + 64) >> 7;
            int vl = iv - (vh << 7);
            size_t row = (size_t)i * BP1 + c * 128 + jb * 8 + u;
            dh[row * 128 + f] = (int8_t)vh;
            dl[row * 128 + f] = (int8_t)vl;
            if (f == 0) sc[row] = m * (1.0f / 16256.0f);
        }
        __syncthreads();
    }
}

__global__ void quant_last(const float* __restrict__ imv,
                           int8_t* __restrict__ dh, int8_t* __restrict__ dl,
                           float* __restrict__ sc)
{
    int w = blockIdx.x * 8 + (threadIdx.x >> 5), lane = threadIdx.x & 31;
    if (w >= AA) return;
    size_t row = (size_t)w * BP1 + BB;
    quant_row_dev(imv + row * 128, dh + row * 128, dl + row * 128,
                  sc + row, 128, 1.0f, lane);
}

__global__ void cls_kernel(const float* __restrict__ cls,
                           const float* __restrict__ bias,
                           float* __restrict__ out)
{
    int i = blockIdx.x, l = threadIdx.x;
    out[(size_t)i * BP1 * 128 + l] = cls[i * 128 + l] + bias[(size_t)i * BP1 * 128 + l];
}

// ---------------------------------------------------------------------------
// Launch
// ---------------------------------------------------------------------------
extern "C" void kernel_launch(void* const* d_in, const int* in_sizes, int n_in,
                              void* d_out, int out_size)
{
    const float* x      = (const float*)d_in[0];
    const float* weight = (const float*)d_in[1];
    const float* cls    = (const float*)d_in[2];
    const float* bias   = (const float*)d_in[3];
    const float* Wqkv   = (const float*)d_in[4];
    const float* Wo     = (const float*)d_in[5];
    const float* ln1_g  = (const float*)d_in[6];
    const float* ln1_b  = (const float*)d_in[7];
    const float* ln2_g  = (const float*)d_in[8];
    const float* ln2_b  = (const float*)d_in[9];
    const float* fc1_w  = (const float*)d_in[10];
    const float* fc1_b  = (const float*)d_in[11];
    const float* fc2_w  = (const float*)d_in[12];
    const float* fc2_b  = (const float*)d_in[13];
    float* s = (float*)d_out;

    void *pbig, *pact, *ph8, *pwh, *pwl, *pscw, *psct, *psch, *ppart;
    cudaGetSymbolAddress(&pbig, g_big);
    cudaGetSymbolAddress(&pact, g_act8);
    cudaGetSymbolAddress(&ph8,  g_h8);
    cudaGetSymbolAddress(&pwh,  g_w8h);
    cudaGetSymbolAddress(&pwl,  g_w8l);
    cudaGetSymbolAddress(&pscw, g_sc_w);
    cudaGetSymbolAddress(&psct, g_sc_tok);
    cudaGetSymbolAddress(&psch, g_sch);
    cudaGetSymbolAddress(&ppart, g_part);

    float*  big   = (float*)pbig;
    int8_t* act8  = (int8_t*)pact;
    int8_t* h8    = (int8_t*)ph8;
    int8_t* w8h   = (int8_t*)pwh;
    int8_t* w8l   = (int8_t*)pwl;
    float*  sc_w  = (float*)pscw;
    float*  sc_t  = (float*)psct;
    float*  sc_h  = (float*)psch;
    float*  partb = (float*)ppart;

    const int T  = TTOK;
    const int Tx = TXTOK;
    const int tokBlocks = (T + 127) / 128;   // 1922
    const int m64Blocks = (T + 63) / 64;     // 3842
    const int m64BlocksX = Tx / 64;          // 3840

    int8_t* z8h   = act8;
    int8_t* z8l   = z8h + (size_t)T * 128;
    int8_t* imv8h = z8h;                     // alias (z dead after qkv)
    int8_t* imv8l = z8l;
    int8_t* h8h   = h8;
    int8_t* h8l   = h8h + (size_t)T * 512;
    int8_t* x8h   = h8;                      // alias (x only used at init)
    int8_t* x8l   = x8h + (size_t)Tx * 128;
    float* imv32 = big;                      // T*128
    float* s_z   = sc_t;
    float* s_imv = sc_t + T;
    float* s_x   = sc_t + 3 * (size_t)T;

    const int SM_M64  = 52224;   // 48K tiles + 3K red (+pad)
    const int SM_QKV  = 81920;   // A 16K + B 2x32K
    const int SM_FC2  = 101376;  // 96K tiles + 3K red (+pad)
    const int SM_FC1  = 65536;
    cudaFuncSetAttribute(i8_gemm_m64k128<1>, cudaFuncAttributeMaxDynamicSharedMemorySize, SM_M64);
    cudaFuncSetAttribute(i8_gemm_m64k128<0>, cudaFuncAttributeMaxDynamicSharedMemorySize, SM_M64);
    cudaFuncSetAttribute(i8_gemm_fc1,       cudaFuncAttributeMaxDynamicSharedMemorySize, SM_FC1);
    cudaFuncSetAttribute(i8_gemm_fc2m64<1>, cudaFuncAttributeMaxDynamicSharedMemorySize, SM_FC2);
    cudaFuncSetAttribute(i8_gemm_fc2m64<0>, cudaFuncAttributeMaxDynamicSharedMemorySize, SM_FC2);
    cudaFuncSetAttribute(i8_qkv_rsa_m64,    cudaFuncAttributeMaxDynamicSharedMemorySize, SM_QKV);

    // 1: weights + x quant + cls row
    quantW<<<224, 256>>>(weight, Wqkv, Wo, fc1_w, fc2_w, w8h, w8l, sc_w);
    quant_rows<128><<<(Tx + 7) / 8, 256>>>(x, x8h, x8l, s_x, Tx);
    cls_kernel<<<AA, 128>>>(cls, bias, s);
    // 2: s = concat([cls, x @ W^T], 1) + bias ; fused LN1 -> z8
    i8_gemm_m64k128<1><<<m64BlocksX, 256, SM_M64>>>(
        x8h, x8l, s_x, w8h, w8l, sc_w, bias, ln1_g, ln1_b,
        s, z8h, z8l, s_z, Tx);
    // 3: LN1 for the 120 cls rows
    ln_cls<<<(AA + 7) / 8, 256>>>(s, ln1_g, ln1_b, z8h, z8l, s_z);

    for (int a = 0; a < 2; a++) {
        const int8_t* wq_h = w8h + 16384 + (size_t)a * 49152;
        const int8_t* wq_l = w8l + 16384 + (size_t)a * 49152;
        const float*  uq   = sc_w + 128 + a * 384;
        const int8_t* wo_h = w8h + 114688 + (size_t)a * 16384;
        const int8_t* wo_l = w8l + 114688 + (size_t)a * 16384;
        const float*  uo   = sc_w + 896 + a * 128;

        // imv32 = 0.25*(q.k per head)*v  (fused qkv + rsa, 2 CTAs/SM)
        i8_qkv_rsa_m64<<<m64Blocks, 256, SM_QKV>>>(
            z8h, z8l, s_z, wq_h, wq_l, uq, imv32, T);
        // chunked causal cumsum + quantization
        csum_partial<<<dim3(16, AA), 128>>>(imv32, partb);
        csum_scan<<<AA, 128>>>(partb);
        csum_apply<<<dim3(16, AA), 128>>>(imv32, partb, imv8h, imv8l, s_imv);
        quant_last<<<(AA + 7) / 8, 256>>>(imv32, imv8h, imv8l, s_imv);
        // s += imv @ Wo^T ; fused LN2 -> z8
        i8_gemm_m64k128<0><<<m64Blocks, 256, SM_M64>>>(
            imv8h, imv8l, s_imv, wo_h, wo_l, uo, s, ln2_g, ln2_b,
            s, z8h, z8l, s_z, T);
        // h8 = quant(gelu(z @ fc1^T + b1)) with group scales
        i8_gemm_fc1<<<tokBlocks, 256, SM_FC1>>>(
            z8h, z8l, s_z, w8h + 147456, w8l + 147456, sc_w + 1152,
            fc1_b, h8h, h8l, sc_h, T);
        // s = h @ fc2^T + b2 + s ; fused LN1 for next layer (a=0 only)
        if (a == 0) {
            i8_gemm_fc2m64<1><<<m64Blocks, 256, SM_FC2>>>(
                h8h, h8l, sc_h, w8h + 212992, w8l + 212992, sc_w + 1664,
                fc2_b, s, ln1_g, ln1_b, s, z8h, z8l, s_z, T);
        } else {
            i8_gemm_fc2m64<0><<<m64Blocks, 256, SM_FC2>>>(
                h8h, h8l, sc_h, w8h + 212992, w8l + 212992, sc_w + 1664,
                fc2_b, s, nullptr, nullptr, s, nullptr, nullptr, nullptr, T);
        }
    }
    (void)in_sizes; (void)n_in; (void)out_size;
}

// round 17
// speedup vs baseline: 1.1452x; 1.0816x over previous
#include <cuda_runtime.h>
#include <cuda_bf16.h>
#include <math.h>
#include <stdint.h>

// ---------------------------------------------------------------------------
// EEGformer forward. int8 dual-plane GEMMs (mma.sync.m16n8k32.s8).
// R17 (= R16 resubmit after infra flake): fc1+fc2 fused into one kernel;
// h stays in smem (no h8 DRAM round-trip).
// A=120, B=2048, Bp1=2049, M=128, T = 120*2049 = 245880 tokens.
// ---------------------------------------------------------------------------

#define AA    120
#define BB    2048
#define BP1   2049
#define TTOK  (AA * BP1)      // 245880
#define TXTOK (AA * BB)       // 245760

__device__ float  g_big[(size_t)TTOK * 128];        // imv32 fp32
__device__ int8_t g_act8[(size_t)TTOK * 256];       // z / imv planes
__device__ int8_t g_x8  [(size_t)TXTOK * 256];      // x planes
__device__ int8_t g_w8h[278528];
__device__ int8_t g_w8l[278528];
__device__ float  g_sc_w[1792];
__device__ float  g_sc_tok[(size_t)3 * TTOK + TXTOK];
__device__ float  g_part[AA * 16 * 128];

// ---------------------------------------------------------------------------
// PTX helpers
// ---------------------------------------------------------------------------
__device__ __forceinline__ uint32_t smem_to_u32(const void* p) {
    uint32_t a;
    asm("{ .reg .u64 t; cvta.to.shared.u64 t, %1; cvt.u32.u64 %0, t; }" : "=r"(a) : "l"(p));
    return a;
}
__device__ __forceinline__ void ldm4(uint32_t r[4], uint32_t addr) {
    asm volatile("ldmatrix.sync.aligned.m8n8.x4.shared.b16 {%0,%1,%2,%3}, [%4];"
        : "=r"(r[0]), "=r"(r[1]), "=r"(r[2]), "=r"(r[3]) : "r"(addr));
}
__device__ __forceinline__ void imma(int d[4], const uint32_t a[4],
                                     uint32_t b0, uint32_t b1) {
    asm volatile("mma.sync.aligned.m16n8k32.row.col.s32.s8.s8.s32 "
        "{%0,%1,%2,%3}, {%4,%5,%6,%7}, {%8,%9}, {%0,%1,%2,%3};"
        : "+r"(d[0]), "+r"(d[1]), "+r"(d[2]), "+r"(d[3])
        : "r"(a[0]), "r"(a[1]), "r"(a[2]), "r"(a[3]), "r"(b0), "r"(b1));
}
__device__ __forceinline__ void cp16(uint32_t saddr, const void* g, bool p) {
    int sz = p ? 16 : 0;
    asm volatile("cp.async.cg.shared.global [%0], [%1], 16, %2;"
        :: "r"(saddr), "l"(g), "r"(sz) : "memory");
}
#define CP_COMMIT() asm volatile("cp.async.commit_group;" ::: "memory")
#define CP_WAIT1()  asm volatile("cp.async.wait_group 1;" ::: "memory")
#define CP_WAIT0()  asm volatile("cp.async.wait_group 0;" ::: "memory")

// 32-byte-row swizzle inside one k-tile: line = row>>2 (128B)
#define SWZ8(row, kc) ((((row) >> 2) * 128) + \
    (((((row) & 3) * 2 + (kc)) ^ (((row) >> 2) & 7)) << 4))

#define GELU1(x) (0.5f * (x) * (1.0f + erff((x) * 0.70710678118654752f)))

// ---------------------------------------------------------------------------
// Fused LN + int8 quant epilogue for M=64 x N=128 kernels (2M x 4N warps).
// ---------------------------------------------------------------------------
__device__ __forceinline__ void ln_epilogue_m64(
    float v[4][8], char* smem, int red_off,
    int mwid, int nwid, int lane,
    const int ok[4], const size_t orow[4],
    const float* __restrict__ ln_g, const float* __restrict__ ln_b,
    int8_t* __restrict__ z8h, int8_t* __restrict__ z8l,
    float* __restrict__ s_z)
{
    float* sm_sum = (float*)(smem + red_off);   // [64][4]
    float* sm_sq  = sm_sum + 256;
    float* sm_mx  = sm_sum + 512;
    int rl[4];
#pragma unroll
    for (int idx = 0; idx < 4; idx++)
        rl[idx] = mwid * 32 + (idx >> 1) * 16 + (idx & 1) * 8 + (lane >> 2);

#pragma unroll
    for (int idx = 0; idx < 4; idx++) {
        float ps = 0.0f, pq = 0.0f;
#pragma unroll
        for (int j = 0; j < 8; j++) { ps += v[idx][j]; pq += v[idx][j] * v[idx][j]; }
        ps += __shfl_xor_sync(0xffffffffu, ps, 1);
        ps += __shfl_xor_sync(0xffffffffu, ps, 2);
        pq += __shfl_xor_sync(0xffffffffu, pq, 1);
        pq += __shfl_xor_sync(0xffffffffu, pq, 2);
        if ((lane & 3) == 0) {
            sm_sum[rl[idx] * 4 + nwid] = ps;
            sm_sq [rl[idx] * 4 + nwid] = pq;
        }
    }
    __syncthreads();
#pragma unroll
    for (int idx = 0; idx < 4; idx++) {
        float ts = sm_sum[rl[idx] * 4 + 0] + sm_sum[rl[idx] * 4 + 1]
                 + sm_sum[rl[idx] * 4 + 2] + sm_sum[rl[idx] * 4 + 3];
        float tq = sm_sq[rl[idx] * 4 + 0] + sm_sq[rl[idx] * 4 + 1]
                 + sm_sq[rl[idx] * 4 + 2] + sm_sq[rl[idx] * 4 + 3];
        float mu = ts * (1.0f / 128.0f);
        float var = tq * (1.0f / 128.0f) - mu * mu;
        float rs = rsqrtf(var + 1e-5f);
        float m = 0.0f;
#pragma unroll
        for (int j = 0; j < 8; j++) {
            int col = nwid * 32 + (j >> 1) * 8 + (lane & 3) * 2 + (j & 1);
            float o = (v[idx][j] - mu) * rs * ln_g[col] + ln_b[col];
            v[idx][j] = o;
            m = fmaxf(m, fabsf(o));
        }
        m = fmaxf(m, __shfl_xor_sync(0xffffffffu, m, 1));
        m = fmaxf(m, __shfl_xor_sync(0xffffffffu, m, 2));
        if ((lane & 3) == 0) sm_mx[rl[idx] * 4 + nwid] = m;
    }
    __syncthreads();
#pragma unroll
    for (int idx = 0; idx < 4; idx++) {
        float m = fmaxf(fmaxf(sm_mx[rl[idx] * 4 + 0], sm_mx[rl[idx] * 4 + 1]),
                        fmaxf(sm_mx[rl[idx] * 4 + 2], sm_mx[rl[idx] * 4 + 3]));
        float inv = (m > 0.0f) ? (16256.0f / m) : 0.0f;
        if (ok[idx]) {
#pragma unroll
            for (int nt = 0; nt < 4; nt++) {
                int colp = nwid * 32 + nt * 8 + (lane & 3) * 2;
                char hh[2], ll[2];
#pragma unroll
                for (int e = 0; e < 2; e++) {
                    int iv = __float2int_rn(v[idx][nt * 2 + e] * inv);
                    int vh = (iv + 64) >> 7;
                    hh[e] = (char)vh;
                    ll[e] = (char)(iv - (vh << 7));
                }
                *(char2*)(z8h + orow[idx] * 128 + colp) = make_char2(hh[0], hh[1]);
                *(char2*)(z8l + orow[idx] * 128 + colp) = make_char2(ll[0], ll[1]);
            }
            if ((lane & 3) == 0 && nwid == 0) s_z[orow[idx]] = m * (1.0f / 16256.0f);
        }
    }
}

// ---------------------------------------------------------------------------
// M=64 x N=128, K=128 single-shot burst GEMM (init, Wo) with fused LN+quant.
// ---------------------------------------------------------------------------
template<int REMAP>
__global__ __launch_bounds__(256, 2)
void i8_gemm_m64k128(const int8_t* __restrict__ a_h, const int8_t* __restrict__ a_l,
                     const float* __restrict__ sA,
                     const int8_t* __restrict__ w_h, const int8_t* __restrict__ w_l,
                     const float* __restrict__ uB,
                     const float* __restrict__ addend,
                     const float* __restrict__ ln_g, const float* __restrict__ ln_b,
                     float* __restrict__ outf,
                     int8_t* __restrict__ z8h, int8_t* __restrict__ z8l,
                     float* __restrict__ s_z, int T)
{
    constexpr int K = 128;
    extern __shared__ char smem[];
    const uint32_t sbase = smem_to_u32(smem);
    const int tid = threadIdx.x, wid = tid >> 5, lane = tid & 31;
    const int t0 = blockIdx.x * 64;
    const int mwid = wid & 1, nwid = wid >> 1;

#pragma unroll
    for (int h = 0; h < 4; h++) {
        int i = tid + h * 256;
        int plane = i >> 9, idx = i & 511;
        int kt = idx >> 7, sub = idx & 127, row = sub >> 1, kc = sub & 1;
        int t = t0 + row; bool p = t < T;
        uint32_t dst = sbase + (plane ? 8192u : 0u) + (uint32_t)kt * 2048 + SWZ8(row, kc);
        cp16(dst, (plane ? a_l : a_h) + (size_t)(p ? t : 0) * K + kt * 32 + kc * 16, p);
    }
#pragma unroll
    for (int h = 0; h < 8; h++) {
        int i = tid + h * 256;
        int plane = i >> 10, idx = i & 1023;
        int kt = idx >> 8, sub = idx & 255, row = sub >> 1, kc = sub & 1;
        uint32_t dst = sbase + 16384 + (plane ? 16384u : 0u) + (uint32_t)kt * 4096 + SWZ8(row, kc);
        cp16(dst, (plane ? w_l : w_h) + (size_t)row * K + kt * 32 + kc * 16, true);
    }
    CP_COMMIT();
    CP_WAIT0();
    __syncthreads();

    int accHH[2][4][4], accMID[2][4][4];
#pragma unroll
    for (int i = 0; i < 2; i++)
#pragma unroll
        for (int j = 0; j < 4; j++)
#pragma unroll
            for (int q = 0; q < 4; q++) { accHH[i][j][q] = 0; accMID[i][j][q] = 0; }

#pragma unroll
    for (int kt = 0; kt < 4; kt++) {
        uint32_t fAh[2][4], fAl[2][4], fBh[2][4], fBl[2][4];
        {
            int arow = mwid * 32 + (lane & 7) + ((lane >> 3) & 1) * 8;
            int akc  = lane >> 4;
#pragma unroll
            for (int mt = 0; mt < 2; mt++) {
                uint32_t off = (uint32_t)kt * 2048 + SWZ8(arow + mt * 16, akc);
                ldm4(fAh[mt], sbase + off);
                ldm4(fAl[mt], sbase + 8192 + off);
            }
            int brow = nwid * 32 + ((lane >> 4) & 1) * 8 + (lane & 7);
            int bkc  = (lane >> 3) & 1;
#pragma unroll
            for (int j = 0; j < 2; j++) {
                uint32_t off = (uint32_t)kt * 4096 + SWZ8(brow + j * 16, bkc);
                ldm4(fBh[j], sbase + 16384 + off);
                ldm4(fBl[j], sbase + 32768 + off);
            }
        }
#pragma unroll
        for (int mt = 0; mt < 2; mt++)
#pragma unroll
            for (int nt = 0; nt < 4; nt++) {
                int j = nt >> 1, o = (nt & 1) * 2;
                imma(accHH[mt][nt],  fAh[mt], fBh[j][o], fBh[j][o + 1]);
                imma(accMID[mt][nt], fAh[mt], fBl[j][o], fBl[j][o + 1]);
                imma(accMID[mt][nt], fAl[mt], fBh[j][o], fBh[j][o + 1]);
            }
    }

    float v[4][8];
    int ok[4]; size_t orow[4];
#pragma unroll
    for (int idx = 0; idx < 4; idx++) {
        int mt = idx >> 1, r2 = idx & 1;
        int row = mwid * 32 + mt * 16 + (lane >> 2) + r2 * 8;
        int t = t0 + row;
        ok[idx] = (t < T);
        orow[idx] = REMAP ? ((size_t)t + (size_t)((unsigned)t / 2048u) + 1) : (size_t)t;
        float sa = sA[ok[idx] ? t : 0];
#pragma unroll
        for (int nt = 0; nt < 4; nt++) {
            int col = nwid * 32 + nt * 8 + (lane & 3) * 2;
            int i0 = accHH[mt][nt][r2 * 2]     * 128 + accMID[mt][nt][r2 * 2];
            int i1 = accHH[mt][nt][r2 * 2 + 1] * 128 + accMID[mt][nt][r2 * 2 + 1];
            float v0 = (float)i0 * sa * uB[col];
            float v1 = (float)i1 * sa * uB[col + 1];
            float2 a2 = *(const float2*)(addend + orow[idx] * 128 + col);
            v0 += a2.x; v1 += a2.y;
            if (ok[idx])
                *(float2*)(outf + orow[idx] * 128 + col) = make_float2(v0, v1);
            v[idx][nt * 2] = v0; v[idx][nt * 2 + 1] = v1;
        }
    }
    __syncthreads();
    ln_epilogue_m64(v, smem, 49152, mwid, nwid, lane, ok, orow,
                    ln_g, ln_b, z8h, z8l, s_z);
}

// ---------------------------------------------------------------------------
// Fused QKV + rsa + imv, M=64 x N=128, q in registers, rsa via quad shuffles.
// ---------------------------------------------------------------------------
__global__ __launch_bounds__(256, 2)
void i8_qkv_rsa_m64(const int8_t* __restrict__ a_h, const int8_t* __restrict__ a_l,
                    const float* __restrict__ sA,
                    const int8_t* __restrict__ w_h, const int8_t* __restrict__ w_l,
                    const float* __restrict__ uB,
                    float* __restrict__ imv32, int T)
{
    constexpr int K = 128;
    extern __shared__ char smem[];
    const uint32_t sbase = smem_to_u32(smem);
    const uint32_t sAh = sbase, sAl = sbase + 8192, sB0 = sbase + 16384;
    const int tid = threadIdx.x, wid = tid >> 5, lane = tid & 31;
    const int t0 = blockIdx.x * 64;
    const int mwid = wid & 1, nwid = wid >> 1;

#pragma unroll
    for (int h = 0; h < 4; h++) {
        int i = tid + h * 256;
        int plane = i >> 9, idx = i & 511;
        int kt = idx >> 7, sub = idx & 127, row = sub >> 1, kc = sub & 1;
        int t = t0 + row; bool p = t < T;
        uint32_t dst = (plane ? sAl : sAh) + (uint32_t)kt * 2048 + SWZ8(row, kc);
        cp16(dst, (plane ? a_l : a_h) + (size_t)(p ? t : 0) * K + kt * 32 + kc * 16, p);
    }
    auto stageB = [&](int c) {
        uint32_t bb = sB0 + (uint32_t)(c & 1) * 32768;
#pragma unroll
        for (int h = 0; h < 8; h++) {
            int i = tid + h * 256;
            int plane = i >> 10, idx = i & 1023;
            int kt = idx >> 8, sub = idx & 255, row = sub >> 1, kc = sub & 1;
            uint32_t dst = bb + (plane ? 16384u : 0u) + (uint32_t)kt * 4096 + SWZ8(row, kc);
            cp16(dst, (plane ? w_l : w_h) + (size_t)(c * 128 + row) * K + kt * 32 + kc * 16, true);
        }
    };
    stageB(0); CP_COMMIT();
    stageB(1); CP_COMMIT();

    float qv[4][8];
    float rsa[4][2];

#pragma unroll 1
    for (int c = 0; c < 3; c++) {
        if (c < 2) CP_WAIT1(); else CP_WAIT0();
        __syncthreads();
        uint32_t bb = sB0 + (uint32_t)(c & 1) * 32768;
        int accHH[2][4][4], accMID[2][4][4];
#pragma unroll
        for (int i = 0; i < 2; i++)
#pragma unroll
            for (int j = 0; j < 4; j++)
#pragma unroll
                for (int q = 0; q < 4; q++) { accHH[i][j][q] = 0; accMID[i][j][q] = 0; }
#pragma unroll
        for (int kt = 0; kt < 4; kt++) {
            uint32_t fAh[2][4], fAl[2][4], fBh[2][4], fBl[2][4];
            {
                int arow = mwid * 32 + (lane & 7) + ((lane >> 3) & 1) * 8;
                int akc  = lane >> 4;
#pragma unroll
                for (int mt = 0; mt < 2; mt++) {
                    uint32_t off = (uint32_t)kt * 2048 + SWZ8(arow + mt * 16, akc);
                    ldm4(fAh[mt], sAh + off);
                    ldm4(fAl[mt], sAl + off);
                }
                int brow = nwid * 32 + ((lane >> 4) & 1) * 8 + (lane & 7);
                int bkc  = (lane >> 3) & 1;
#pragma unroll
                for (int j = 0; j < 2; j++) {
                    uint32_t off = (uint32_t)kt * 4096 + SWZ8(brow + j * 16, bkc);
                    ldm4(fBh[j], bb + off);
                    ldm4(fBl[j], bb + 16384 + off);
                }
            }
#pragma unroll
            for (int mt = 0; mt < 2; mt++)
#pragma unroll
                for (int nt = 0; nt < 4; nt++) {
                    int j = nt >> 1, o = (nt & 1) * 2;
                    imma(accHH[mt][nt],  fAh[mt], fBh[j][o], fBh[j][o + 1]);
                    imma(accMID[mt][nt], fAh[mt], fBl[j][o], fBl[j][o + 1]);
                    imma(accMID[mt][nt], fAl[mt], fBh[j][o], fBh[j][o + 1]);
                }
        }
        __syncthreads();
        if (c + 2 < 3) { stageB(c + 2); CP_COMMIT(); }

        const int cb = c * 128;
#pragma unroll
        for (int idx = 0; idx < 4; idx++) {
            int mt = idx >> 1, r2 = idx & 1;
            int row = mwid * 32 + mt * 16 + (lane >> 2) + r2 * 8;
            int t = t0 + row;
            bool ok = t < T;
            float sa = sA[ok ? t : 0];
            if (c == 0) {
#pragma unroll
                for (int nt = 0; nt < 4; nt++) {
                    int col = nwid * 32 + nt * 8 + (lane & 3) * 2;
                    int i0 = accHH[mt][nt][r2*2]   * 128 + accMID[mt][nt][r2*2];
                    int i1 = accHH[mt][nt][r2*2+1] * 128 + accMID[mt][nt][r2*2+1];
                    qv[idx][nt * 2]     = (float)i0 * sa * uB[cb + col];
                    qv[idx][nt * 2 + 1] = (float)i1 * sa * uB[cb + col + 1];
                }
            } else if (c == 1) {
                float p0 = 0.0f, p1 = 0.0f;
#pragma unroll
                for (int nt = 0; nt < 4; nt++) {
                    int col = nwid * 32 + nt * 8 + (lane & 3) * 2;
                    int i0 = accHH[mt][nt][r2*2]   * 128 + accMID[mt][nt][r2*2];
                    int i1 = accHH[mt][nt][r2*2+1] * 128 + accMID[mt][nt][r2*2+1];
                    float k0 = (float)i0 * sa * uB[cb + col];
                    float k1 = (float)i1 * sa * uB[cb + col + 1];
                    float d = qv[idx][nt * 2] * k0 + qv[idx][nt * 2 + 1] * k1;
                    if (nt < 2) p0 += d; else p1 += d;
                }
                p0 += __shfl_xor_sync(0xffffffffu, p0, 1);
                p0 += __shfl_xor_sync(0xffffffffu, p0, 2);
                p1 += __shfl_xor_sync(0xffffffffu, p1, 1);
                p1 += __shfl_xor_sync(0xffffffffu, p1, 2);
                rsa[idx][0] = p0 * 0.25f;
                rsa[idx][1] = p1 * 0.25f;
            } else {
#pragma unroll
                for (int nt = 0; nt < 4; nt++) {
                    int col = nwid * 32 + nt * 8 + (lane & 3) * 2;
                    int i0 = accHH[mt][nt][r2*2]   * 128 + accMID[mt][nt][r2*2];
                    int i1 = accHH[mt][nt][r2*2+1] * 128 + accMID[mt][nt][r2*2+1];
                    float v0 = (float)i0 * sa * uB[cb + col];
                    float v1 = (float)i1 * sa * uB[cb + col + 1];
                    float r = rsa[idx][nt >> 1];
                    if (ok)
                        *(float2*)(imv32 + (size_t)t * 128 + col) =
                            make_float2(r * v0, r * v1);
                }
            }
        }
    }
}

// ---------------------------------------------------------------------------
// Fused MLP: h = gelu(z @ w1^T + b1) computed per 64-col chunk, quantized to
// smem, immediately consumed by fc2 partial; s = h @ w2^T + b2 + s (+LN).
// M=64 rows/CTA. smem 92KB -> 2 CTAs/SM.
//   0      z hi (8K, 4kt x 2048) | 8192 z lo (8K)
//   16384  w1 buf[2] 16K each (hi 8K [4kt x 2048], lo 8K)
//   49152  w2 buf[2] 16K each (hi 8K [2kt x 4096], lo 8K)
//   81920  h hi (4K, 2kt x 2048) | 86016 h lo (4K)
//   90112  hsc [64][2] floats (512B)
//   90624  LN reduction arrays (3K)
// ---------------------------------------------------------------------------
template<int DO_LN>
__global__ __launch_bounds__(256, 2)
void i8_mlp_fused(const int8_t* __restrict__ z_h, const int8_t* __restrict__ z_l,
                  const float* __restrict__ sA,
                  const int8_t* __restrict__ w1_h, const int8_t* __restrict__ w1_l,
                  const float* __restrict__ u1, const float* __restrict__ b1,
                  const int8_t* __restrict__ w2_h, const int8_t* __restrict__ w2_l,
                  const float* __restrict__ u2, const float* __restrict__ b2,
                  const float* __restrict__ addend,
                  const float* __restrict__ ln_g, const float* __restrict__ ln_b,
                  float* __restrict__ outf,
                  int8_t* __restrict__ z8h, int8_t* __restrict__ z8l,
                  float* __restrict__ s_z, int T)
{
    extern __shared__ char smem[];
    const uint32_t sbase = smem_to_u32(smem);
    const int tid = threadIdx.x, wid = tid >> 5, lane = tid & 31;
    const int t0 = blockIdx.x * 64;
    const int mwid = wid & 1, nwid = wid >> 1;   // fc2 layout (2M x 4N)
    const int mw4 = wid & 3, nw2 = wid >> 2;     // fc1 layout (4M x 2N)
    float* hsc = (float*)(smem + 90112);

    // z burst
#pragma unroll
    for (int h = 0; h < 4; h++) {
        int i = tid + h * 256;
        int plane = i >> 9, idx = i & 511;
        int kt = idx >> 7, sub = idx & 127, row = sub >> 1, kc = sub & 1;
        int t = t0 + row; bool p = t < T;
        uint32_t dst = sbase + (plane ? 8192u : 0u) + (uint32_t)kt * 2048 + SWZ8(row, kc);
        cp16(dst, (plane ? z_l : z_h) + (size_t)(p ? t : 0) * 128 + kt * 32 + kc * 16, p);
    }
    auto stageW = [&](int c) {
        uint32_t b1a = sbase + 16384 + (uint32_t)(c & 1) * 16384;
#pragma unroll
        for (int h = 0; h < 4; h++) {
            int i = tid + h * 256;
            int plane = i >> 9, idx = i & 511;
            int kt = idx >> 7, sub = idx & 127, row = sub >> 1, kc = sub & 1;
            uint32_t dst = b1a + (plane ? 8192u : 0u) + (uint32_t)kt * 2048 + SWZ8(row, kc);
            cp16(dst, (plane ? w1_l : w1_h) + (size_t)(c * 64 + row) * 128 + kt * 32 + kc * 16, true);
        }
        uint32_t b2a = sbase + 49152 + (uint32_t)(c & 1) * 16384;
#pragma unroll
        for (int h = 0; h < 4; h++) {
            int i = tid + h * 256;
            int plane = i >> 9, idx = i & 511;
            int kt = idx >> 8, sub = idx & 255, row = sub >> 1, kc = sub & 1;
            uint32_t dst = b2a + (plane ? 8192u : 0u) + (uint32_t)kt * 4096 + SWZ8(row, kc);
            cp16(dst, (plane ? w2_l : w2_h) + (size_t)row * 512 + c * 64 + kt * 32 + kc * 16, true);
        }
    };
    stageW(0); CP_COMMIT();
    stageW(1); CP_COMMIT();

    float facc[2][4][4];
#pragma unroll
    for (int i = 0; i < 2; i++)
#pragma unroll
        for (int j = 0; j < 4; j++)
#pragma unroll
            for (int q = 0; q < 4; q++) facc[i][j][q] = 0.0f;

#pragma unroll 1
    for (int c = 0; c < 8; c++) {
        if (c < 7) CP_WAIT1(); else CP_WAIT0();
        __syncthreads();
        uint32_t w1b = sbase + 16384 + (uint32_t)(c & 1) * 16384;
        uint32_t w2b = sbase + 49152 + (uint32_t)(c & 1) * 16384;

        // ---- fc1 chunk: m64 x n64 x k128, warps 4M x 2N (tile 16 x 32) ----
        int aHH[4][4], aMID[4][4];
#pragma unroll
        for (int j = 0; j < 4; j++)
#pragma unroll
            for (int q = 0; q < 4; q++) { aHH[j][q] = 0; aMID[j][q] = 0; }
#pragma unroll
        for (int kt = 0; kt < 4; kt++) {
            uint32_t fAh[4], fAl[4], fBh[2][4], fBl[2][4];
            {
                int arow = mw4 * 16 + (lane & 7) + ((lane >> 3) & 1) * 8;
                int akc  = lane >> 4;
                uint32_t off = (uint32_t)kt * 2048 + SWZ8(arow, akc);
                ldm4(fAh, sbase + off);
                ldm4(fAl, sbase + 8192 + off);
                int brow = nw2 * 32 + ((lane >> 4) & 1) * 8 + (lane & 7);
                int bkc  = (lane >> 3) & 1;
#pragma unroll
                for (int j = 0; j < 2; j++) {
                    uint32_t offb = (uint32_t)kt * 2048 + SWZ8(brow + j * 16, bkc);
                    ldm4(fBh[j], w1b + offb);
                    ldm4(fBl[j], w1b + 8192 + offb);
                }
            }
#pragma unroll
            for (int nt = 0; nt < 4; nt++) {
                int j = nt >> 1, o = (nt & 1) * 2;
                imma(aHH[nt],  fAh, fBh[j][o], fBh[j][o + 1]);
                imma(aMID[nt], fAh, fBl[j][o], fBl[j][o + 1]);
                imma(aMID[nt], fAl, fBh[j][o], fBh[j][o + 1]);
            }
        }
        // fc1 epilogue: gelu + group quant (32 cols = this n-warp) -> h stage
#pragma unroll
        for (int r2 = 0; r2 < 2; r2++) {
            int rowl = mw4 * 16 + (lane >> 2) + r2 * 8;    // 0..63
            int t = t0 + rowl;
            float sa = sA[(t < T) ? t : 0];
            float v[8];
            float m = 0.0f;
#pragma unroll
            for (int nt = 0; nt < 4; nt++) {
                int colg = c * 64 + nw2 * 32 + nt * 8 + (lane & 3) * 2;
                int i0 = aHH[nt][r2 * 2]     * 128 + aMID[nt][r2 * 2];
                int i1 = aHH[nt][r2 * 2 + 1] * 128 + aMID[nt][r2 * 2 + 1];
                float v0 = (float)i0 * sa * u1[colg]     + b1[colg];
                float v1 = (float)i1 * sa * u1[colg + 1] + b1[colg + 1];
                v0 = GELU1(v0); v1 = GELU1(v1);
                v[nt * 2] = v0; v[nt * 2 + 1] = v1;
                m = fmaxf(m, fmaxf(fabsf(v0), fabsf(v1)));
            }
            m = fmaxf(m, __shfl_xor_sync(0xffffffffu, m, 1));
            m = fmaxf(m, __shfl_xor_sync(0xffffffffu, m, 2));
            float inv = (m > 0.0f) ? (16256.0f / m) : 0.0f;
#pragma unroll
            for (int nt = 0; nt < 4; nt++) {
                int cl = nw2 * 32 + nt * 8 + (lane & 3) * 2;   // 0..63 local
                int ktl = cl >> 5, inner = cl & 31;
                int kcc = inner >> 4, byt = inner & 15;
                uint32_t hoff = 81920u + (uint32_t)ktl * 2048 + SWZ8(rowl, kcc) + byt;
                char hh[2], ll[2];
#pragma unroll
                for (int e = 0; e < 2; e++) {
                    int iv = __float2int_rn(v[nt * 2 + e] * inv);
                    int vh = (iv + 64) >> 7;
                    hh[e] = (char)vh;
                    ll[e] = (char)(iv - (vh << 7));
                }
                *(char2*)(smem + hoff)        = make_char2(hh[0], hh[1]);
                *(char2*)(smem + hoff + 4096) = make_char2(ll[0], ll[1]);
            }
            if ((lane & 3) == 0) hsc[rowl * 2 + nw2] = m * (1.0f / 16256.0f);
        }
        __syncthreads();

        // ---- fc2 partial: m64 x n128 x k64, warps 2M x 4N ----
#pragma unroll
        for (int kt = 0; kt < 2; kt++) {
            float sg[2][2];
#pragma unroll
            for (int mt = 0; mt < 2; mt++)
#pragma unroll
                for (int r2 = 0; r2 < 2; r2++) {
                    int row = mwid * 32 + mt * 16 + (lane >> 2) + r2 * 8;
                    sg[mt][r2] = hsc[row * 2 + kt];
                }
            uint32_t fAh[2][4], fAl[2][4], fBh[2][4], fBl[2][4];
            {
                int arow = mwid * 32 + (lane & 7) + ((lane >> 3) & 1) * 8;
                int akc  = lane >> 4;
#pragma unroll
                for (int mt = 0; mt < 2; mt++) {
                    uint32_t off = 81920u + (uint32_t)kt * 2048 + SWZ8(arow + mt * 16, akc);
                    ldm4(fAh[mt], sbase + off);
                    ldm4(fAl[mt], sbase + off + 4096);
                }
                int brow = nwid * 32 + ((lane >> 4) & 1) * 8 + (lane & 7);
                int bkc  = (lane >> 3) & 1;
#pragma unroll
                for (int j = 0; j < 2; j++) {
                    uint32_t off = (uint32_t)kt * 4096 + SWZ8(brow + j * 16, bkc);
                    ldm4(fBh[j], w2b + off);
                    ldm4(fBl[j], w2b + 8192 + off);
                }
            }
#pragma unroll
            for (int mt = 0; mt < 2; mt++)
#pragma unroll
                for (int nt = 0; nt < 4; nt++) {
                    int j = nt >> 1, o = (nt & 1) * 2;
                    int tHH[4] = {0, 0, 0, 0}, tMID[4] = {0, 0, 0, 0};
                    imma(tHH,  fAh[mt], fBh[j][o], fBh[j][o + 1]);
                    imma(tMID, fAh[mt], fBl[j][o], fBl[j][o + 1]);
                    imma(tMID, fAl[mt], fBh[j][o], fBh[j][o + 1]);
#pragma unroll
                    for (int e = 0; e < 4; e++)
                        facc[mt][nt][e] += (float)(tHH[e] * 128 + tMID[e]) * sg[mt][e >> 1];
                }
        }
        __syncthreads();
        if (c + 2 < 8) { stageW(c + 2); CP_COMMIT(); }
    }

    // Final epilogue: bias2 + residual, write s, optional LN+quant.
    float v[4][8];
    int ok[4]; size_t orow[4];
#pragma unroll
    for (int idx = 0; idx < 4; idx++) {
        int mt = idx >> 1, r2 = idx & 1;
        int row = mwid * 32 + mt * 16 + (lane >> 2) + r2 * 8;
        int t = t0 + row;
        ok[idx] = (t < T);
        orow[idx] = (size_t)t;
#pragma unroll
        for (int nt = 0; nt < 4; nt++) {
            int col = nwid * 32 + nt * 8 + (lane & 3) * 2;
            float v0 = facc[mt][nt][r2 * 2]     * u2[col];
            float v1 = facc[mt][nt][r2 * 2 + 1] * u2[col + 1];
            float2 bb = *(const float2*)(b2 + col);
            v0 += bb.x; v1 += bb.y;
            float2 a2 = *(const float2*)(addend + (size_t)(ok[idx] ? t : 0) * 128 + col);
            v0 += a2.x; v1 += a2.y;
            if (ok[idx])
                *(float2*)(outf + (size_t)t * 128 + col) = make_float2(v0, v1);
            v[idx][nt * 2] = v0; v[idx][nt * 2 + 1] = v1;
        }
    }
    if (DO_LN) {
        __syncthreads();
        ln_epilogue_m64(v, smem, 90624, mwid, nwid, lane, ok, orow,
                        ln_g, ln_b, z8h, z8l, s_z);
    }
}

// ---------------------------------------------------------------------------
// Row quantization helpers.
// ---------------------------------------------------------------------------
__device__ __forceinline__ void quant_row_dev(
    const float* __restrict__ src, int8_t* __restrict__ dh,
    int8_t* __restrict__ dl, float* __restrict__ sout,
    int kd, float smul, int lane)
{
    int n4 = kd >> 7;
    float4 v[4];
    float m = 0.0f;
#pragma unroll 4
    for (int i = 0; i < n4; i++) {
        v[i] = ((const float4*)src)[lane + 32 * i];
        m = fmaxf(m, fmaxf(fmaxf(fabsf(v[i].x), fabsf(v[i].y)),
                           fmaxf(fabsf(v[i].z), fabsf(v[i].w))));
    }
#pragma unroll
    for (int o = 16; o >= 1; o >>= 1) m = fmaxf(m, __shfl_xor_sync(0xffffffffu, m, o));
    float s   = m * (1.0f / 16256.0f);
    float inv = (m > 0.0f) ? (16256.0f / m) : 0.0f;
#pragma unroll 4
    for (int i = 0; i < n4; i++) {
        float vv[4] = {v[i].x, v[i].y, v[i].z, v[i].w};
        char h4[4], l4[4];
#pragma unroll
        for (int q = 0; q < 4; q++) {
            int iv = __float2int_rn(vv[q] * inv);
            int vh = (iv + 64) >> 7;
            int vl = iv - (vh << 7);
            h4[q] = (char)vh; l4[q] = (char)vl;
        }
        ((char4*)dh)[lane + 32 * i] = make_char4(h4[0], h4[1], h4[2], h4[3]);
        ((char4*)dl)[lane + 32 * i] = make_char4(l4[0], l4[1], l4[2], l4[3]);
    }
    if (lane == 0) *sout = s * smul;
}

template<int KD>
__global__ void quant_rows(const float* __restrict__ src,
                           int8_t* __restrict__ dh, int8_t* __restrict__ dl,
                           float* __restrict__ sc, int T)
{
    int warp = threadIdx.x >> 5, lane = threadIdx.x & 31;
    int t = blockIdx.x * 8 + warp;
    if (t >= T) return;
    quant_row_dev(src + (size_t)t * KD, dh + (size_t)t * KD, dl + (size_t)t * KD,
                  sc + t, KD, 1.0f, lane);
}

__global__ void quantW(const float* __restrict__ w0, const float* __restrict__ wq,
                       const float* __restrict__ wo, const float* __restrict__ f1,
                       const float* __restrict__ f2,
                       int8_t* __restrict__ dh, int8_t* __restrict__ dl,
                       float* __restrict__ sc)
{
    int gw = blockIdx.x * 8 + (threadIdx.x >> 5);
    int lane = threadIdx.x & 31;
    if (gw >= 1792) return;
    const float* src; int kd = 128; size_t off;
    if (gw < 128)       { src = w0 + (size_t)gw * 128;          off = (size_t)gw * 128; }
    else if (gw < 896)  { int q = gw - 128;  src = wq + (size_t)q * 128; off = 16384  + (size_t)q * 128; }
    else if (gw < 1152) { int q = gw - 896;  src = wo + (size_t)q * 128; off = 114688 + (size_t)q * 128; }
    else if (gw < 1664) { int q = gw - 1152; src = f1 + (size_t)q * 128; off = 147456 + (size_t)q * 128; }
    else                { int q = gw - 1664; src = f2 + (size_t)q * 512; off = 212992 + (size_t)q * 512; kd = 512; }
    quant_row_dev(src, dh + off, dl + off, sc + gw, kd, 128.0f, lane);
}

// ---------------------------------------------------------------------------
// LN + quant for the 120 cls rows only.
// ---------------------------------------------------------------------------
__global__ void ln_cls(const float* __restrict__ x,
                       const float* __restrict__ g,
                       const float* __restrict__ b,
                       int8_t* __restrict__ zh, int8_t* __restrict__ zl,
                       float* __restrict__ sc)
{
    int warp = threadIdx.x >> 5, lane = threadIdx.x & 31;
    int w = blockIdx.x * 8 + warp;
    if (w >= AA) return;
    size_t t = (size_t)w * BP1;

    float4 v = ((const float4*)(x + t * 128))[lane];
    float s = v.x + v.y + v.z + v.w;
#pragma unroll
    for (int o = 16; o >= 1; o >>= 1) s += __shfl_xor_sync(0xffffffffu, s, o);
    float mu = s * (1.0f / 128.0f);
    float dx = v.x - mu, dy = v.y - mu, dz = v.z - mu, dw = v.w - mu;
    float q = dx * dx + dy * dy + dz * dz + dw * dw;
#pragma unroll
    for (int o = 16; o >= 1; o >>= 1) q += __shfl_xor_sync(0xffffffffu, q, o);
    float rs = rsqrtf(q * (1.0f / 128.0f) + 1e-5f);

    float4 gg = ((const float4*)g)[lane];
    float4 bb = ((const float4*)b)[lane];
    float o0 = dx * rs * gg.x + bb.x;
    float o1 = dy * rs * gg.y + bb.y;
    float o2 = dz * rs * gg.z + bb.z;
    float o3 = dw * rs * gg.w + bb.w;

    float m = fmaxf(fmaxf(fabsf(o0), fabsf(o1)), fmaxf(fabsf(o2), fabsf(o3)));
#pragma unroll
    for (int o = 16; o >= 1; o >>= 1) m = fmaxf(m, __shfl_xor_sync(0xffffffffu, m, o));
    float inv = (m > 0.0f) ? (16256.0f / m) : 0.0f;

    float vv[4] = {o0, o1, o2, o3};
    char h4[4], l4[4];
#pragma unroll
    for (int qi = 0; qi < 4; qi++) {
        int iv = __float2int_rn(vv[qi] * inv);
        int vh = (iv + 64) >> 7;
        h4[qi] = (char)vh;
        l4[qi] = (char)(iv - (vh << 7));
    }
    ((char4*)(zh + t * 128))[lane] = make_char4(h4[0], h4[1], h4[2], h4[3]);
    ((char4*)(zl + t * 128))[lane] = make_char4(l4[0], l4[1], l4[2], l4[3]);
    if (lane == 0) sc[t] = m * (1.0f / 16256.0f);
}

// ---------------------------------------------------------------------------
// Chunked cumsum + fused quantization.
// ---------------------------------------------------------------------------
__global__ void csum_partial(const float* __restrict__ imv, float* __restrict__ part)
{
    int c = blockIdx.x, i = blockIdx.y, f = threadIdx.x;
    size_t base = ((size_t)i * BP1 + c * 128) * 128 + f;
    float sum = 0.0f;
#pragma unroll 8
    for (int j = 0; j < 128; j++) sum += imv[base + (size_t)j * 128];
    part[((size_t)i * 16 + c) * 128 + f] = sum;
}

__global__ void csum_scan(float* __restrict__ part)
{
    int i = blockIdx.x, f = threadIdx.x;
    float run = 0.0f;
#pragma unroll
    for (int c = 0; c < 16; c++) {
        size_t idx = ((size_t)i * 16 + c) * 128 + f;
        float t = part[idx];
        part[idx] = run;
        run += t;
    }
}

__global__ void csum_apply(const float* __restrict__ imv,
                           const float* __restrict__ part,
                           int8_t* __restrict__ dh, int8_t* __restrict__ dl,
                           float* __restrict__ sc)
{
    __shared__ float sm[4][8];
    int c = blockIdx.x, i = blockIdx.y, f = threadIdx.x;
    int warp = f >> 5, lane = f & 31;
    size_t base = ((size_t)i * BP1 + c * 128) * 128 + f;
    float acc = part[((size_t)i * 16 + c) * 128 + f];

#pragma unroll 1
    for (int jb = 0; jb < 16; jb++) {
        float val[8], mx[8];
#pragma unroll
        for (int u = 0; u < 8; u++) {
            acc += imv[base + (size_t)(jb * 8 + u) * 128];
            val[u] = acc;
            mx[u] = fabsf(acc);
        }
#pragma unroll
        for (int o = 16; o >= 1; o >>= 1)
#pragma unroll
            for (int u = 0; u < 8; u++)
                mx[u] = fmaxf(mx[u], __shfl_xor_sync(0xffffffffu, mx[u], o));
        if (lane == 0) {
#pragma unroll
            for (int u = 0; u < 8; u++) sm[warp][u] = mx[u];
        }
        __syncthreads();
#pragma unroll
        for (int u = 0; u < 8; u++) {
            float m = fmaxf(fmaxf(sm[0][u], sm[1][u]), fmaxf(sm[2][u], sm[3][u]));
            float inv = (m > 0.0f) ? (16256.0f / m) : 0.0f;
            int iv = __float2int_rn(val[u] * inv);
            int vh = (iv + 64) >> 7;
            int vl = iv - (vh << 7);
            size_t row = (size_t)i * BP1 + c * 128 + jb * 8 + u;
            dh[row * 128 + f] = (int8_t)vh;
            dl[row * 128 + f] = (int8_t)vl;
            if (f == 0) sc[row] = m * (1.0f / 16256.0f);
        }
        __syncthreads();
    }
}

__global__ void quant_last(const float* __restrict__ imv,
                           int8_t* __restrict__ dh, int8_t* __restrict__ dl,
                           float* __restrict__ sc)
{
    int w = blockIdx.x * 8 + (threadIdx.x >> 5), lane = threadIdx.x & 31;
    if (w >= AA) return;
    size_t row = (size_t)w * BP1 + BB;
    quant_row_dev(imv + row * 128, dh + row * 128, dl + row * 128,
                  sc + row, 128, 1.0f, lane);
}

__global__ void cls_kernel(const float* __restrict__ cls,
                           const float* __restrict__ bias,
                           float* __restrict__ out)
{
    int i = blockIdx.x, l = threadIdx.x;
    out[(size_t)i * BP1 * 128 + l] = cls[i * 128 + l] + bias[(size_t)i * BP1 * 128 + l];
}

// ---------------------------------------------------------------------------
// Launch
// ---------------------------------------------------------------------------
extern "C" void kernel_launch(void* const* d_in, const int* in_sizes, int n_in,
                              void* d_out, int out_size)
{
    const float* x      = (const float*)d_in[0];
    const float* weight = (const float*)d_in[1];
    const float* cls    = (const float*)d_in[2];
    const float* bias   = (const float*)d_in[3];
    const float* Wqkv   = (const float*)d_in[4];
    const float* Wo     = (const float*)d_in[5];
    const float* ln1_g  = (const float*)d_in[6];
    const float* ln1_b  = (const float*)d_in[7];
    const float* ln2_g  = (const float*)d_in[8];
    const float* ln2_b  = (const float*)d_in[9];
    const float* fc1_w  = (const float*)d_in[10];
    const float* fc1_b  = (const float*)d_in[11];
    const float* fc2_w  = (const float*)d_in[12];
    const float* fc2_b  = (const float*)d_in[13];
    float* s = (float*)d_out;

    void *pbig, *pact, *px8, *pwh, *pwl, *pscw, *psct, *ppart;
    cudaGetSymbolAddress(&pbig, g_big);
    cudaGetSymbolAddress(&pact, g_act8);
    cudaGetSymbolAddress(&px8,  g_x8);
    cudaGetSymbolAddress(&pwh,  g_w8h);
    cudaGetSymbolAddress(&pwl,  g_w8l);
    cudaGetSymbolAddress(&pscw, g_sc_w);
    cudaGetSymbolAddress(&psct, g_sc_tok);
    cudaGetSymbolAddress(&ppart, g_part);

    float*  big   = (float*)pbig;
    int8_t* act8  = (int8_t*)pact;
    int8_t* x8    = (int8_t*)px8;
    int8_t* w8h   = (int8_t*)pwh;
    int8_t* w8l   = (int8_t*)pwl;
    float*  sc_w  = (float*)pscw;
    float*  sc_t  = (float*)psct;
    float*  partb = (float*)ppart;

    const int T  = TTOK;
    const int Tx = TXTOK;
    const int m64Blocks = (T + 63) / 64;     // 3842
    const int m64BlocksX = Tx / 64;          // 3840

    int8_t* z8h   = act8;
    int8_t* z8l   = z8h + (size_t)T * 128;
    int8_t* imv8h = z8h;                     // alias (z dead after qkv)
    int8_t* imv8l = z8l;
    int8_t* x8h   = x8;
    int8_t* x8l   = x8h + (size_t)Tx * 128;
    float* imv32 = big;                      // T*128
    float* s_z   = sc_t;
    float* s_imv = sc_t + T;
    float* s_x   = sc_t + 3 * (size_t)T;

    const int SM_M64  = 52224;   // 48K tiles + 3K red (+pad)
    const int SM_QKV  = 81920;   // A 16K + B 2x32K
    const int SM_MLP  = 94208;   // layout documented at kernel
    cudaFuncSetAttribute(i8_gemm_m64k128<1>, cudaFuncAttributeMaxDynamicSharedMemorySize, SM_M64);
    cudaFuncSetAttribute(i8_gemm_m64k128<0>, cudaFuncAttributeMaxDynamicSharedMemorySize, SM_M64);
    cudaFuncSetAttribute(i8_qkv_rsa_m64,     cudaFuncAttributeMaxDynamicSharedMemorySize, SM_QKV);
    cudaFuncSetAttribute(i8_mlp_fused<1>,    cudaFuncAttributeMaxDynamicSharedMemorySize, SM_MLP);
    cudaFuncSetAttribute(i8_mlp_fused<0>,    cudaFuncAttributeMaxDynamicSharedMemorySize, SM_MLP);

    // 1: weights + x quant + cls row
    quantW<<<224, 256>>>(weight, Wqkv, Wo, fc1_w, fc2_w, w8h, w8l, sc_w);
    quant_rows<128><<<(Tx + 7) / 8, 256>>>(x, x8h, x8l, s_x, Tx);
    cls_kernel<<<AA, 128>>>(cls, bias, s);
    // 2: s = concat([cls, x @ W^T], 1) + bias ; fused LN1 -> z8
    i8_gemm_m64k128<1><<<m64BlocksX, 256, SM_M64>>>(
        x8h, x8l, s_x, w8h, w8l, sc_w, bias, ln1_g, ln1_b,
        s, z8h, z8l, s_z, Tx);
    // 3: LN1 for the 120 cls rows
    ln_cls<<<(AA + 7) / 8, 256>>>(s, ln1_g, ln1_b, z8h, z8l, s_z);

    for (int a = 0; a < 2; a++) {
        const int8_t* wq_h = w8h + 16384 + (size_t)a * 49152;
        const int8_t* wq_l = w8l + 16384 + (size_t)a * 49152;
        const float*  uq   = sc_w + 128 + a * 384;
        const int8_t* wo_h = w8h + 114688 + (size_t)a * 16384;
        const int8_t* wo_l = w8l + 114688 + (size_t)a * 16384;
        const float*  uo   = sc_w + 896 + a * 128;

        // imv32 = 0.25*(q.k per head)*v  (fused qkv + rsa)
        i8_qkv_rsa_m64<<<m64Blocks, 256, SM_QKV>>>(
            z8h, z8l, s_z, wq_h, wq_l, uq, imv32, T);
        // chunked causal cumsum + quantization
        csum_partial<<<dim3(16, AA), 128>>>(imv32, partb);
        csum_scan<<<AA, 128>>>(partb);
        csum_apply<<<dim3(16, AA), 128>>>(imv32, partb, imv8h, imv8l, s_imv);
        quant_last<<<(AA + 7) / 8, 256>>>(imv32, imv8h, imv8l, s_imv);
        // s += imv @ Wo^T ; fused LN2 -> z8
        i8_gemm_m64k128<0><<<m64Blocks, 256, SM_M64>>>(
            imv8h, imv8l, s_imv, wo_h, wo_l, uo, s, ln2_g, ln2_b,
            s, z8h, z8l, s_z, T);
        // fused MLP: s = gelu(z@fc1^T+b1)@fc2^T + b2 + s ; LN1 for next layer
        if (a == 0) {
            i8_mlp_fused<1><<<m64Blocks, 256, SM_MLP>>>(
                z8h, z8l, s_z,
                w8h + 147456, w8l + 147456, sc_w + 1152, fc1_b,
                w8h + 212992, w8l + 212992, sc_w + 1664, fc2_b,
                s, ln1_g, ln1_b, s, z8h, z8l, s_z, T);
        } else {
            i8_mlp_fused<0><<<m64Blocks, 256, SM_MLP>>>(
                z8h, z8l, s_z,
                w8h + 147456, w8l + 147456, sc_w + 1152, fc1_b,
                w8h + 212992, w8l + 212992, sc_w + 1664, fc2_b,
                s, nullptr, nullptr, s, nullptr, nullptr, nullptr, T);
        }
    }
    (void)in_sizes; (void)n_in; (void)out_size;
}